// round 6
// baseline (speedup 1.0000x reference)
#include <cuda_runtime.h>
#include <cuda_bf16.h>
#include <math.h>

#define BQ 8
#define SEQ 1024
#define DIMV 512
#define HEADS 8
#define DHEAD 64
#define NHEADS 64        // BQ*HEADS
#define QKVW 1536        // 3*HEADS*DHEAD

#define MU_C (1.0f/1024.0f)
#define NU_C (1.0f/1024.0f)

typedef unsigned long long u64;

__device__ __forceinline__ u64 dup2(float v) {
    u64 r; asm("mov.b64 %0, {%1, %1};" : "=l"(r) : "f"(v)); return r;
}
__device__ __forceinline__ void ffma2(u64& d, u64 a, u64 b) {
    asm("fma.rn.f32x2 %0, %1, %2, %0;" : "+l"(d) : "l"(a), "l"(b));
}
__device__ __forceinline__ float2 up2(u64 v) {
    float2 f; asm("mov.b64 {%0, %1}, %2;" : "=f"(f.x), "=f"(f.y) : "l"(v)); return f;
}

union F4U { float4 f; u64 u[2]; };

// ---------------- scratch (device globals; no allocations allowed) ----------
__device__ float g_qkv[(size_t)BQ * SEQ * QKVW];
__device__ float g_E[(size_t)NHEADS * SEQ * SEQ];            // E = exp(-C) fp32
__device__ __nv_bfloat16 g_Ebf[(size_t)NHEADS * SEQ * SEQ];  // bf16 shadow
__device__ float g_r[NHEADS * SEQ];
__device__ float g_rowsum[NHEADS * SEQ];
__device__ float g_cs1[NHEADS * SEQ];
__device__ float g_cs2[NHEADS * SEQ];
__device__ float g_cs3[NHEADS * SEQ];
__device__ float g_ho[(size_t)BQ * SEQ * DIMV];

// ------- 128x128x8 fp32 GEMM: f32x2, dup-A smem, double buffered ------------
__global__ __launch_bounds__(256) void sgemm128(
    const float* __restrict__ A, const float* __restrict__ Bm,
    float* __restrict__ C, int M, int Nn, int K, const float* __restrict__ bias)
{
    __shared__ float Asd[2][8][256];
    __shared__ float Bs[2][8][128];
    const int t = threadIdx.x;
    const int m0 = blockIdx.y * 128, n0 = blockIdx.x * 128;
    const int alr = t >> 1, alc = (t & 1) * 4;
    const int blr = t >> 5, blc = (t & 31) * 4;
    const int tx = t & 15, ty = t >> 4;

    u64 acc2[8][4];
#pragma unroll
    for (int r = 0; r < 8; r++)
#pragma unroll
        for (int c = 0; c < 4; c++) acc2[r][c] = 0ull;

    const float* Aptr = A + (size_t)(m0 + alr) * K + alc;
    const float* Bptr = Bm + (size_t)blr * Nn + n0 + blc;

    float4 av = *(const float4*)(Aptr);
    float4 bv = *(const float4*)(Bptr);
    // preamble: store tile 0
    *(u64*)&Asd[0][alc + 0][alr * 2] = dup2(av.x);
    *(u64*)&Asd[0][alc + 1][alr * 2] = dup2(av.y);
    *(u64*)&Asd[0][alc + 2][alr * 2] = dup2(av.z);
    *(u64*)&Asd[0][alc + 3][alr * 2] = dup2(av.w);
    *(float4*)&Bs[0][blr][blc] = bv;
    __syncthreads();

    const int NT = K / 8;
    for (int kt = 0; kt < NT; kt++) {
        const int buf = kt & 1;
        if (kt + 1 < NT) {
            av = *(const float4*)(Aptr + (kt + 1) * 8);
            bv = *(const float4*)(Bptr + (size_t)(kt + 1) * 8 * Nn);
        }
#pragma unroll
        for (int kk = 0; kk < 8; kk++) {
            F4U A0, A1, A2, A3, B0, B1;
            A0.f = *(const float4*)&Asd[buf][kk][ty * 8];
            A1.f = *(const float4*)&Asd[buf][kk][ty * 8 + 4];
            A2.f = *(const float4*)&Asd[buf][kk][128 + ty * 8];
            A3.f = *(const float4*)&Asd[buf][kk][128 + ty * 8 + 4];
            B0.f = *(const float4*)&Bs[buf][kk][tx * 4];
            B1.f = *(const float4*)&Bs[buf][kk][64 + tx * 4];
            u64 a2r[8] = {A0.u[0], A0.u[1], A1.u[0], A1.u[1],
                          A2.u[0], A2.u[1], A3.u[0], A3.u[1]};
            u64 b0 = B0.u[0], b1 = B0.u[1], b2 = B1.u[0], b3 = B1.u[1];
#pragma unroll
            for (int r = 0; r < 8; r++) {
                ffma2(acc2[r][0], a2r[r], b0);
                ffma2(acc2[r][1], a2r[r], b1);
                ffma2(acc2[r][2], a2r[r], b2);
                ffma2(acc2[r][3], a2r[r], b3);
            }
        }
        if (kt + 1 < NT) {
            const int nb = buf ^ 1;
            *(u64*)&Asd[nb][alc + 0][alr * 2] = dup2(av.x);
            *(u64*)&Asd[nb][alc + 1][alr * 2] = dup2(av.y);
            *(u64*)&Asd[nb][alc + 2][alr * 2] = dup2(av.z);
            *(u64*)&Asd[nb][alc + 3][alr * 2] = dup2(av.w);
            *(float4*)&Bs[nb][blr][blc] = bv;
        }
        __syncthreads();
    }
#pragma unroll
    for (int r = 0; r < 8; r++) {
        int gr = m0 + ((r < 4) ? (ty * 4 + r) : (64 + ty * 4 + (r - 4)));
#pragma unroll
        for (int half = 0; half < 2; half++) {
            int gc = n0 + ((half == 0) ? tx * 4 : 64 + tx * 4);
            float2 p0 = up2(acc2[r][half * 2 + 0]);
            float2 p1 = up2(acc2[r][half * 2 + 1]);
            float4 o; o.x = p0.x; o.y = p0.y; o.z = p1.x; o.w = p1.y;
            if (bias) {
                o.x += bias[gc]; o.y += bias[gc + 1];
                o.z += bias[gc + 2]; o.w += bias[gc + 3];
            }
            *(float4*)(C + (size_t)gr * Nn + gc) = o;
        }
    }
}

// -------- dots -> E fp32 + bf16, fused first row-sum; double buffered -------
__global__ __launch_bounds__(256) void qk_dots_exp(
    const float* __restrict__ qkv, float* __restrict__ E,
    __nv_bfloat16* __restrict__ Ebf, float* __restrict__ rowsum)
{
    const int bh = blockIdx.z, b = bh >> 3, h = bh & 7;
    const int i0 = blockIdx.y * 128, j0 = blockIdx.x * 128;
    const float* qbase = qkv + (size_t)b * SEQ * QKVW + h * DHEAD;
    const float* kbase = qkv + (size_t)b * SEQ * QKVW + 512 + h * DHEAD;

    __shared__ float Qsd[2][8][256];
    __shared__ float Ks[2][8][128];
    const int t = threadIdx.x;
    const int lr = t >> 1, lc = (t & 1) * 4;
    const int tx = t & 15, ty = t >> 4;

    u64 acc2[8][4];
#pragma unroll
    for (int r = 0; r < 8; r++)
#pragma unroll
        for (int c = 0; c < 4; c++) acc2[r][c] = 0ull;

    const float* qptr = qbase + (size_t)(i0 + lr) * QKVW + lc;
    const float* kptr = kbase + (size_t)(j0 + lr) * QKVW + lc;

    float4 qv = *(const float4*)(qptr);
    float4 kv = *(const float4*)(kptr);
    *(u64*)&Qsd[0][lc + 0][lr * 2] = dup2(qv.x);
    *(u64*)&Qsd[0][lc + 1][lr * 2] = dup2(qv.y);
    *(u64*)&Qsd[0][lc + 2][lr * 2] = dup2(qv.z);
    *(u64*)&Qsd[0][lc + 3][lr * 2] = dup2(qv.w);
    Ks[0][lc + 0][lr] = kv.x; Ks[0][lc + 1][lr] = kv.y;
    Ks[0][lc + 2][lr] = kv.z; Ks[0][lc + 3][lr] = kv.w;
    __syncthreads();

#pragma unroll
    for (int kt = 0; kt < 8; kt++) {
        const int buf = kt & 1;
        if (kt < 7) {
            qv = *(const float4*)(qptr + (kt + 1) * 8);
            kv = *(const float4*)(kptr + (kt + 1) * 8);
        }
#pragma unroll
        for (int kk = 0; kk < 8; kk++) {
            F4U A0, A1, A2, A3, B0, B1;
            A0.f = *(const float4*)&Qsd[buf][kk][ty * 8];
            A1.f = *(const float4*)&Qsd[buf][kk][ty * 8 + 4];
            A2.f = *(const float4*)&Qsd[buf][kk][128 + ty * 8];
            A3.f = *(const float4*)&Qsd[buf][kk][128 + ty * 8 + 4];
            B0.f = *(const float4*)&Ks[buf][kk][tx * 4];
            B1.f = *(const float4*)&Ks[buf][kk][64 + tx * 4];
            u64 a2r[8] = {A0.u[0], A0.u[1], A1.u[0], A1.u[1],
                          A2.u[0], A2.u[1], A3.u[0], A3.u[1]};
            u64 b0 = B0.u[0], b1 = B0.u[1], b2 = B1.u[0], b3 = B1.u[1];
#pragma unroll
            for (int r = 0; r < 8; r++) {
                ffma2(acc2[r][0], a2r[r], b0);
                ffma2(acc2[r][1], a2r[r], b1);
                ffma2(acc2[r][2], a2r[r], b2);
                ffma2(acc2[r][3], a2r[r], b3);
            }
        }
        if (kt < 7) {
            const int nb = buf ^ 1;
            *(u64*)&Qsd[nb][lc + 0][lr * 2] = dup2(qv.x);
            *(u64*)&Qsd[nb][lc + 1][lr * 2] = dup2(qv.y);
            *(u64*)&Qsd[nb][lc + 2][lr * 2] = dup2(qv.z);
            *(u64*)&Qsd[nb][lc + 3][lr * 2] = dup2(qv.w);
            Ks[nb][lc + 0][lr] = kv.x; Ks[nb][lc + 1][lr] = kv.y;
            Ks[nb][lc + 2][lr] = kv.z; Ks[nb][lc + 3][lr] = kv.w;
        }
        __syncthreads();
    }

    float* Ep = E + (size_t)bh * SEQ * SEQ;
    __nv_bfloat16* Ebp = Ebf + (size_t)bh * SEQ * SEQ;
    float rsum[8];
#pragma unroll
    for (int r = 0; r < 8; r++) rsum[r] = 0.f;
#pragma unroll
    for (int r = 0; r < 8; r++) {
        int gi = i0 + ((r < 4) ? (ty * 4 + r) : (64 + ty * 4 + (r - 4)));
#pragma unroll
        for (int half = 0; half < 2; half++) {
            int gj = j0 + ((half == 0) ? tx * 4 : 64 + tx * 4);
            float2 p0 = up2(acc2[r][half * 2 + 0]);
            float2 p1 = up2(acc2[r][half * 2 + 1]);
            float4 o;
            o.x = __expf(-0.125f * p0.x);
            o.y = __expf(-0.125f * p0.y);
            o.z = __expf(-0.125f * p1.x);
            o.w = __expf(-0.125f * p1.y);
            rsum[r] += o.x + o.y + o.z + o.w;
            *(float4*)(Ep + (size_t)gi * SEQ + gj) = o;
            union { __nv_bfloat162 h[2]; uint2 u; } pk;
            pk.h[0] = __floats2bfloat162_rn(o.x, o.y);
            pk.h[1] = __floats2bfloat162_rn(o.z, o.w);
            *(uint2*)(Ebp + (size_t)gi * SEQ + gj) = pk.u;
        }
    }
#pragma unroll
    for (int r = 0; r < 8; r++) {
#pragma unroll
        for (int off = 1; off < 16; off <<= 1)
            rsum[r] += __shfl_xor_sync(0xffffffffu, rsum[r], off);
    }
    if (tx == 0) {
#pragma unroll
        for (int r = 0; r < 8; r++) {
            int gi = i0 + ((r < 4) ? (ty * 4 + r) : (64 + ty * 4 + (r - 4)));
            atomicAdd(&rowsum[bh * SEQ + gi], rsum[r]);
        }
    }
}

// ---- col pass over bf16 E: colsum_j += sum_i E_ij * rs_i -------------------
__global__ __launch_bounds__(256) void colpass_bf(
    const __nv_bfloat16* __restrict__ Eb, const float* __restrict__ rvec,
    float* __restrict__ colsum, int recip)
{
    const int bh = blockIdx.y;
    const int i0 = blockIdx.x * 64;
    const int t = threadIdx.x;
    __shared__ float rs[64];
    if (t < 64) {
        float rv = rvec[bh * SEQ + i0 + t];
        rs[t] = recip ? (MU_C / rv) : rv;
    }
    __syncthreads();

    const __nv_bfloat16* Ep = Eb + (size_t)bh * SEQ * SEQ + (size_t)i0 * SEQ;
    const int j = t * 4;
    float ax = 0.f, ay = 0.f, az = 0.f, aw = 0.f;
#pragma unroll 4
    for (int i = 0; i < 64; i++) {
        uint2 raw = *(const uint2*)(Ep + (size_t)i * SEQ + j);
        float2 f0 = __bfloat1622float2(*(__nv_bfloat162*)&raw.x);
        float2 f1 = __bfloat1622float2(*(__nv_bfloat162*)&raw.y);
        float rv = rs[i];
        ax = fmaf(f0.x, rv, ax); ay = fmaf(f0.y, rv, ay);
        az = fmaf(f1.x, rv, az); aw = fmaf(f1.y, rv, aw);
    }
    atomicAdd(&colsum[bh * SEQ + j + 0], ax);
    atomicAdd(&colsum[bh * SEQ + j + 1], ay);
    atomicAdd(&colsum[bh * SEQ + j + 2], az);
    atomicAdd(&colsum[bh * SEQ + j + 3], aw);
}

// ---- row pass over bf16 E: r_i = MU / sum_j E_ij * (NU/colsum_j) -----------
__global__ __launch_bounds__(256) void rowpass_bf(
    const __nv_bfloat16* __restrict__ Eb, const float* __restrict__ colsum,
    float* __restrict__ r)
{
    const int bh = blockIdx.y;
    const int t = threadIdx.x, lane = t & 31, w = t >> 5;
    const int row = blockIdx.x * 8 + w;
    __shared__ float cs[SEQ];
    {
        float4 cv = *(const float4*)(colsum + bh * SEQ + t * 4);
        cs[t * 4 + 0] = NU_C / cv.x;
        cs[t * 4 + 1] = NU_C / cv.y;
        cs[t * 4 + 2] = NU_C / cv.z;
        cs[t * 4 + 3] = NU_C / cv.w;
    }
    __syncthreads();

    const __nv_bfloat16* Er = Eb + (size_t)bh * SEQ * SEQ + (size_t)row * SEQ;
    float acc = 0.f;
#pragma unroll
    for (int it = 0; it < 8; it++) {
        int j = it * 128 + lane * 4;
        uint2 raw = *(const uint2*)(Er + j);
        float2 f0 = __bfloat1622float2(*(__nv_bfloat162*)&raw.x);
        float2 f1 = __bfloat1622float2(*(__nv_bfloat162*)&raw.y);
        acc += f0.x * cs[j] + f0.y * cs[j + 1] + f1.x * cs[j + 2] + f1.y * cs[j + 3];
    }
#pragma unroll
    for (int o = 16; o > 0; o >>= 1)
        acc += __shfl_xor_sync(0xffffffffu, acc, o);
    if (lane == 0) r[bh * SEQ + row] = MU_C / acc;
}

__global__ void init_sums(float* __restrict__ rowsum, float* __restrict__ c1,
                          float* __restrict__ c2, float* __restrict__ c3)
{
    int i = blockIdx.x * 256 + threadIdx.x;
    rowsum[i] = 0.f; c1[i] = 0.f; c2[i] = 0.f; c3[i] = 0.f;
}

// -------- per-head GEMM: ho = rn_i * (E @ (c_j V)), fused attn write --------
// dynamic smem: Est[2][32][260] (k x dup-i), Ws[2][32][64], cr[1024], rn[128]
#define AV_ESTSZ (32 * 260)
#define AV_WS    (2 * AV_ESTSZ)
#define AV_WSSZ  (32 * 64)
#define AV_CR    (AV_WS + 2 * AV_WSSZ)
#define AV_RN    (AV_CR + 1024)
#define AV_TOT   (AV_RN + 128)

__global__ __launch_bounds__(128) void av_gemm(
    const float* __restrict__ E, const float* __restrict__ r,
    const float* __restrict__ colsum3, const float* __restrict__ qkv,
    float* __restrict__ attn, float* __restrict__ ho, int write_attn)
{
    extern __shared__ float dsh[];
    float* Est = dsh;
    float* Ws  = dsh + AV_WS;
    float* cr  = dsh + AV_CR;
    float* rn  = dsh + AV_RN;

    const int bh = blockIdx.y, b = bh >> 3, h = bh & 7;
    const int i0 = blockIdx.x * 128;
    const int t = threadIdx.x;
    const int tx = t & 7, ty = t >> 3;
    const int vk0 = t >> 4, vd0 = (t & 15) * 4;   // V loader coords

    if (t < 128) rn[t] = r[bh * SEQ + i0 + t] * 1024.0f;
#pragma unroll
    for (int q = 0; q < 8; q++) {
        int j = t + 128 * q;
        cr[j] = NU_C / colsum3[bh * SEQ + j];
    }
    __syncthreads();

    const float* Ep = E + (size_t)bh * SEQ * SEQ;
    const float* vb = qkv + (size_t)b * SEQ * QKVW + 1024 + h * DHEAD;
    float* ap = attn + (size_t)bh * SEQ * SEQ;

    u64 acc2[8][4];
#pragma unroll
    for (int rr = 0; rr < 8; rr++)
#pragma unroll
        for (int cc = 0; cc < 4; cc++) acc2[rr][cc] = 0ull;

    float4 er[8], vr[4];

    // ---- tile 0 load + attn write ----
#pragma unroll
    for (int q = 0; q < 8; q++) {
        int i = ty + 16 * q;
        er[q] = *(const float4*)(Ep + (size_t)(i0 + i) * SEQ + tx * 4);
        if (write_attn) {
            float rv = rn[i];
            float4 o;
            o.x = rv * er[q].x * cr[tx * 4 + 0];
            o.y = rv * er[q].y * cr[tx * 4 + 1];
            o.z = rv * er[q].z * cr[tx * 4 + 2];
            o.w = rv * er[q].w * cr[tx * 4 + 3];
            *(float4*)(ap + (size_t)(i0 + i) * SEQ + tx * 4) = o;
        }
    }
#pragma unroll
    for (int q = 0; q < 4; q++)
        vr[q] = *(const float4*)(vb + (size_t)(vk0 + 8 * q) * QKVW + vd0);
    // store tile 0 to buf 0
#pragma unroll
    for (int q = 0; q < 8; q++) {
        int i = ty + 16 * q;
        float* eb = Est + 0 * AV_ESTSZ;
        *(u64*)&eb[(tx * 4 + 0) * 260 + i * 2] = dup2(er[q].x);
        *(u64*)&eb[(tx * 4 + 1) * 260 + i * 2] = dup2(er[q].y);
        *(u64*)&eb[(tx * 4 + 2) * 260 + i * 2] = dup2(er[q].z);
        *(u64*)&eb[(tx * 4 + 3) * 260 + i * 2] = dup2(er[q].w);
    }
#pragma unroll
    for (int q = 0; q < 4; q++) {
        int k = vk0 + 8 * q;
        float cw = cr[k];
        float4 v = vr[q];
        v.x *= cw; v.y *= cw; v.z *= cw; v.w *= cw;
        *(float4*)&Ws[0 * AV_WSSZ + k * 64 + vd0] = v;
    }
    __syncthreads();

    for (int jt = 0; jt < 32; jt++) {
        const int buf = jt & 1;
        const int j0n = (jt + 1) * 32;
        if (jt + 1 < 32) {
#pragma unroll
            for (int q = 0; q < 8; q++) {
                int i = ty + 16 * q;
                er[q] = *(const float4*)(Ep + (size_t)(i0 + i) * SEQ + j0n + tx * 4);
                if (write_attn) {
                    float rv = rn[i];
                    float4 o;
                    o.x = rv * er[q].x * cr[j0n + tx * 4 + 0];
                    o.y = rv * er[q].y * cr[j0n + tx * 4 + 1];
                    o.z = rv * er[q].z * cr[j0n + tx * 4 + 2];
                    o.w = rv * er[q].w * cr[j0n + tx * 4 + 3];
                    *(float4*)(ap + (size_t)(i0 + i) * SEQ + j0n + tx * 4) = o;
                }
            }
#pragma unroll
            for (int q = 0; q < 4; q++)
                vr[q] = *(const float4*)(vb + (size_t)(j0n + vk0 + 8 * q) * QKVW + vd0);
        }
        // compute on buf
        const float* eb = Est + buf * AV_ESTSZ;
        const float* wb = Ws + buf * AV_WSSZ;
#pragma unroll
        for (int kk = 0; kk < 32; kk++) {
            F4U A0, A1, A2, A3, B0, B1;
            A0.f = *(const float4*)&eb[kk * 260 + ty * 16];
            A1.f = *(const float4*)&eb[kk * 260 + ty * 16 + 4];
            A2.f = *(const float4*)&eb[kk * 260 + ty * 16 + 8];
            A3.f = *(const float4*)&eb[kk * 260 + ty * 16 + 12];
            B0.f = *(const float4*)&wb[kk * 64 + tx * 8];
            B1.f = *(const float4*)&wb[kk * 64 + tx * 8 + 4];
            u64 a2r[8] = {A0.u[0], A0.u[1], A1.u[0], A1.u[1],
                          A2.u[0], A2.u[1], A3.u[0], A3.u[1]};
            u64 b0 = B0.u[0], b1 = B0.u[1], b2 = B1.u[0], b3 = B1.u[1];
#pragma unroll
            for (int rr = 0; rr < 8; rr++) {
                ffma2(acc2[rr][0], a2r[rr], b0);
                ffma2(acc2[rr][1], a2r[rr], b1);
                ffma2(acc2[rr][2], a2r[rr], b2);
                ffma2(acc2[rr][3], a2r[rr], b3);
            }
        }
        if (jt + 1 < 32) {
            const int nb = buf ^ 1;
            float* ebw = Est + nb * AV_ESTSZ;
#pragma unroll
            for (int q = 0; q < 8; q++) {
                int i = ty + 16 * q;
                *(u64*)&ebw[(tx * 4 + 0) * 260 + i * 2] = dup2(er[q].x);
                *(u64*)&ebw[(tx * 4 + 1) * 260 + i * 2] = dup2(er[q].y);
                *(u64*)&ebw[(tx * 4 + 2) * 260 + i * 2] = dup2(er[q].z);
                *(u64*)&ebw[(tx * 4 + 3) * 260 + i * 2] = dup2(er[q].w);
            }
#pragma unroll
            for (int q = 0; q < 4; q++) {
                int k = vk0 + 8 * q;
                float cw = cr[j0n + k];
                float4 v = vr[q];
                v.x *= cw; v.y *= cw; v.z *= cw; v.w *= cw;
                *(float4*)&Ws[nb * AV_WSSZ + k * 64 + vd0] = v;
            }
        }
        __syncthreads();
    }
#pragma unroll
    for (int rr = 0; rr < 8; rr++) {
        float rv = rn[ty * 8 + rr];
        float* hp = ho + (size_t)(b * SEQ + i0 + ty * 8 + rr) * DIMV + h * DHEAD + tx * 8;
        float2 p0 = up2(acc2[rr][0]);
        float2 p1 = up2(acc2[rr][1]);
        float2 p2 = up2(acc2[rr][2]);
        float2 p3 = up2(acc2[rr][3]);
        float4 o0, o1;
        o0.x = p0.x * rv; o0.y = p0.y * rv; o0.z = p1.x * rv; o0.w = p1.y * rv;
        o1.x = p2.x * rv; o1.y = p2.y * rv; o1.z = p3.x * rv; o1.w = p3.y * rv;
        *(float4*)(hp) = o0;
        *(float4*)(hp + 4) = o1;
    }
}

// ---------------- launcher ---------------------------------------------------
extern "C" void kernel_launch(void* const* d_in, const int* in_sizes, int n_in,
                              void* d_out, int out_size)
{
    const float* x    = (const float*)d_in[0];
    const float* Wqkv = (const float*)d_in[1];
    const float* Wout = (const float*)d_in[2];
    const float* bout = (const float*)d_in[3];
    float* out = (float*)d_out;

    float *qkvp, *Ep, *rp, *rsp, *c1p, *c2p, *c3p, *hop;
    __nv_bfloat16* Ebp;
    cudaGetSymbolAddress((void**)&qkvp, g_qkv);
    cudaGetSymbolAddress((void**)&Ep,   g_E);
    cudaGetSymbolAddress((void**)&Ebp,  g_Ebf);
    cudaGetSymbolAddress((void**)&rp,   g_r);
    cudaGetSymbolAddress((void**)&rsp,  g_rowsum);
    cudaGetSymbolAddress((void**)&c1p,  g_cs1);
    cudaGetSymbolAddress((void**)&c2p,  g_cs2);
    cudaGetSymbolAddress((void**)&c3p,  g_cs3);
    cudaGetSymbolAddress((void**)&hop,  g_ho);

    const size_t FIN = (size_t)BQ * SEQ * DIMV;
    const size_t ATT = (size_t)NHEADS * SEQ * SEQ;
    float* fin_ptr = 0;
    float* attn_ptr = 0;
    if ((size_t)out_size >= FIN + ATT) { fin_ptr = out; attn_ptr = out + FIN; }
    else if ((size_t)out_size == ATT)  { attn_ptr = out; }
    else                               { fin_ptr = out; }

    const int NV = NHEADS * SEQ;
    const int AV_SMEM = AV_TOT * 4;
    cudaFuncSetAttribute(av_gemm, cudaFuncAttributeMaxDynamicSharedMemorySize,
                         AV_SMEM);

    init_sums<<<NV / 256, 256>>>(rsp, c1p, c2p, c3p);

    // 1) qkv = x @ W_qkv
    sgemm128<<<dim3(QKVW / 128, (BQ * SEQ) / 128), 256>>>(
        x, Wqkv, qkvp, BQ * SEQ, QKVW, DIMV, (const float*)0);

    // 2) E = exp(-scale*q k^T) fp32 + bf16 shadow, fused rowsum (c0 = 1)
    qk_dots_exp<<<dim3(SEQ / 128, SEQ / 128, NHEADS), 256>>>(qkvp, Ep, Ebp, rsp);

    // 3) Sinkhorn over bf16 E: col1, row2, col2, row3, col3
    colpass_bf<<<dim3(SEQ / 64, NHEADS), 256>>>(Ebp, rsp, c1p, 1);
    rowpass_bf<<<dim3(SEQ / 8, NHEADS), 256>>>(Ebp, c1p, rp);
    colpass_bf<<<dim3(SEQ / 64, NHEADS), 256>>>(Ebp, rp, c2p, 0);
    rowpass_bf<<<dim3(SEQ / 8, NHEADS), 256>>>(Ebp, c2p, rp);
    colpass_bf<<<dim3(SEQ / 64, NHEADS), 256>>>(Ebp, rp, c3p, 0);

    // 4) attn = r*E*c*n (fused write) and ho = attn @ V, per head
    av_gemm<<<dim3(SEQ / 128, NHEADS), 128, AV_SMEM>>>(
        Ep, rp, c3p, qkvp, attn_ptr ? attn_ptr : Ep, hop, attn_ptr ? 1 : 0);

    // 5) final = ho @ W_out + b_out
    if (fin_ptr)
        sgemm128<<<dim3(DIMV / 128, (BQ * SEQ) / 128), 256>>>(
            hop, Wout, fin_ptr, BQ * SEQ, DIMV, DIMV, bout);
}

// round 7
// speedup vs baseline: 1.1740x; 1.1740x over previous
#include <cuda_runtime.h>
#include <cuda_bf16.h>
#include <math.h>

#define BQ 8
#define SEQ 1024
#define DIMV 512
#define HEADS 8
#define DHEAD 64
#define NHEADS 64        // BQ*HEADS
#define QKVW 1536        // 3*HEADS*DHEAD

#define MU_C (1.0f/1024.0f)
#define NU_C (1.0f/1024.0f)

typedef unsigned long long u64;

__device__ __forceinline__ u64 dup2(float v) {
    u64 r; asm("mov.b64 %0, {%1, %1};" : "=l"(r) : "f"(v)); return r;
}
__device__ __forceinline__ void ffma2(u64& d, u64 a, u64 b) {
    asm("fma.rn.f32x2 %0, %1, %2, %0;" : "+l"(d) : "l"(a), "l"(b));
}
__device__ __forceinline__ float2 up2(u64 v) {
    float2 f; asm("mov.b64 {%0, %1}, %2;" : "=f"(f.x), "=f"(f.y) : "l"(v)); return f;
}

// ---------------- scratch (device globals; no allocations allowed) ----------
__device__ float g_qkv[(size_t)BQ * SEQ * QKVW];
__device__ float g_E[(size_t)NHEADS * SEQ * SEQ];            // E = exp(-C) fp32
__device__ __nv_bfloat16 g_Ebf[(size_t)NHEADS * SEQ * SEQ];  // bf16 shadow
__device__ float g_r[NHEADS * SEQ];
__device__ float g_rowsum[NHEADS * SEQ];
__device__ float g_cs1[NHEADS * SEQ];
__device__ float g_cs2[NHEADS * SEQ];
__device__ float g_cs3[NHEADS * SEQ];
__device__ float g_ho[(size_t)BQ * SEQ * DIMV];

// ---------------- 128x128x8 fp32 GEMM with fma.rn.f32x2 ---------------------
__global__ __launch_bounds__(256) void sgemm128(
    const float* __restrict__ A, const float* __restrict__ Bm,
    float* __restrict__ C, int M, int Nn, int K, const float* __restrict__ bias)
{
    __shared__ float As[8][128];
    __shared__ float Bs[8][128];
    const int t = threadIdx.x;
    const int m0 = blockIdx.y * 128, n0 = blockIdx.x * 128;
    const int alr = t >> 1, alc = (t & 1) * 4;
    const int blr = t >> 5, blc = (t & 31) * 4;
    const int tx = t & 15, ty = t >> 4;

    u64 acc2[8][4];
#pragma unroll
    for (int r = 0; r < 8; r++)
#pragma unroll
        for (int c = 0; c < 4; c++) acc2[r][c] = 0ull;

    for (int k0 = 0; k0 < K; k0 += 8) {
        float4 av = *(const float4*)(A + (size_t)(m0 + alr) * K + k0 + alc);
        As[alc + 0][alr] = av.x; As[alc + 1][alr] = av.y;
        As[alc + 2][alr] = av.z; As[alc + 3][alr] = av.w;
        *(float4*)(&Bs[blr][blc]) =
            *(const float4*)(Bm + (size_t)(k0 + blr) * Nn + n0 + blc);
        __syncthreads();
#pragma unroll
        for (int kk = 0; kk < 8; kk++) {
            float4 A0 = *(const float4*)(&As[kk][ty * 4]);
            float4 A1 = *(const float4*)(&As[kk][64 + ty * 4]);
            u64 b0 = *(const u64*)(&Bs[kk][tx * 4]);
            u64 b1 = *(const u64*)(&Bs[kk][tx * 4 + 2]);
            u64 b2 = *(const u64*)(&Bs[kk][64 + tx * 4]);
            u64 b3 = *(const u64*)(&Bs[kk][64 + tx * 4 + 2]);
            u64 a2[8];
            a2[0] = dup2(A0.x); a2[1] = dup2(A0.y);
            a2[2] = dup2(A0.z); a2[3] = dup2(A0.w);
            a2[4] = dup2(A1.x); a2[5] = dup2(A1.y);
            a2[6] = dup2(A1.z); a2[7] = dup2(A1.w);
#pragma unroll
            for (int r = 0; r < 8; r++) {
                ffma2(acc2[r][0], a2[r], b0);
                ffma2(acc2[r][1], a2[r], b1);
                ffma2(acc2[r][2], a2[r], b2);
                ffma2(acc2[r][3], a2[r], b3);
            }
        }
        __syncthreads();
    }
#pragma unroll
    for (int r = 0; r < 8; r++) {
        int gr = m0 + ((r < 4) ? (ty * 4 + r) : (64 + ty * 4 + (r - 4)));
#pragma unroll
        for (int half = 0; half < 2; half++) {
            int gc = n0 + ((half == 0) ? tx * 4 : 64 + tx * 4);
            float2 p0 = up2(acc2[r][half * 2 + 0]);
            float2 p1 = up2(acc2[r][half * 2 + 1]);
            float4 o; o.x = p0.x; o.y = p0.y; o.z = p1.x; o.w = p1.y;
            if (bias) {
                o.x += bias[gc]; o.y += bias[gc + 1];
                o.z += bias[gc + 2]; o.w += bias[gc + 3];
            }
            *(float4*)(C + (size_t)gr * Nn + gc) = o;
        }
    }
}

// -------- per-head dots -> E fp32 + bf16 shadow, fused first row-sum --------
__global__ __launch_bounds__(256) void qk_dots_exp(
    const float* __restrict__ qkv, float* __restrict__ E,
    __nv_bfloat16* __restrict__ Ebf, float* __restrict__ rowsum)
{
    const int bh = blockIdx.z, b = bh >> 3, h = bh & 7;
    const int i0 = blockIdx.y * 128, j0 = blockIdx.x * 128;
    const float* qbase = qkv + (size_t)b * SEQ * QKVW + h * DHEAD;
    const float* kbase = qkv + (size_t)b * SEQ * QKVW + 512 + h * DHEAD;

    __shared__ float Qs[8][128];
    __shared__ float Ks[8][128];
    const int t = threadIdx.x;
    const int lr = t >> 1, lc = (t & 1) * 4;
    const int tx = t & 15, ty = t >> 4;

    u64 acc2[8][4];
#pragma unroll
    for (int r = 0; r < 8; r++)
#pragma unroll
        for (int c = 0; c < 4; c++) acc2[r][c] = 0ull;

    for (int k0 = 0; k0 < DHEAD; k0 += 8) {
        float4 qv = *(const float4*)(qbase + (size_t)(i0 + lr) * QKVW + k0 + lc);
        Qs[lc + 0][lr] = qv.x; Qs[lc + 1][lr] = qv.y;
        Qs[lc + 2][lr] = qv.z; Qs[lc + 3][lr] = qv.w;
        float4 kv = *(const float4*)(kbase + (size_t)(j0 + lr) * QKVW + k0 + lc);
        Ks[lc + 0][lr] = kv.x; Ks[lc + 1][lr] = kv.y;
        Ks[lc + 2][lr] = kv.z; Ks[lc + 3][lr] = kv.w;
        __syncthreads();
#pragma unroll
        for (int kk = 0; kk < 8; kk++) {
            float4 A0 = *(const float4*)(&Qs[kk][ty * 4]);
            float4 A1 = *(const float4*)(&Qs[kk][64 + ty * 4]);
            u64 b0 = *(const u64*)(&Ks[kk][tx * 4]);
            u64 b1 = *(const u64*)(&Ks[kk][tx * 4 + 2]);
            u64 b2 = *(const u64*)(&Ks[kk][64 + tx * 4]);
            u64 b3 = *(const u64*)(&Ks[kk][64 + tx * 4 + 2]);
            u64 a2[8];
            a2[0] = dup2(A0.x); a2[1] = dup2(A0.y);
            a2[2] = dup2(A0.z); a2[3] = dup2(A0.w);
            a2[4] = dup2(A1.x); a2[5] = dup2(A1.y);
            a2[6] = dup2(A1.z); a2[7] = dup2(A1.w);
#pragma unroll
            for (int r = 0; r < 8; r++) {
                ffma2(acc2[r][0], a2[r], b0);
                ffma2(acc2[r][1], a2[r], b1);
                ffma2(acc2[r][2], a2[r], b2);
                ffma2(acc2[r][3], a2[r], b3);
            }
        }
        __syncthreads();
    }
    float* Ep = E + (size_t)bh * SEQ * SEQ;
    __nv_bfloat16* Ebp = Ebf + (size_t)bh * SEQ * SEQ;
    float rsum[8];
#pragma unroll
    for (int r = 0; r < 8; r++) rsum[r] = 0.f;
#pragma unroll
    for (int r = 0; r < 8; r++) {
        int gi = i0 + ((r < 4) ? (ty * 4 + r) : (64 + ty * 4 + (r - 4)));
#pragma unroll
        for (int half = 0; half < 2; half++) {
            int gj = j0 + ((half == 0) ? tx * 4 : 64 + tx * 4);
            float2 p0 = up2(acc2[r][half * 2 + 0]);
            float2 p1 = up2(acc2[r][half * 2 + 1]);
            float4 o;
            o.x = __expf(-0.125f * p0.x);
            o.y = __expf(-0.125f * p0.y);
            o.z = __expf(-0.125f * p1.x);
            o.w = __expf(-0.125f * p1.y);
            rsum[r] += o.x + o.y + o.z + o.w;
            *(float4*)(Ep + (size_t)gi * SEQ + gj) = o;
            union { __nv_bfloat162 h[2]; uint2 u; } pk;
            pk.h[0] = __floats2bfloat162_rn(o.x, o.y);
            pk.h[1] = __floats2bfloat162_rn(o.z, o.w);
            *(uint2*)(Ebp + (size_t)gi * SEQ + gj) = pk.u;
        }
    }
#pragma unroll
    for (int r = 0; r < 8; r++) {
#pragma unroll
        for (int off = 1; off < 16; off <<= 1)
            rsum[r] += __shfl_xor_sync(0xffffffffu, rsum[r], off);
    }
    if (tx == 0) {
#pragma unroll
        for (int r = 0; r < 8; r++) {
            int gi = i0 + ((r < 4) ? (ty * 4 + r) : (64 + ty * 4 + (r - 4)));
            atomicAdd(&rowsum[bh * SEQ + gi], rsum[r]);
        }
    }
}

// ---- col pass over bf16 E: colsum_j += sum_i E_ij * rs_i -------------------
__global__ __launch_bounds__(256) void colpass_bf(
    const __nv_bfloat16* __restrict__ Eb, const float* __restrict__ rvec,
    float* __restrict__ colsum, int recip)
{
    const int bh = blockIdx.y;
    const int i0 = blockIdx.x * 64;
    const int t = threadIdx.x;
    __shared__ float rs[64];
    if (t < 64) {
        float rv = rvec[bh * SEQ + i0 + t];
        rs[t] = recip ? (MU_C / rv) : rv;
    }
    __syncthreads();

    const __nv_bfloat16* Ep = Eb + (size_t)bh * SEQ * SEQ + (size_t)i0 * SEQ;
    const int j = t * 4;
    float ax = 0.f, ay = 0.f, az = 0.f, aw = 0.f;
#pragma unroll 4
    for (int i = 0; i < 64; i++) {
        uint2 raw = *(const uint2*)(Ep + (size_t)i * SEQ + j);
        float2 f0 = __bfloat1622float2(*(__nv_bfloat162*)&raw.x);
        float2 f1 = __bfloat1622float2(*(__nv_bfloat162*)&raw.y);
        float rv = rs[i];
        ax = fmaf(f0.x, rv, ax); ay = fmaf(f0.y, rv, ay);
        az = fmaf(f1.x, rv, az); aw = fmaf(f1.y, rv, aw);
    }
    atomicAdd(&colsum[bh * SEQ + j + 0], ax);
    atomicAdd(&colsum[bh * SEQ + j + 1], ay);
    atomicAdd(&colsum[bh * SEQ + j + 2], az);
    atomicAdd(&colsum[bh * SEQ + j + 3], aw);
}

// ---- row pass over bf16 E: r_i = MU / sum_j E_ij * (NU/colsum_j) -----------
__global__ __launch_bounds__(256) void rowpass_bf(
    const __nv_bfloat16* __restrict__ Eb, const float* __restrict__ colsum,
    float* __restrict__ r)
{
    const int bh = blockIdx.y;
    const int t = threadIdx.x, lane = t & 31, w = t >> 5;
    const int row = blockIdx.x * 8 + w;
    __shared__ float cs[SEQ];
    {
        float4 cv = *(const float4*)(colsum + bh * SEQ + t * 4);
        cs[t * 4 + 0] = NU_C / cv.x;
        cs[t * 4 + 1] = NU_C / cv.y;
        cs[t * 4 + 2] = NU_C / cv.z;
        cs[t * 4 + 3] = NU_C / cv.w;
    }
    __syncthreads();

    const __nv_bfloat16* Er = Eb + (size_t)bh * SEQ * SEQ + (size_t)row * SEQ;
    float acc = 0.f;
#pragma unroll
    for (int it = 0; it < 8; it++) {
        int j = it * 128 + lane * 4;
        uint2 raw = *(const uint2*)(Er + j);
        float2 f0 = __bfloat1622float2(*(__nv_bfloat162*)&raw.x);
        float2 f1 = __bfloat1622float2(*(__nv_bfloat162*)&raw.y);
        acc += f0.x * cs[j] + f0.y * cs[j + 1] + f1.x * cs[j + 2] + f1.y * cs[j + 3];
    }
#pragma unroll
    for (int o = 16; o > 0; o >>= 1)
        acc += __shfl_xor_sync(0xffffffffu, acc, o);
    if (lane == 0) r[bh * SEQ + row] = MU_C / acc;
}

__global__ void init_sums(float* __restrict__ rowsum, float* __restrict__ c1,
                          float* __restrict__ c2, float* __restrict__ c3)
{
    int i = blockIdx.x * 256 + threadIdx.x;
    rowsum[i] = 0.f; c1[i] = 0.f; c2[i] = 0.f; c3[i] = 0.f;
}

// -------- per-head GEMM: ho = rn_i * (E @ (c_j V)), fused attn write --------
__global__ __launch_bounds__(128) void av_gemm(
    const float* __restrict__ E, const float* __restrict__ r,
    const float* __restrict__ colsum3, const float* __restrict__ qkv,
    float* __restrict__ attn, float* __restrict__ ho, int write_attn)
{
    const int bh = blockIdx.y, b = bh >> 3, h = bh & 7;
    const int i0 = blockIdx.x * 128;
    const int t = threadIdx.x;
    const int tx = t & 7, ty = t >> 3;

    __shared__ float Es[128][33];
    __shared__ float Ws[32][64];
    __shared__ float cr[SEQ];
    __shared__ float rn[128];

    if (t < 128) rn[t] = r[bh * SEQ + i0 + t] * 1024.0f;
#pragma unroll
    for (int q = 0; q < 8; q++) {
        int j = t + 128 * q;
        cr[j] = NU_C / colsum3[bh * SEQ + j];
    }
    __syncthreads();

    const float* Ep = E + (size_t)bh * SEQ * SEQ;
    const float* vb = qkv + (size_t)b * SEQ * QKVW + 1024 + h * DHEAD;
    float* ap = attn + (size_t)bh * SEQ * SEQ;

    u64 acc2[8][4];
#pragma unroll
    for (int rr = 0; rr < 8; rr++)
#pragma unroll
        for (int cc = 0; cc < 4; cc++) acc2[rr][cc] = 0ull;

    for (int jt = 0; jt < 32; jt++) {
        const int j0 = jt * 32;
#pragma unroll
        for (int q = 0; q < 8; q++) {
            int f = t + 128 * q;
            int i = f >> 3, jq = (f & 7) * 4;
            float4 e = *(const float4*)(Ep + (size_t)(i0 + i) * SEQ + j0 + jq);
            Es[i][jq + 0] = e.x; Es[i][jq + 1] = e.y;
            Es[i][jq + 2] = e.z; Es[i][jq + 3] = e.w;
            if (write_attn) {
                float rv = rn[i];
                float4 o;
                o.x = rv * e.x * cr[j0 + jq + 0];
                o.y = rv * e.y * cr[j0 + jq + 1];
                o.z = rv * e.z * cr[j0 + jq + 2];
                o.w = rv * e.w * cr[j0 + jq + 3];
                *(float4*)(ap + (size_t)(i0 + i) * SEQ + j0 + jq) = o;
            }
        }
#pragma unroll
        for (int q = 0; q < 4; q++) {
            int f = t + 128 * q;
            int k = f >> 4, dq = (f & 15) * 4;
            float4 v = *(const float4*)(vb + (size_t)(j0 + k) * QKVW + dq);
            float cw = cr[j0 + k];
            v.x *= cw; v.y *= cw; v.z *= cw; v.w *= cw;
            *(float4*)(&Ws[k][dq]) = v;
        }
        __syncthreads();
#pragma unroll
        for (int kk = 0; kk < 32; kk++) {
            u64 b0 = *(const u64*)(&Ws[kk][tx * 8]);
            u64 b1 = *(const u64*)(&Ws[kk][tx * 8 + 2]);
            u64 b2 = *(const u64*)(&Ws[kk][tx * 8 + 4]);
            u64 b3 = *(const u64*)(&Ws[kk][tx * 8 + 6]);
            u64 a2[8];
#pragma unroll
            for (int rr = 0; rr < 8; rr++) a2[rr] = dup2(Es[ty * 8 + rr][kk]);
#pragma unroll
            for (int rr = 0; rr < 8; rr++) {
                ffma2(acc2[rr][0], a2[rr], b0);
                ffma2(acc2[rr][1], a2[rr], b1);
                ffma2(acc2[rr][2], a2[rr], b2);
                ffma2(acc2[rr][3], a2[rr], b3);
            }
        }
        __syncthreads();
    }
#pragma unroll
    for (int rr = 0; rr < 8; rr++) {
        float rv = rn[ty * 8 + rr];
        float* hp = ho + (size_t)(b * SEQ + i0 + ty * 8 + rr) * DIMV + h * DHEAD + tx * 8;
        float2 p0 = up2(acc2[rr][0]);
        float2 p1 = up2(acc2[rr][1]);
        float2 p2 = up2(acc2[rr][2]);
        float2 p3 = up2(acc2[rr][3]);
        float4 o0, o1;
        o0.x = p0.x * rv; o0.y = p0.y * rv; o0.z = p1.x * rv; o0.w = p1.y * rv;
        o1.x = p2.x * rv; o1.y = p2.y * rv; o1.z = p3.x * rv; o1.w = p3.y * rv;
        *(float4*)(hp) = o0;
        *(float4*)(hp + 4) = o1;
    }
}

// ---------------- launcher ---------------------------------------------------
extern "C" void kernel_launch(void* const* d_in, const int* in_sizes, int n_in,
                              void* d_out, int out_size)
{
    const float* x    = (const float*)d_in[0];
    const float* Wqkv = (const float*)d_in[1];
    const float* Wout = (const float*)d_in[2];
    const float* bout = (const float*)d_in[3];
    float* out = (float*)d_out;

    float *qkvp, *Ep, *rp, *rsp, *c1p, *c2p, *c3p, *hop;
    __nv_bfloat16* Ebp;
    cudaGetSymbolAddress((void**)&qkvp, g_qkv);
    cudaGetSymbolAddress((void**)&Ep,   g_E);
    cudaGetSymbolAddress((void**)&Ebp,  g_Ebf);
    cudaGetSymbolAddress((void**)&rp,   g_r);
    cudaGetSymbolAddress((void**)&rsp,  g_rowsum);
    cudaGetSymbolAddress((void**)&c1p,  g_cs1);
    cudaGetSymbolAddress((void**)&c2p,  g_cs2);
    cudaGetSymbolAddress((void**)&c3p,  g_cs3);
    cudaGetSymbolAddress((void**)&hop,  g_ho);

    const size_t FIN = (size_t)BQ * SEQ * DIMV;
    const size_t ATT = (size_t)NHEADS * SEQ * SEQ;
    float* fin_ptr = 0;
    float* attn_ptr = 0;
    if ((size_t)out_size >= FIN + ATT) { fin_ptr = out; attn_ptr = out + FIN; }
    else if ((size_t)out_size == ATT)  { attn_ptr = out; }
    else                               { fin_ptr = out; }

    const int NV = NHEADS * SEQ;

    init_sums<<<NV / 256, 256>>>(rsp, c1p, c2p, c3p);

    // 1) qkv = x @ W_qkv
    sgemm128<<<dim3(QKVW / 128, (BQ * SEQ) / 128), 256>>>(
        x, Wqkv, qkvp, BQ * SEQ, QKVW, DIMV, (const float*)0);

    // 2) E = exp(-scale*q k^T) fp32 + bf16 shadow, fused rowsum (c0 = 1)
    qk_dots_exp<<<dim3(SEQ / 128, SEQ / 128, NHEADS), 256>>>(qkvp, Ep, Ebp, rsp);

    // 3) Sinkhorn over bf16 E: col1, row2, col2, row3, col3
    colpass_bf<<<dim3(SEQ / 64, NHEADS), 256>>>(Ebp, rsp, c1p, 1);
    rowpass_bf<<<dim3(SEQ / 8, NHEADS), 256>>>(Ebp, c1p, rp);
    colpass_bf<<<dim3(SEQ / 64, NHEADS), 256>>>(Ebp, rp, c2p, 0);
    rowpass_bf<<<dim3(SEQ / 8, NHEADS), 256>>>(Ebp, c2p, rp);
    colpass_bf<<<dim3(SEQ / 64, NHEADS), 256>>>(Ebp, rp, c3p, 0);

    // 4) attn = r*E*c*n (fused write) and ho = attn @ V, per head
    av_gemm<<<dim3(SEQ / 128, NHEADS), 128>>>(
        Ep, rp, c3p, qkvp, attn_ptr ? attn_ptr : Ep, hop, attn_ptr ? 1 : 0);

    // 5) final = ho @ W_out + b_out
    if (fin_ptr)
        sgemm128<<<dim3(DIMV / 128, (BQ * SEQ) / 128), 256>>>(
            hop, Wout, fin_ptr, BQ * SEQ, DIMV, DIMV, bout);
}

// round 8
// speedup vs baseline: 1.7242x; 1.4687x over previous
#include <cuda_runtime.h>
#include <cuda_bf16.h>
#include <math.h>

#define BQ 8
#define SEQ 1024
#define DIMV 512
#define HEADS 8
#define DHEAD 64
#define NHEADS 64        // BQ*HEADS
#define QKVW 1536        // 3*HEADS*DHEAD

#define MU_C (1.0f/1024.0f)
#define NU_C (1.0f/1024.0f)

typedef unsigned int u32;

// tf32 round (RNA) of an fp32 value, kept as fp32 bit pattern
__device__ __forceinline__ float tf32f(float f) {
    u32 r; asm("cvt.rna.tf32.f32 %0, %1;" : "=r"(r) : "f"(f));
    return __uint_as_float(r);
}
__device__ __forceinline__ void mma_tf32(float4& d, const u32* a, u32 b0, u32 b1) {
    asm volatile(
        "mma.sync.aligned.m16n8k8.row.col.f32.tf32.tf32.f32 "
        "{%0,%1,%2,%3}, {%4,%5,%6,%7}, {%8,%9}, {%0,%1,%2,%3};\n"
        : "+f"(d.x), "+f"(d.y), "+f"(d.z), "+f"(d.w)
        : "r"(a[0]), "r"(a[1]), "r"(a[2]), "r"(a[3]), "r"(b0), "r"(b1));
}
__device__ __forceinline__ u32 su(const float* p) { return __float_as_uint(*p); }

// ---------------- scratch (device globals; no allocations allowed) ----------
__device__ float g_qkv[(size_t)BQ * SEQ * QKVW];
__device__ float g_E[(size_t)NHEADS * SEQ * SEQ];            // E = exp(-C) fp32
__device__ __nv_bfloat16 g_Ebf[(size_t)NHEADS * SEQ * SEQ];  // bf16 shadow
__device__ float g_r[NHEADS * SEQ];
__device__ float g_rowsum[NHEADS * SEQ];
__device__ float g_cs1[NHEADS * SEQ];
__device__ float g_cs2[NHEADS * SEQ];
__device__ float g_cs3[NHEADS * SEQ];
__device__ float g_ho[(size_t)BQ * SEQ * DIMV];

// --------- generic tf32 tensor-core GEMM: C[M,N] = A[M,K]@B[K,N] (+bias) ----
// 256 thr, block tile 128x128, BK=16, warps 4(m) x 2(n) -> warp tile 32x64
__global__ __launch_bounds__(256) void gemm_tf32(
    const float* __restrict__ A, const float* __restrict__ Bm,
    float* __restrict__ C, int M, int N, int K, const float* __restrict__ bias)
{
    __shared__ float As[16][132];   // [k][m]
    __shared__ float Bs[16][132];   // [k][n]
    const int t = threadIdx.x;
    const int m0 = blockIdx.y * 128, n0 = blockIdx.x * 128;
    const int lane = t & 31, w = t >> 5;
    const int wm = w & 3, wn = w >> 2;
    const int g = lane >> 2, tc = lane & 3;
    const int m0w = wm * 32, n0w = wn * 64;
    const int arow = t >> 2, acol = (t & 3) * 4;
    const int brow = t >> 5, bcol = (t & 31) * 4;

    float4 acc[2][8];
#pragma unroll
    for (int mf = 0; mf < 2; mf++)
#pragma unroll
        for (int nf = 0; nf < 8; nf++) acc[mf][nf] = make_float4(0.f, 0.f, 0.f, 0.f);

    for (int kt = 0; kt < K; kt += 16) {
#pragma unroll
        for (int half = 0; half < 2; half++) {
            int r_ = arow + half * 64;
            float4 v = *(const float4*)(A + (size_t)(m0 + r_) * K + kt + acol);
            As[acol + 0][r_] = tf32f(v.x); As[acol + 1][r_] = tf32f(v.y);
            As[acol + 2][r_] = tf32f(v.z); As[acol + 3][r_] = tf32f(v.w);
        }
#pragma unroll
        for (int half = 0; half < 2; half++) {
            int kr = brow + half * 8;
            float4 v = *(const float4*)(Bm + (size_t)(kt + kr) * N + n0 + bcol);
            Bs[kr][bcol + 0] = tf32f(v.x); Bs[kr][bcol + 1] = tf32f(v.y);
            Bs[kr][bcol + 2] = tf32f(v.z); Bs[kr][bcol + 3] = tf32f(v.w);
        }
        __syncthreads();
#pragma unroll
        for (int ks = 0; ks < 16; ks += 8) {
            u32 a[2][4];
#pragma unroll
            for (int mf = 0; mf < 2; mf++) {
                a[mf][0] = su(&As[ks + tc][m0w + mf * 16 + g]);
                a[mf][1] = su(&As[ks + tc][m0w + mf * 16 + g + 8]);
                a[mf][2] = su(&As[ks + tc + 4][m0w + mf * 16 + g]);
                a[mf][3] = su(&As[ks + tc + 4][m0w + mf * 16 + g + 8]);
            }
#pragma unroll
            for (int nf = 0; nf < 8; nf++) {
                u32 b0 = su(&Bs[ks + tc][n0w + nf * 8 + g]);
                u32 b1 = su(&Bs[ks + tc + 4][n0w + nf * 8 + g]);
                mma_tf32(acc[0][nf], a[0], b0, b1);
                mma_tf32(acc[1][nf], a[1], b0, b1);
            }
        }
        __syncthreads();
    }
#pragma unroll
    for (int mf = 0; mf < 2; mf++) {
        int gr = m0 + m0w + mf * 16 + g;
#pragma unroll
        for (int nf = 0; nf < 8; nf++) {
            int gc = n0 + n0w + nf * 8 + tc * 2;
            float2 lo = make_float2(acc[mf][nf].x, acc[mf][nf].y);
            float2 hi = make_float2(acc[mf][nf].z, acc[mf][nf].w);
            if (bias) {
                lo.x += bias[gc]; lo.y += bias[gc + 1];
                hi.x += bias[gc]; hi.y += bias[gc + 1];
            }
            *(float2*)(C + (size_t)gr * N + gc) = lo;
            *(float2*)(C + (size_t)(gr + 8) * N + gc) = hi;
        }
    }
}

// ------- dots (tf32 mma) -> E fp32 + bf16 shadow, fused first row-sum -------
__global__ __launch_bounds__(256) void qk_dots_exp(
    const float* __restrict__ qkv, float* __restrict__ E,
    __nv_bfloat16* __restrict__ Ebf, float* __restrict__ rowsum)
{
    __shared__ float As[16][132];   // [d][i]
    __shared__ float Bs[16][132];   // [d][j]
    const int bh = blockIdx.z, b = bh >> 3, h = bh & 7;
    const int i0 = blockIdx.y * 128, j0 = blockIdx.x * 128;
    const float* qbase = qkv + (size_t)b * SEQ * QKVW + h * DHEAD;
    const float* kbase = qkv + (size_t)b * SEQ * QKVW + 512 + h * DHEAD;

    const int t = threadIdx.x;
    const int lane = t & 31, w = t >> 5;
    const int wm = w & 3, wn = w >> 2;
    const int g = lane >> 2, tc = lane & 3;
    const int m0w = wm * 32, n0w = wn * 64;
    const int arow = t >> 2, acol = (t & 3) * 4;

    float4 acc[2][8];
#pragma unroll
    for (int mf = 0; mf < 2; mf++)
#pragma unroll
        for (int nf = 0; nf < 8; nf++) acc[mf][nf] = make_float4(0.f, 0.f, 0.f, 0.f);

    for (int kt = 0; kt < DHEAD; kt += 16) {
#pragma unroll
        for (int half = 0; half < 2; half++) {
            int r_ = arow + half * 64;
            float4 qv = *(const float4*)(qbase + (size_t)(i0 + r_) * QKVW + kt + acol);
            As[acol + 0][r_] = tf32f(qv.x); As[acol + 1][r_] = tf32f(qv.y);
            As[acol + 2][r_] = tf32f(qv.z); As[acol + 3][r_] = tf32f(qv.w);
            float4 kv = *(const float4*)(kbase + (size_t)(j0 + r_) * QKVW + kt + acol);
            Bs[acol + 0][r_] = tf32f(kv.x); Bs[acol + 1][r_] = tf32f(kv.y);
            Bs[acol + 2][r_] = tf32f(kv.z); Bs[acol + 3][r_] = tf32f(kv.w);
        }
        __syncthreads();
#pragma unroll
        for (int ks = 0; ks < 16; ks += 8) {
            u32 a[2][4];
#pragma unroll
            for (int mf = 0; mf < 2; mf++) {
                a[mf][0] = su(&As[ks + tc][m0w + mf * 16 + g]);
                a[mf][1] = su(&As[ks + tc][m0w + mf * 16 + g + 8]);
                a[mf][2] = su(&As[ks + tc + 4][m0w + mf * 16 + g]);
                a[mf][3] = su(&As[ks + tc + 4][m0w + mf * 16 + g + 8]);
            }
#pragma unroll
            for (int nf = 0; nf < 8; nf++) {
                u32 b0 = su(&Bs[ks + tc][n0w + nf * 8 + g]);
                u32 b1 = su(&Bs[ks + tc + 4][n0w + nf * 8 + g]);
                mma_tf32(acc[0][nf], a[0], b0, b1);
                mma_tf32(acc[1][nf], a[1], b0, b1);
            }
        }
        __syncthreads();
    }

    float* Ep = E + (size_t)bh * SEQ * SEQ;
    __nv_bfloat16* Ebp = Ebf + (size_t)bh * SEQ * SEQ;
#pragma unroll
    for (int mf = 0; mf < 2; mf++) {
        int gi = i0 + m0w + mf * 16 + g;
        float rs0 = 0.f, rs1 = 0.f;
#pragma unroll
        for (int nf = 0; nf < 8; nf++) {
            int gj = j0 + n0w + nf * 8 + tc * 2;
            float e0 = __expf(-0.125f * acc[mf][nf].x);
            float e1 = __expf(-0.125f * acc[mf][nf].y);
            float e2 = __expf(-0.125f * acc[mf][nf].z);
            float e3 = __expf(-0.125f * acc[mf][nf].w);
            *(float2*)(Ep + (size_t)gi * SEQ + gj) = make_float2(e0, e1);
            *(float2*)(Ep + (size_t)(gi + 8) * SEQ + gj) = make_float2(e2, e3);
            __nv_bfloat162 p0 = __floats2bfloat162_rn(e0, e1);
            __nv_bfloat162 p1 = __floats2bfloat162_rn(e2, e3);
            *(__nv_bfloat162*)(Ebp + (size_t)gi * SEQ + gj) = p0;
            *(__nv_bfloat162*)(Ebp + (size_t)(gi + 8) * SEQ + gj) = p1;
            rs0 += e0 + e1; rs1 += e2 + e3;
        }
        rs0 += __shfl_xor_sync(0xffffffffu, rs0, 1);
        rs0 += __shfl_xor_sync(0xffffffffu, rs0, 2);
        rs1 += __shfl_xor_sync(0xffffffffu, rs1, 1);
        rs1 += __shfl_xor_sync(0xffffffffu, rs1, 2);
        if (tc == 0) {
            atomicAdd(&rowsum[bh * SEQ + gi], rs0);
            atomicAdd(&rowsum[bh * SEQ + gi + 8], rs1);
        }
    }
}

// ---- col pass over bf16 E: colsum_j += sum_i E_ij * rs_i -------------------
__global__ __launch_bounds__(256) void colpass_bf(
    const __nv_bfloat16* __restrict__ Eb, const float* __restrict__ rvec,
    float* __restrict__ colsum, int recip)
{
    const int bh = blockIdx.y;
    const int i0 = blockIdx.x * 64;
    const int t = threadIdx.x;
    __shared__ float rs[64];
    if (t < 64) {
        float rv = rvec[bh * SEQ + i0 + t];
        rs[t] = recip ? (MU_C / rv) : rv;
    }
    __syncthreads();

    const __nv_bfloat16* Ep = Eb + (size_t)bh * SEQ * SEQ + (size_t)i0 * SEQ;
    const int j = t * 4;
    float ax = 0.f, ay = 0.f, az = 0.f, aw = 0.f;
#pragma unroll 4
    for (int i = 0; i < 64; i++) {
        uint2 raw = *(const uint2*)(Ep + (size_t)i * SEQ + j);
        float2 f0 = __bfloat1622float2(*(__nv_bfloat162*)&raw.x);
        float2 f1 = __bfloat1622float2(*(__nv_bfloat162*)&raw.y);
        float rv = rs[i];
        ax = fmaf(f0.x, rv, ax); ay = fmaf(f0.y, rv, ay);
        az = fmaf(f1.x, rv, az); aw = fmaf(f1.y, rv, aw);
    }
    atomicAdd(&colsum[bh * SEQ + j + 0], ax);
    atomicAdd(&colsum[bh * SEQ + j + 1], ay);
    atomicAdd(&colsum[bh * SEQ + j + 2], az);
    atomicAdd(&colsum[bh * SEQ + j + 3], aw);
}

// ---- row pass over bf16 E: r_i = MU / sum_j E_ij * (NU/colsum_j) -----------
__global__ __launch_bounds__(256) void rowpass_bf(
    const __nv_bfloat16* __restrict__ Eb, const float* __restrict__ colsum,
    float* __restrict__ r)
{
    const int bh = blockIdx.y;
    const int t = threadIdx.x, lane = t & 31, w = t >> 5;
    const int row = blockIdx.x * 8 + w;
    __shared__ float cs[SEQ];
    {
        float4 cv = *(const float4*)(colsum + bh * SEQ + t * 4);
        cs[t * 4 + 0] = NU_C / cv.x;
        cs[t * 4 + 1] = NU_C / cv.y;
        cs[t * 4 + 2] = NU_C / cv.z;
        cs[t * 4 + 3] = NU_C / cv.w;
    }
    __syncthreads();

    const __nv_bfloat16* Er = Eb + (size_t)bh * SEQ * SEQ + (size_t)row * SEQ;
    float acc = 0.f;
#pragma unroll
    for (int it = 0; it < 8; it++) {
        int j = it * 128 + lane * 4;
        uint2 raw = *(const uint2*)(Er + j);
        float2 f0 = __bfloat1622float2(*(__nv_bfloat162*)&raw.x);
        float2 f1 = __bfloat1622float2(*(__nv_bfloat162*)&raw.y);
        acc += f0.x * cs[j] + f0.y * cs[j + 1] + f1.x * cs[j + 2] + f1.y * cs[j + 3];
    }
#pragma unroll
    for (int o = 16; o > 0; o >>= 1)
        acc += __shfl_xor_sync(0xffffffffu, acc, o);
    if (lane == 0) r[bh * SEQ + row] = MU_C / acc;
}

__global__ void init_sums(float* __restrict__ rowsum, float* __restrict__ c1,
                          float* __restrict__ c2, float* __restrict__ c3)
{
    int i = blockIdx.x * 256 + threadIdx.x;
    rowsum[i] = 0.f; c1[i] = 0.f; c2[i] = 0.f; c3[i] = 0.f;
}

// --- per-head AV (tf32 mma): ho = rn_i*(E@(c_j V)), fused attn write --------
// 256 thr, tile 128(i) x 64(d), BK=32, warps 4(m) x 2(n) -> warp 32x32
__global__ __launch_bounds__(256) void av_gemm(
    const float* __restrict__ E, const float* __restrict__ r,
    const float* __restrict__ colsum3, const float* __restrict__ qkv,
    float* __restrict__ attn, float* __restrict__ ho, int write_attn)
{
    __shared__ float Es[32][132];   // [j][i]
    __shared__ float Ws[32][68];    // [j][d]
    __shared__ float cr[SEQ];
    __shared__ float rn[128];

    const int bh = blockIdx.y, b = bh >> 3, h = bh & 7;
    const int i0 = blockIdx.x * 128;
    const int t = threadIdx.x;
    const int lane = t & 31, w = t >> 5;
    const int wm = w & 3, wn = w >> 2;
    const int g = lane >> 2, tc = lane & 3;
    const int m0w = wm * 32, n0w = wn * 32;

    if (t < 128) rn[t] = r[bh * SEQ + i0 + t] * 1024.0f;
#pragma unroll
    for (int q = 0; q < 4; q++) {
        int j = t + 256 * q;
        cr[j] = NU_C / colsum3[bh * SEQ + j];
    }
    __syncthreads();

    const float* Ep = E + (size_t)bh * SEQ * SEQ;
    const float* vb = qkv + (size_t)b * SEQ * QKVW + 1024 + h * DHEAD;
    float* ap = attn + (size_t)bh * SEQ * SEQ;

    float4 acc[2][4];
#pragma unroll
    for (int mf = 0; mf < 2; mf++)
#pragma unroll
        for (int nf = 0; nf < 4; nf++) acc[mf][nf] = make_float4(0.f, 0.f, 0.f, 0.f);

    for (int jt = 0; jt < 32; jt++) {
        const int j0 = jt * 32;
        // E tile 128x32 (+ fused attn write), store [j][i] tf32
#pragma unroll
        for (int q = 0; q < 4; q++) {
            int f = t + 256 * q;
            int i = f >> 3, jq = (f & 7) * 4;
            float4 e = *(const float4*)(Ep + (size_t)(i0 + i) * SEQ + j0 + jq);
            if (write_attn) {
                float rv = rn[i];
                float4 o;
                o.x = rv * e.x * cr[j0 + jq + 0];
                o.y = rv * e.y * cr[j0 + jq + 1];
                o.z = rv * e.z * cr[j0 + jq + 2];
                o.w = rv * e.w * cr[j0 + jq + 3];
                *(float4*)(ap + (size_t)(i0 + i) * SEQ + j0 + jq) = o;
            }
            Es[jq + 0][i] = tf32f(e.x); Es[jq + 1][i] = tf32f(e.y);
            Es[jq + 2][i] = tf32f(e.z); Es[jq + 3][i] = tf32f(e.w);
        }
        // V tile 32x64, scale by c_j, store [j][d] tf32
#pragma unroll
        for (int q = 0; q < 2; q++) {
            int f = t + 256 * q;
            int k = f >> 4, dq = (f & 15) * 4;
            float4 v = *(const float4*)(vb + (size_t)(j0 + k) * QKVW + dq);
            float cw = cr[j0 + k];
            Ws[k][dq + 0] = tf32f(v.x * cw); Ws[k][dq + 1] = tf32f(v.y * cw);
            Ws[k][dq + 2] = tf32f(v.z * cw); Ws[k][dq + 3] = tf32f(v.w * cw);
        }
        __syncthreads();
#pragma unroll
        for (int ks = 0; ks < 32; ks += 8) {
            u32 a[2][4];
#pragma unroll
            for (int mf = 0; mf < 2; mf++) {
                a[mf][0] = su(&Es[ks + tc][m0w + mf * 16 + g]);
                a[mf][1] = su(&Es[ks + tc][m0w + mf * 16 + g + 8]);
                a[mf][2] = su(&Es[ks + tc + 4][m0w + mf * 16 + g]);
                a[mf][3] = su(&Es[ks + tc + 4][m0w + mf * 16 + g + 8]);
            }
#pragma unroll
            for (int nf = 0; nf < 4; nf++) {
                u32 b0 = su(&Ws[ks + tc][n0w + nf * 8 + g]);
                u32 b1 = su(&Ws[ks + tc + 4][n0w + nf * 8 + g]);
                mma_tf32(acc[0][nf], a[0], b0, b1);
                mma_tf32(acc[1][nf], a[1], b0, b1);
            }
        }
        __syncthreads();
    }
#pragma unroll
    for (int mf = 0; mf < 2; mf++) {
        int il = m0w + mf * 16 + g;
        float rv0 = rn[il], rv1 = rn[il + 8];
        float* hp0 = ho + (size_t)(b * SEQ + i0 + il) * DIMV + h * DHEAD;
        float* hp1 = ho + (size_t)(b * SEQ + i0 + il + 8) * DIMV + h * DHEAD;
#pragma unroll
        for (int nf = 0; nf < 4; nf++) {
            int gc = n0w + nf * 8 + tc * 2;
            *(float2*)(hp0 + gc) = make_float2(acc[mf][nf].x * rv0, acc[mf][nf].y * rv0);
            *(float2*)(hp1 + gc) = make_float2(acc[mf][nf].z * rv1, acc[mf][nf].w * rv1);
        }
    }
}

// ---------------- launcher ---------------------------------------------------
extern "C" void kernel_launch(void* const* d_in, const int* in_sizes, int n_in,
                              void* d_out, int out_size)
{
    const float* x    = (const float*)d_in[0];
    const float* Wqkv = (const float*)d_in[1];
    const float* Wout = (const float*)d_in[2];
    const float* bout = (const float*)d_in[3];
    float* out = (float*)d_out;

    float *qkvp, *Ep, *rp, *rsp, *c1p, *c2p, *c3p, *hop;
    __nv_bfloat16* Ebp;
    cudaGetSymbolAddress((void**)&qkvp, g_qkv);
    cudaGetSymbolAddress((void**)&Ep,   g_E);
    cudaGetSymbolAddress((void**)&Ebp,  g_Ebf);
    cudaGetSymbolAddress((void**)&rp,   g_r);
    cudaGetSymbolAddress((void**)&rsp,  g_rowsum);
    cudaGetSymbolAddress((void**)&c1p,  g_cs1);
    cudaGetSymbolAddress((void**)&c2p,  g_cs2);
    cudaGetSymbolAddress((void**)&c3p,  g_cs3);
    cudaGetSymbolAddress((void**)&hop,  g_ho);

    const size_t FIN = (size_t)BQ * SEQ * DIMV;
    const size_t ATT = (size_t)NHEADS * SEQ * SEQ;
    float* fin_ptr = 0;
    float* attn_ptr = 0;
    if ((size_t)out_size >= FIN + ATT) { fin_ptr = out; attn_ptr = out + FIN; }
    else if ((size_t)out_size == ATT)  { attn_ptr = out; }
    else                               { fin_ptr = out; }

    const int NV = NHEADS * SEQ;

    init_sums<<<NV / 256, 256>>>(rsp, c1p, c2p, c3p);

    // 1) qkv = x @ W_qkv  (tf32 tensor cores)
    gemm_tf32<<<dim3(QKVW / 128, (BQ * SEQ) / 128), 256>>>(
        x, Wqkv, qkvp, BQ * SEQ, QKVW, DIMV, (const float*)0);

    // 2) E = exp(-scale*q k^T) fp32 + bf16 shadow, fused rowsum (c0 = 1)
    qk_dots_exp<<<dim3(SEQ / 128, SEQ / 128, NHEADS), 256>>>(qkvp, Ep, Ebp, rsp);

    // 3) Sinkhorn over bf16 E: col1, row2, col2, row3, col3
    colpass_bf<<<dim3(SEQ / 64, NHEADS), 256>>>(Ebp, rsp, c1p, 1);
    rowpass_bf<<<dim3(SEQ / 8, NHEADS), 256>>>(Ebp, c1p, rp);
    colpass_bf<<<dim3(SEQ / 64, NHEADS), 256>>>(Ebp, rp, c2p, 0);
    rowpass_bf<<<dim3(SEQ / 8, NHEADS), 256>>>(Ebp, c2p, rp);
    colpass_bf<<<dim3(SEQ / 64, NHEADS), 256>>>(Ebp, rp, c3p, 0);

    // 4) attn = r*E*c*n (fused write) and ho = attn @ V (tf32 tensor cores)
    av_gemm<<<dim3(SEQ / 128, NHEADS), 256>>>(
        Ep, rp, c3p, qkvp, attn_ptr ? attn_ptr : Ep, hop, attn_ptr ? 1 : 0);

    // 5) final = ho @ W_out + b_out  (tf32 tensor cores)
    if (fin_ptr)
        gemm_tf32<<<dim3(DIMV / 128, (BQ * SEQ) / 128), 256>>>(
            hop, Wout, fin_ptr, BQ * SEQ, DIMV, DIMV, bout);
}

// round 9
// speedup vs baseline: 1.7462x; 1.0128x over previous
#include <cuda_runtime.h>
#include <cuda_bf16.h>
#include <math.h>

#define BQ 8
#define SEQ 1024
#define DIMV 512
#define HEADS 8
#define DHEAD 64
#define NHEADS 64        // BQ*HEADS
#define QKVW 1536        // 3*HEADS*DHEAD

#define MU_C (1.0f/1024.0f)
#define NU_C (1.0f/1024.0f)

typedef unsigned int u32;

__device__ __forceinline__ float tf32f(float f) {
    u32 r; asm("cvt.rna.tf32.f32 %0, %1;" : "=r"(r) : "f"(f));
    return __uint_as_float(r);
}
__device__ __forceinline__ void mma_tf32(float4& d, const u32* a, u32 b0, u32 b1) {
    asm volatile(
        "mma.sync.aligned.m16n8k8.row.col.f32.tf32.tf32.f32 "
        "{%0,%1,%2,%3}, {%4,%5,%6,%7}, {%8,%9}, {%0,%1,%2,%3};\n"
        : "+f"(d.x), "+f"(d.y), "+f"(d.z), "+f"(d.w)
        : "r"(a[0]), "r"(a[1]), "r"(a[2]), "r"(a[3]), "r"(b0), "r"(b1));
}
__device__ __forceinline__ u32 su(const float* p) { return __float_as_uint(*p); }

// ---------------- scratch (device globals; no allocations allowed) ----------
__device__ float g_qkv[(size_t)BQ * SEQ * QKVW];
__device__ float g_E[(size_t)NHEADS * SEQ * SEQ];            // E = exp(-C) fp32
__device__ __nv_bfloat16 g_Ebf[(size_t)NHEADS * SEQ * SEQ];  // bf16 shadow
__device__ float g_r[NHEADS * SEQ];
__device__ float g_rowsum[NHEADS * SEQ];
__device__ float g_cs1[NHEADS * SEQ];
__device__ float g_cs2[NHEADS * SEQ];
__device__ float g_cs3[NHEADS * SEQ];
__device__ float g_ho[(size_t)BQ * SEQ * DIMV];

// ---- tf32 GEMM: block 128x256, 8 warps @ 64x64, BK=16 ----------------------
// C[M,N] = A[M,K]@B[K,N] (+bias). M%128==0, N%256==0, K%16==0.
__global__ __launch_bounds__(256) void gemm_tf32(
    const float* __restrict__ A, const float* __restrict__ Bm,
    float* __restrict__ C, int M, int N, int K, const float* __restrict__ bias)
{
    __shared__ float As[16 * 132];   // [k][m], pad 4
    __shared__ float Bs[16 * 260];   // [k][n], pad 4
    const int t = threadIdx.x;
    const int m0 = blockIdx.y * 128, n0 = blockIdx.x * 256;
    const int lane = t & 31, w = t >> 5;
    const int wm = w & 1, wn = w >> 1;           // 2 x 4 warps
    const int g = lane >> 2, tc = lane & 3;
    const int m0w = wm * 64, n0w = wn * 64;
    const int arow = t >> 2, acol = (t & 3) * 4; // A loader: 512 f4, 2/thr
    const int bkr = t >> 6, bnc = (t & 63) * 4;  // B loader: 1024 f4, 4/thr

    float4 acc[4][8];
#pragma unroll
    for (int mf = 0; mf < 4; mf++)
#pragma unroll
        for (int nf = 0; nf < 8; nf++) acc[mf][nf] = make_float4(0.f, 0.f, 0.f, 0.f);

    for (int kt = 0; kt < K; kt += 16) {
#pragma unroll
        for (int q = 0; q < 2; q++) {
            int r_ = arow, c_ = acol + q * 0;    // 2 halves by row offset
            r_ = arow + q * 64;
            float4 v = *(const float4*)(A + (size_t)(m0 + r_) * K + kt + acol);
            As[(acol + 0) * 132 + r_] = tf32f(v.x);
            As[(acol + 1) * 132 + r_] = tf32f(v.y);
            As[(acol + 2) * 132 + r_] = tf32f(v.z);
            As[(acol + 3) * 132 + r_] = tf32f(v.w);
            (void)c_;
        }
#pragma unroll
        for (int q = 0; q < 4; q++) {
            int kr = bkr + q * 4;
            float4 v = *(const float4*)(Bm + (size_t)(kt + kr) * N + n0 + bnc);
            float4 o = make_float4(tf32f(v.x), tf32f(v.y), tf32f(v.z), tf32f(v.w));
            *(float4*)&Bs[kr * 260 + bnc] = o;
        }
        __syncthreads();
#pragma unroll
        for (int ks = 0; ks < 16; ks += 8) {
            u32 a[4][4];
#pragma unroll
            for (int mf = 0; mf < 4; mf++) {
                a[mf][0] = su(&As[(ks + tc) * 132 + m0w + mf * 16 + g]);
                a[mf][1] = su(&As[(ks + tc) * 132 + m0w + mf * 16 + g + 8]);
                a[mf][2] = su(&As[(ks + tc + 4) * 132 + m0w + mf * 16 + g]);
                a[mf][3] = su(&As[(ks + tc + 4) * 132 + m0w + mf * 16 + g + 8]);
            }
#pragma unroll
            for (int nf = 0; nf < 8; nf++) {
                u32 b0 = su(&Bs[(ks + tc) * 260 + n0w + nf * 8 + g]);
                u32 b1 = su(&Bs[(ks + tc + 4) * 260 + n0w + nf * 8 + g]);
#pragma unroll
                for (int mf = 0; mf < 4; mf++)
                    mma_tf32(acc[mf][nf], a[mf], b0, b1);
            }
        }
        __syncthreads();
    }
#pragma unroll
    for (int mf = 0; mf < 4; mf++) {
        int gr = m0 + m0w + mf * 16 + g;
#pragma unroll
        for (int nf = 0; nf < 8; nf++) {
            int gc = n0 + n0w + nf * 8 + tc * 2;
            float2 lo = make_float2(acc[mf][nf].x, acc[mf][nf].y);
            float2 hi = make_float2(acc[mf][nf].z, acc[mf][nf].w);
            if (bias) {
                lo.x += bias[gc]; lo.y += bias[gc + 1];
                hi.x += bias[gc]; hi.y += bias[gc + 1];
            }
            *(float2*)(C + (size_t)gr * N + gc) = lo;
            *(float2*)(C + (size_t)(gr + 8) * N + gc) = hi;
        }
    }
}

// ------- dots (tf32 mma, 128x256 tile) -> E fp32 + bf16, fused row-sum ------
__global__ __launch_bounds__(256) void qk_dots_exp(
    const float* __restrict__ qkv, float* __restrict__ E,
    __nv_bfloat16* __restrict__ Ebf, float* __restrict__ rowsum)
{
    __shared__ float As[16 * 132];   // [d][i]
    __shared__ float Bs[16 * 260];   // [d][j]
    const int bh = blockIdx.z, b = bh >> 3, h = bh & 7;
    const int i0 = blockIdx.y * 128, j0 = blockIdx.x * 256;
    const float* qbase = qkv + (size_t)b * SEQ * QKVW + h * DHEAD;
    const float* kbase = qkv + (size_t)b * SEQ * QKVW + 512 + h * DHEAD;

    const int t = threadIdx.x;
    const int lane = t & 31, w = t >> 5;
    const int wm = w & 1, wn = w >> 1;
    const int g = lane >> 2, tc = lane & 3;
    const int m0w = wm * 64, n0w = wn * 64;
    const int arow = t >> 2, acol = (t & 3) * 4;

    float4 acc[4][8];
#pragma unroll
    for (int mf = 0; mf < 4; mf++)
#pragma unroll
        for (int nf = 0; nf < 8; nf++) acc[mf][nf] = make_float4(0.f, 0.f, 0.f, 0.f);

#pragma unroll
    for (int kt = 0; kt < DHEAD; kt += 16) {
        // q tile 128x16 -> As[d][i]
        float4 qv = *(const float4*)(qbase + (size_t)(i0 + arow) * QKVW + kt + acol);
        As[(acol + 0) * 132 + arow] = tf32f(qv.x);
        As[(acol + 1) * 132 + arow] = tf32f(qv.y);
        As[(acol + 2) * 132 + arow] = tf32f(qv.z);
        As[(acol + 3) * 132 + arow] = tf32f(qv.w);
        // only 128 rows; arow covers them with 1 f4 each (128*4 f = 512 f4 / 256 thr = 2)
        {
            int r2 = arow + 0;  // second half below
            (void)r2;
        }
        // second A half: rows 0..127 need 512 f4; arow gives 256 -> do two cols
        {
            float4 q2 = *(const float4*)(qbase + (size_t)(i0 + arow) * QKVW + kt + acol);
            (void)q2; // (already covered: 128 rows x 16 cols = 512 f4; arow in 0..63?)
        }
        // k tile 256x16 -> Bs[d][j]
#pragma unroll
        for (int q = 0; q < 4; q++) {
            int r_ = (t + 256 * q) >> 2;
            int c_ = ((t + 256 * q) & 3) * 4;
            float4 kv = *(const float4*)(kbase + (size_t)(j0 + r_) * QKVW + kt + c_);
            Bs[(c_ + 0) * 260 + r_] = tf32f(kv.x);
            Bs[(c_ + 1) * 260 + r_] = tf32f(kv.y);
            Bs[(c_ + 2) * 260 + r_] = tf32f(kv.z);
            Bs[(c_ + 3) * 260 + r_] = tf32f(kv.w);
        }
        // A actually needs 2 f4 per thread: rows arow and arow+64
        {
            int r_ = arow + 64;
            float4 qv2 = *(const float4*)(qbase + (size_t)(i0 + r_) * QKVW + kt + acol);
            As[(acol + 0) * 132 + r_] = tf32f(qv2.x);
            As[(acol + 1) * 132 + r_] = tf32f(qv2.y);
            As[(acol + 2) * 132 + r_] = tf32f(qv2.z);
            As[(acol + 3) * 132 + r_] = tf32f(qv2.w);
        }
        __syncthreads();
#pragma unroll
        for (int ks = 0; ks < 16; ks += 8) {
            u32 a[4][4];
#pragma unroll
            for (int mf = 0; mf < 4; mf++) {
                a[mf][0] = su(&As[(ks + tc) * 132 + m0w + mf * 16 + g]);
                a[mf][1] = su(&As[(ks + tc) * 132 + m0w + mf * 16 + g + 8]);
                a[mf][2] = su(&As[(ks + tc + 4) * 132 + m0w + mf * 16 + g]);
                a[mf][3] = su(&As[(ks + tc + 4) * 132 + m0w + mf * 16 + g + 8]);
            }
#pragma unroll
            for (int nf = 0; nf < 8; nf++) {
                u32 b0 = su(&Bs[(ks + tc) * 260 + n0w + nf * 8 + g]);
                u32 b1 = su(&Bs[(ks + tc + 4) * 260 + n0w + nf * 8 + g]);
#pragma unroll
                for (int mf = 0; mf < 4; mf++)
                    mma_tf32(acc[mf][nf], a[mf], b0, b1);
            }
        }
        __syncthreads();
    }

    float* Ep = E + (size_t)bh * SEQ * SEQ;
    __nv_bfloat16* Ebp = Ebf + (size_t)bh * SEQ * SEQ;
#pragma unroll
    for (int mf = 0; mf < 4; mf++) {
        int gi = i0 + m0w + mf * 16 + g;
        float rs0 = 0.f, rs1 = 0.f;
#pragma unroll
        for (int nf = 0; nf < 8; nf++) {
            int gj = j0 + n0w + nf * 8 + tc * 2;
            float e0 = __expf(-0.125f * acc[mf][nf].x);
            float e1 = __expf(-0.125f * acc[mf][nf].y);
            float e2 = __expf(-0.125f * acc[mf][nf].z);
            float e3 = __expf(-0.125f * acc[mf][nf].w);
            *(float2*)(Ep + (size_t)gi * SEQ + gj) = make_float2(e0, e1);
            *(float2*)(Ep + (size_t)(gi + 8) * SEQ + gj) = make_float2(e2, e3);
            *(__nv_bfloat162*)(Ebp + (size_t)gi * SEQ + gj) =
                __floats2bfloat162_rn(e0, e1);
            *(__nv_bfloat162*)(Ebp + (size_t)(gi + 8) * SEQ + gj) =
                __floats2bfloat162_rn(e2, e3);
            rs0 += e0 + e1; rs1 += e2 + e3;
        }
        rs0 += __shfl_xor_sync(0xffffffffu, rs0, 1);
        rs0 += __shfl_xor_sync(0xffffffffu, rs0, 2);
        rs1 += __shfl_xor_sync(0xffffffffu, rs1, 1);
        rs1 += __shfl_xor_sync(0xffffffffu, rs1, 2);
        if (tc == 0) {
            atomicAdd(&rowsum[bh * SEQ + gi], rs0);
            atomicAdd(&rowsum[bh * SEQ + gi + 8], rs1);
        }
    }
}

// ---- col pass over bf16 E: colsum_j += sum_i E_ij * rs_i -------------------
__global__ __launch_bounds__(256) void colpass_bf(
    const __nv_bfloat16* __restrict__ Eb, const float* __restrict__ rvec,
    float* __restrict__ colsum, int recip)
{
    const int bh = blockIdx.y;
    const int i0 = blockIdx.x * 64;
    const int t = threadIdx.x;
    __shared__ float rs[64];
    if (t < 64) {
        float rv = rvec[bh * SEQ + i0 + t];
        rs[t] = recip ? (MU_C / rv) : rv;
    }
    __syncthreads();

    const __nv_bfloat16* Ep = Eb + (size_t)bh * SEQ * SEQ + (size_t)i0 * SEQ;
    const int j = t * 4;
    float ax = 0.f, ay = 0.f, az = 0.f, aw = 0.f;
#pragma unroll 4
    for (int i = 0; i < 64; i++) {
        uint2 raw = *(const uint2*)(Ep + (size_t)i * SEQ + j);
        float2 f0 = __bfloat1622float2(*(__nv_bfloat162*)&raw.x);
        float2 f1 = __bfloat1622float2(*(__nv_bfloat162*)&raw.y);
        float rv = rs[i];
        ax = fmaf(f0.x, rv, ax); ay = fmaf(f0.y, rv, ay);
        az = fmaf(f1.x, rv, az); aw = fmaf(f1.y, rv, aw);
    }
    atomicAdd(&colsum[bh * SEQ + j + 0], ax);
    atomicAdd(&colsum[bh * SEQ + j + 1], ay);
    atomicAdd(&colsum[bh * SEQ + j + 2], az);
    atomicAdd(&colsum[bh * SEQ + j + 3], aw);
}

// ---- row pass over bf16 E: r_i = MU / sum_j E_ij * (NU/colsum_j) -----------
__global__ __launch_bounds__(256) void rowpass_bf(
    const __nv_bfloat16* __restrict__ Eb, const float* __restrict__ colsum,
    float* __restrict__ r)
{
    const int bh = blockIdx.y;
    const int t = threadIdx.x, lane = t & 31, w = t >> 5;
    const int row = blockIdx.x * 8 + w;
    __shared__ float cs[SEQ];
    {
        float4 cv = *(const float4*)(colsum + bh * SEQ + t * 4);
        cs[t * 4 + 0] = NU_C / cv.x;
        cs[t * 4 + 1] = NU_C / cv.y;
        cs[t * 4 + 2] = NU_C / cv.z;
        cs[t * 4 + 3] = NU_C / cv.w;
    }
    __syncthreads();

    const __nv_bfloat16* Er = Eb + (size_t)bh * SEQ * SEQ + (size_t)row * SEQ;
    float acc = 0.f;
#pragma unroll
    for (int it = 0; it < 8; it++) {
        int j = it * 128 + lane * 4;
        uint2 raw = *(const uint2*)(Er + j);
        float2 f0 = __bfloat1622float2(*(__nv_bfloat162*)&raw.x);
        float2 f1 = __bfloat1622float2(*(__nv_bfloat162*)&raw.y);
        acc += f0.x * cs[j] + f0.y * cs[j + 1] + f1.x * cs[j + 2] + f1.y * cs[j + 3];
    }
#pragma unroll
    for (int o = 16; o > 0; o >>= 1)
        acc += __shfl_xor_sync(0xffffffffu, acc, o);
    if (lane == 0) r[bh * SEQ + row] = MU_C / acc;
}

__global__ void init_sums(float* __restrict__ rowsum, float* __restrict__ c1,
                          float* __restrict__ c2, float* __restrict__ c3)
{
    int i = blockIdx.x * 256 + threadIdx.x;
    rowsum[i] = 0.f; c1[i] = 0.f; c2[i] = 0.f; c3[i] = 0.f;
}

// --- per-head AV (tf32 mma): ho = rn_i*(E@(c_j V)), fused attn write --------
__global__ __launch_bounds__(256) void av_gemm(
    const float* __restrict__ E, const float* __restrict__ r,
    const float* __restrict__ colsum3, const float* __restrict__ qkv,
    float* __restrict__ attn, float* __restrict__ ho, int write_attn)
{
    __shared__ float Es[32][132];   // [j][i]
    __shared__ float Ws[32][68];    // [j][d]
    __shared__ float cr[SEQ];
    __shared__ float rn[128];

    const int bh = blockIdx.y, b = bh >> 3, h = bh & 7;
    const int i0 = blockIdx.x * 128;
    const int t = threadIdx.x;
    const int lane = t & 31, w = t >> 5;
    const int wm = w & 3, wn = w >> 2;
    const int g = lane >> 2, tc = lane & 3;
    const int m0w = wm * 32, n0w = wn * 32;

    if (t < 128) rn[t] = r[bh * SEQ + i0 + t] * 1024.0f;
#pragma unroll
    for (int q = 0; q < 4; q++) {
        int j = t + 256 * q;
        cr[j] = NU_C / colsum3[bh * SEQ + j];
    }
    __syncthreads();

    const float* Ep = E + (size_t)bh * SEQ * SEQ;
    const float* vb = qkv + (size_t)b * SEQ * QKVW + 1024 + h * DHEAD;
    float* ap = attn + (size_t)bh * SEQ * SEQ;

    float4 acc[2][4];
#pragma unroll
    for (int mf = 0; mf < 2; mf++)
#pragma unroll
        for (int nf = 0; nf < 4; nf++) acc[mf][nf] = make_float4(0.f, 0.f, 0.f, 0.f);

    for (int jt = 0; jt < 32; jt++) {
        const int j0 = jt * 32;
#pragma unroll
        for (int q = 0; q < 4; q++) {
            int f = t + 256 * q;
            int i = f >> 3, jq = (f & 7) * 4;
            float4 e = *(const float4*)(Ep + (size_t)(i0 + i) * SEQ + j0 + jq);
            if (write_attn) {
                float rv = rn[i];
                float4 o;
                o.x = rv * e.x * cr[j0 + jq + 0];
                o.y = rv * e.y * cr[j0 + jq + 1];
                o.z = rv * e.z * cr[j0 + jq + 2];
                o.w = rv * e.w * cr[j0 + jq + 3];
                *(float4*)(ap + (size_t)(i0 + i) * SEQ + j0 + jq) = o;
            }
            Es[jq + 0][i] = tf32f(e.x); Es[jq + 1][i] = tf32f(e.y);
            Es[jq + 2][i] = tf32f(e.z); Es[jq + 3][i] = tf32f(e.w);
        }
#pragma unroll
        for (int q = 0; q < 2; q++) {
            int f = t + 256 * q;
            int k = f >> 4, dq = (f & 15) * 4;
            float4 v = *(const float4*)(vb + (size_t)(j0 + k) * QKVW + dq);
            float cw = cr[j0 + k];
            Ws[k][dq + 0] = tf32f(v.x * cw); Ws[k][dq + 1] = tf32f(v.y * cw);
            Ws[k][dq + 2] = tf32f(v.z * cw); Ws[k][dq + 3] = tf32f(v.w * cw);
        }
        __syncthreads();
#pragma unroll
        for (int ks = 0; ks < 32; ks += 8) {
            u32 a[2][4];
#pragma unroll
            for (int mf = 0; mf < 2; mf++) {
                a[mf][0] = su(&Es[ks + tc][m0w + mf * 16 + g]);
                a[mf][1] = su(&Es[ks + tc][m0w + mf * 16 + g + 8]);
                a[mf][2] = su(&Es[ks + tc + 4][m0w + mf * 16 + g]);
                a[mf][3] = su(&Es[ks + tc + 4][m0w + mf * 16 + g + 8]);
            }
#pragma unroll
            for (int nf = 0; nf < 4; nf++) {
                u32 b0 = su(&Ws[ks + tc][n0w + nf * 8 + g]);
                u32 b1 = su(&Ws[ks + tc + 4][n0w + nf * 8 + g]);
                mma_tf32(acc[0][nf], a[0], b0, b1);
                mma_tf32(acc[1][nf], a[1], b0, b1);
            }
        }
        __syncthreads();
    }
#pragma unroll
    for (int mf = 0; mf < 2; mf++) {
        int il = m0w + mf * 16 + g;
        float rv0 = rn[il], rv1 = rn[il + 8];
        float* hp0 = ho + (size_t)(b * SEQ + i0 + il) * DIMV + h * DHEAD;
        float* hp1 = ho + (size_t)(b * SEQ + i0 + il + 8) * DIMV + h * DHEAD;
#pragma unroll
        for (int nf = 0; nf < 4; nf++) {
            int gc = n0w + nf * 8 + tc * 2;
            *(float2*)(hp0 + gc) = make_float2(acc[mf][nf].x * rv0, acc[mf][nf].y * rv0);
            *(float2*)(hp1 + gc) = make_float2(acc[mf][nf].z * rv1, acc[mf][nf].w * rv1);
        }
    }
}

// ---------------- launcher ---------------------------------------------------
extern "C" void kernel_launch(void* const* d_in, const int* in_sizes, int n_in,
                              void* d_out, int out_size)
{
    const float* x    = (const float*)d_in[0];
    const float* Wqkv = (const float*)d_in[1];
    const float* Wout = (const float*)d_in[2];
    const float* bout = (const float*)d_in[3];
    float* out = (float*)d_out;

    float *qkvp, *Ep, *rp, *rsp, *c1p, *c2p, *c3p, *hop;
    __nv_bfloat16* Ebp;
    cudaGetSymbolAddress((void**)&qkvp, g_qkv);
    cudaGetSymbolAddress((void**)&Ep,   g_E);
    cudaGetSymbolAddress((void**)&Ebp,  g_Ebf);
    cudaGetSymbolAddress((void**)&rp,   g_r);
    cudaGetSymbolAddress((void**)&rsp,  g_rowsum);
    cudaGetSymbolAddress((void**)&c1p,  g_cs1);
    cudaGetSymbolAddress((void**)&c2p,  g_cs2);
    cudaGetSymbolAddress((void**)&c3p,  g_cs3);
    cudaGetSymbolAddress((void**)&hop,  g_ho);

    const size_t FIN = (size_t)BQ * SEQ * DIMV;
    const size_t ATT = (size_t)NHEADS * SEQ * SEQ;
    float* fin_ptr = 0;
    float* attn_ptr = 0;
    if ((size_t)out_size >= FIN + ATT) { fin_ptr = out; attn_ptr = out + FIN; }
    else if ((size_t)out_size == ATT)  { attn_ptr = out; }
    else                               { fin_ptr = out; }

    const int NV = NHEADS * SEQ;

    init_sums<<<NV / 256, 256>>>(rsp, c1p, c2p, c3p);

    // 1) qkv = x @ W_qkv  (tf32, 128x256 tiles)
    gemm_tf32<<<dim3(QKVW / 256, (BQ * SEQ) / 128), 256>>>(
        x, Wqkv, qkvp, BQ * SEQ, QKVW, DIMV, (const float*)0);

    // 2) E = exp(-scale*q k^T) fp32 + bf16 shadow, fused rowsum (c0 = 1)
    qk_dots_exp<<<dim3(SEQ / 256, SEQ / 128, NHEADS), 256>>>(qkvp, Ep, Ebp, rsp);

    // 3) Sinkhorn over bf16 E: col1, row2, col2, row3, col3
    colpass_bf<<<dim3(SEQ / 64, NHEADS), 256>>>(Ebp, rsp, c1p, 1);
    rowpass_bf<<<dim3(SEQ / 8, NHEADS), 256>>>(Ebp, c1p, rp);
    colpass_bf<<<dim3(SEQ / 64, NHEADS), 256>>>(Ebp, rp, c2p, 0);
    rowpass_bf<<<dim3(SEQ / 8, NHEADS), 256>>>(Ebp, c2p, rp);
    colpass_bf<<<dim3(SEQ / 64, NHEADS), 256>>>(Ebp, rp, c3p, 0);

    // 4) attn = r*E*c*n (fused write) and ho = attn @ V (tf32 mma)
    av_gemm<<<dim3(SEQ / 128, NHEADS), 256>>>(
        Ep, rp, c3p, qkvp, attn_ptr ? attn_ptr : Ep, hop, attn_ptr ? 1 : 0);

    // 5) final = ho @ W_out + b_out  (tf32, 128x256 tiles)
    if (fin_ptr)
        gemm_tf32<<<dim3(DIMV / 256, (BQ * SEQ) / 128), 256>>>(
            hop, Wout, fin_ptr, BQ * SEQ, DIMV, DIMV, bout);
}

// round 10
// speedup vs baseline: 1.8752x; 1.0739x over previous
#include <cuda_runtime.h>
#include <cuda_fp16.h>
#include <math.h>

#define BQ 8
#define SEQ 1024
#define DIMV 512
#define HEADS 8
#define DHEAD 64
#define NHEADS 64        // BQ*HEADS
#define QKVW 1536        // 3*HEADS*DHEAD

#define MU_C (1.0f/1024.0f)
#define NU_C (1.0f/1024.0f)

typedef unsigned int u32;

__device__ __forceinline__ float tf32f(float f) {
    u32 r; asm("cvt.rna.tf32.f32 %0, %1;" : "=r"(r) : "f"(f));
    return __uint_as_float(r);
}
__device__ __forceinline__ void mma_tf32(float4& d, const u32* a, u32 b0, u32 b1) {
    asm volatile(
        "mma.sync.aligned.m16n8k8.row.col.f32.tf32.tf32.f32 "
        "{%0,%1,%2,%3}, {%4,%5,%6,%7}, {%8,%9}, {%0,%1,%2,%3};\n"
        : "+f"(d.x), "+f"(d.y), "+f"(d.z), "+f"(d.w)
        : "r"(a[0]), "r"(a[1]), "r"(a[2]), "r"(a[3]), "r"(b0), "r"(b1));
}
__device__ __forceinline__ u32 su(const float* p) { return __float_as_uint(*p); }

// ---------------- scratch (device globals; no allocations allowed) ----------
__device__ float g_qkv[(size_t)BQ * SEQ * QKVW];
__device__ __half g_Eh[(size_t)NHEADS * SEQ * SEQ];   // E = exp(-C), fp16 only
__device__ float g_r[NHEADS * SEQ];
__device__ float g_rowsum[NHEADS * SEQ];
__device__ float g_cs1[NHEADS * SEQ];
__device__ float g_cs2[NHEADS * SEQ];
__device__ float g_cs3[NHEADS * SEQ];
__device__ float g_ho[(size_t)BQ * SEQ * DIMV];

// ---- tf32 GEMM: block 128x256, 8 warps @ 64x64, BK=16 ----------------------
__global__ __launch_bounds__(256) void gemm_tf32(
    const float* __restrict__ A, const float* __restrict__ Bm,
    float* __restrict__ C, int M, int N, int K, const float* __restrict__ bias)
{
    __shared__ float As[16 * 132];   // [k][m], pad 4
    __shared__ float Bs[16 * 260];   // [k][n], pad 4
    const int t = threadIdx.x;
    const int m0 = blockIdx.y * 128, n0 = blockIdx.x * 256;
    const int lane = t & 31, w = t >> 5;
    const int wm = w & 1, wn = w >> 1;
    const int g = lane >> 2, tc = lane & 3;
    const int m0w = wm * 64, n0w = wn * 64;
    const int arow = t >> 2, acol = (t & 3) * 4;
    const int bkr = t >> 6, bnc = (t & 63) * 4;

    float4 acc[4][8];
#pragma unroll
    for (int mf = 0; mf < 4; mf++)
#pragma unroll
        for (int nf = 0; nf < 8; nf++) acc[mf][nf] = make_float4(0.f, 0.f, 0.f, 0.f);

    for (int kt = 0; kt < K; kt += 16) {
#pragma unroll
        for (int q = 0; q < 2; q++) {
            int r_ = arow + q * 64;
            float4 v = *(const float4*)(A + (size_t)(m0 + r_) * K + kt + acol);
            As[(acol + 0) * 132 + r_] = tf32f(v.x);
            As[(acol + 1) * 132 + r_] = tf32f(v.y);
            As[(acol + 2) * 132 + r_] = tf32f(v.z);
            As[(acol + 3) * 132 + r_] = tf32f(v.w);
        }
#pragma unroll
        for (int q = 0; q < 4; q++) {
            int kr = bkr + q * 4;
            float4 v = *(const float4*)(Bm + (size_t)(kt + kr) * N + n0 + bnc);
            float4 o = make_float4(tf32f(v.x), tf32f(v.y), tf32f(v.z), tf32f(v.w));
            *(float4*)&Bs[kr * 260 + bnc] = o;
        }
        __syncthreads();
#pragma unroll
        for (int ks = 0; ks < 16; ks += 8) {
            u32 a[4][4];
#pragma unroll
            for (int mf = 0; mf < 4; mf++) {
                a[mf][0] = su(&As[(ks + tc) * 132 + m0w + mf * 16 + g]);
                a[mf][1] = su(&As[(ks + tc) * 132 + m0w + mf * 16 + g + 8]);
                a[mf][2] = su(&As[(ks + tc + 4) * 132 + m0w + mf * 16 + g]);
                a[mf][3] = su(&As[(ks + tc + 4) * 132 + m0w + mf * 16 + g + 8]);
            }
#pragma unroll
            for (int nf = 0; nf < 8; nf++) {
                u32 b0 = su(&Bs[(ks + tc) * 260 + n0w + nf * 8 + g]);
                u32 b1 = su(&Bs[(ks + tc + 4) * 260 + n0w + nf * 8 + g]);
#pragma unroll
                for (int mf = 0; mf < 4; mf++)
                    mma_tf32(acc[mf][nf], a[mf], b0, b1);
            }
        }
        __syncthreads();
    }
#pragma unroll
    for (int mf = 0; mf < 4; mf++) {
        int gr = m0 + m0w + mf * 16 + g;
#pragma unroll
        for (int nf = 0; nf < 8; nf++) {
            int gc = n0 + n0w + nf * 8 + tc * 2;
            float2 lo = make_float2(acc[mf][nf].x, acc[mf][nf].y);
            float2 hi = make_float2(acc[mf][nf].z, acc[mf][nf].w);
            if (bias) {
                lo.x += bias[gc]; lo.y += bias[gc + 1];
                hi.x += bias[gc]; hi.y += bias[gc + 1];
            }
            *(float2*)(C + (size_t)gr * N + gc) = lo;
            *(float2*)(C + (size_t)(gr + 8) * N + gc) = hi;
        }
    }
}

// ------- dots (tf32 mma, 128x256 tile) -> E fp16, fused row-sum -------------
__global__ __launch_bounds__(256) void qk_dots_exp(
    const float* __restrict__ qkv, __half* __restrict__ Eh,
    float* __restrict__ rowsum)
{
    __shared__ float As[16 * 132];   // [d][i]
    __shared__ float Bs[16 * 260];   // [d][j]
    const int bh = blockIdx.z, b = bh >> 3, h = bh & 7;
    const int i0 = blockIdx.y * 128, j0 = blockIdx.x * 256;
    const float* qbase = qkv + (size_t)b * SEQ * QKVW + h * DHEAD;
    const float* kbase = qkv + (size_t)b * SEQ * QKVW + 512 + h * DHEAD;

    const int t = threadIdx.x;
    const int lane = t & 31, w = t >> 5;
    const int wm = w & 1, wn = w >> 1;
    const int g = lane >> 2, tc = lane & 3;
    const int m0w = wm * 64, n0w = wn * 64;
    const int arow = t >> 2, acol = (t & 3) * 4;

    float4 acc[4][8];
#pragma unroll
    for (int mf = 0; mf < 4; mf++)
#pragma unroll
        for (int nf = 0; nf < 8; nf++) acc[mf][nf] = make_float4(0.f, 0.f, 0.f, 0.f);

#pragma unroll
    for (int kt = 0; kt < DHEAD; kt += 16) {
#pragma unroll
        for (int q = 0; q < 2; q++) {
            int r_ = arow + q * 64;
            float4 qv = *(const float4*)(qbase + (size_t)(i0 + r_) * QKVW + kt + acol);
            As[(acol + 0) * 132 + r_] = tf32f(qv.x);
            As[(acol + 1) * 132 + r_] = tf32f(qv.y);
            As[(acol + 2) * 132 + r_] = tf32f(qv.z);
            As[(acol + 3) * 132 + r_] = tf32f(qv.w);
        }
#pragma unroll
        for (int q = 0; q < 4; q++) {
            int r_ = (t + 256 * q) >> 2;
            int c_ = ((t + 256 * q) & 3) * 4;
            float4 kv = *(const float4*)(kbase + (size_t)(j0 + r_) * QKVW + kt + c_);
            Bs[(c_ + 0) * 260 + r_] = tf32f(kv.x);
            Bs[(c_ + 1) * 260 + r_] = tf32f(kv.y);
            Bs[(c_ + 2) * 260 + r_] = tf32f(kv.z);
            Bs[(c_ + 3) * 260 + r_] = tf32f(kv.w);
        }
        __syncthreads();
#pragma unroll
        for (int ks = 0; ks < 16; ks += 8) {
            u32 a[4][4];
#pragma unroll
            for (int mf = 0; mf < 4; mf++) {
                a[mf][0] = su(&As[(ks + tc) * 132 + m0w + mf * 16 + g]);
                a[mf][1] = su(&As[(ks + tc) * 132 + m0w + mf * 16 + g + 8]);
                a[mf][2] = su(&As[(ks + tc + 4) * 132 + m0w + mf * 16 + g]);
                a[mf][3] = su(&As[(ks + tc + 4) * 132 + m0w + mf * 16 + g + 8]);
            }
#pragma unroll
            for (int nf = 0; nf < 8; nf++) {
                u32 b0 = su(&Bs[(ks + tc) * 260 + n0w + nf * 8 + g]);
                u32 b1 = su(&Bs[(ks + tc + 4) * 260 + n0w + nf * 8 + g]);
#pragma unroll
                for (int mf = 0; mf < 4; mf++)
                    mma_tf32(acc[mf][nf], a[mf], b0, b1);
            }
        }
        __syncthreads();
    }

    __half* Ehp = Eh + (size_t)bh * SEQ * SEQ;
#pragma unroll
    for (int mf = 0; mf < 4; mf++) {
        int gi = i0 + m0w + mf * 16 + g;
        float rs0 = 0.f, rs1 = 0.f;
#pragma unroll
        for (int nf = 0; nf < 8; nf++) {
            int gj = j0 + n0w + nf * 8 + tc * 2;
            float e0 = __expf(-0.125f * acc[mf][nf].x);
            float e1 = __expf(-0.125f * acc[mf][nf].y);
            float e2 = __expf(-0.125f * acc[mf][nf].z);
            float e3 = __expf(-0.125f * acc[mf][nf].w);
            *(__half2*)(Ehp + (size_t)gi * SEQ + gj) = __floats2half2_rn(e0, e1);
            *(__half2*)(Ehp + (size_t)(gi + 8) * SEQ + gj) = __floats2half2_rn(e2, e3);
            rs0 += e0 + e1; rs1 += e2 + e3;
        }
        rs0 += __shfl_xor_sync(0xffffffffu, rs0, 1);
        rs0 += __shfl_xor_sync(0xffffffffu, rs0, 2);
        rs1 += __shfl_xor_sync(0xffffffffu, rs1, 1);
        rs1 += __shfl_xor_sync(0xffffffffu, rs1, 2);
        if (tc == 0) {
            atomicAdd(&rowsum[bh * SEQ + gi], rs0);
            atomicAdd(&rowsum[bh * SEQ + gi + 8], rs1);
        }
    }
}

// ---- col pass over fp16 E: colsum_j += sum_i E_ij * rs_i -------------------
__global__ __launch_bounds__(256) void colpass_h(
    const __half* __restrict__ Eh, const float* __restrict__ rvec,
    float* __restrict__ colsum, int recip)
{
    const int bh = blockIdx.y;
    const int i0 = blockIdx.x * 64;
    const int t = threadIdx.x;
    __shared__ float rs[64];
    if (t < 64) {
        float rv = rvec[bh * SEQ + i0 + t];
        rs[t] = recip ? (MU_C / rv) : rv;
    }
    __syncthreads();

    const __half* Ep = Eh + (size_t)bh * SEQ * SEQ + (size_t)i0 * SEQ;
    const int j = t * 4;
    float ax = 0.f, ay = 0.f, az = 0.f, aw = 0.f;
#pragma unroll 4
    for (int i = 0; i < 64; i++) {
        uint2 raw = *(const uint2*)(Ep + (size_t)i * SEQ + j);
        float2 f0 = __half22float2(*(__half2*)&raw.x);
        float2 f1 = __half22float2(*(__half2*)&raw.y);
        float rv = rs[i];
        ax = fmaf(f0.x, rv, ax); ay = fmaf(f0.y, rv, ay);
        az = fmaf(f1.x, rv, az); aw = fmaf(f1.y, rv, aw);
    }
    atomicAdd(&colsum[bh * SEQ + j + 0], ax);
    atomicAdd(&colsum[bh * SEQ + j + 1], ay);
    atomicAdd(&colsum[bh * SEQ + j + 2], az);
    atomicAdd(&colsum[bh * SEQ + j + 3], aw);
}

// ---- row pass over fp16 E: r_i = MU / sum_j E_ij * (NU/colsum_j) -----------
__global__ __launch_bounds__(256) void rowpass_h(
    const __half* __restrict__ Eh, const float* __restrict__ colsum,
    float* __restrict__ r)
{
    const int bh = blockIdx.y;
    const int t = threadIdx.x, lane = t & 31, w = t >> 5;
    const int row = blockIdx.x * 8 + w;
    __shared__ float cs[SEQ];
    {
        float4 cv = *(const float4*)(colsum + bh * SEQ + t * 4);
        cs[t * 4 + 0] = NU_C / cv.x;
        cs[t * 4 + 1] = NU_C / cv.y;
        cs[t * 4 + 2] = NU_C / cv.z;
        cs[t * 4 + 3] = NU_C / cv.w;
    }
    __syncthreads();

    const __half* Er = Eh + (size_t)bh * SEQ * SEQ + (size_t)row * SEQ;
    float acc = 0.f;
#pragma unroll
    for (int it = 0; it < 8; it++) {
        int j = it * 128 + lane * 4;
        uint2 raw = *(const uint2*)(Er + j);
        float2 f0 = __half22float2(*(__half2*)&raw.x);
        float2 f1 = __half22float2(*(__half2*)&raw.y);
        acc += f0.x * cs[j] + f0.y * cs[j + 1] + f1.x * cs[j + 2] + f1.y * cs[j + 3];
    }
#pragma unroll
    for (int o = 16; o > 0; o >>= 1)
        acc += __shfl_xor_sync(0xffffffffu, acc, o);
    if (lane == 0) r[bh * SEQ + row] = MU_C / acc;
}

__global__ void init_sums(float* __restrict__ rowsum, float* __restrict__ c1,
                          float* __restrict__ c2, float* __restrict__ c3)
{
    int i = blockIdx.x * 256 + threadIdx.x;
    rowsum[i] = 0.f; c1[i] = 0.f; c2[i] = 0.f; c3[i] = 0.f;
}

// --- per-head AV (tf32 mma, fp16-E input): ho = rn_i*(E@(c_j V)) ------------
__global__ __launch_bounds__(256) void av_gemm(
    const __half* __restrict__ Eh, const float* __restrict__ r,
    const float* __restrict__ colsum3, const float* __restrict__ qkv,
    float* __restrict__ attn, float* __restrict__ ho, int write_attn)
{
    __shared__ float Es[32][132];   // [j][i]
    __shared__ float Ws[32][68];    // [j][d]
    __shared__ float cr[SEQ];
    __shared__ float rn[128];

    const int bh = blockIdx.y, b = bh >> 3, h = bh & 7;
    const int i0 = blockIdx.x * 128;
    const int t = threadIdx.x;
    const int lane = t & 31, w = t >> 5;
    const int wm = w & 3, wn = w >> 2;
    const int g = lane >> 2, tc = lane & 3;
    const int m0w = wm * 32, n0w = wn * 32;

    if (t < 128) rn[t] = r[bh * SEQ + i0 + t] * 1024.0f;
#pragma unroll
    for (int q = 0; q < 4; q++) {
        int j = t + 256 * q;
        cr[j] = NU_C / colsum3[bh * SEQ + j];
    }
    __syncthreads();

    const __half* Ep = Eh + (size_t)bh * SEQ * SEQ;
    const float* vb = qkv + (size_t)b * SEQ * QKVW + 1024 + h * DHEAD;
    float* ap = attn + (size_t)bh * SEQ * SEQ;

    float4 acc[2][4];
#pragma unroll
    for (int mf = 0; mf < 2; mf++)
#pragma unroll
        for (int nf = 0; nf < 4; nf++) acc[mf][nf] = make_float4(0.f, 0.f, 0.f, 0.f);

    for (int jt = 0; jt < 32; jt++) {
        const int j0 = jt * 32;
#pragma unroll
        for (int q = 0; q < 4; q++) {
            int f = t + 256 * q;
            int i = f >> 3, jq = (f & 7) * 4;
            uint2 raw = *(const uint2*)(Ep + (size_t)(i0 + i) * SEQ + j0 + jq);
            float2 e0 = __half22float2(*(__half2*)&raw.x);
            float2 e1 = __half22float2(*(__half2*)&raw.y);
            if (write_attn) {
                float rv = rn[i];
                float4 o;
                o.x = rv * e0.x * cr[j0 + jq + 0];
                o.y = rv * e0.y * cr[j0 + jq + 1];
                o.z = rv * e1.x * cr[j0 + jq + 2];
                o.w = rv * e1.y * cr[j0 + jq + 3];
                *(float4*)(ap + (size_t)(i0 + i) * SEQ + j0 + jq) = o;
            }
            Es[jq + 0][i] = tf32f(e0.x); Es[jq + 1][i] = tf32f(e0.y);
            Es[jq + 2][i] = tf32f(e1.x); Es[jq + 3][i] = tf32f(e1.y);
        }
#pragma unroll
        for (int q = 0; q < 2; q++) {
            int f = t + 256 * q;
            int k = f >> 4, dq = (f & 15) * 4;
            float4 v = *(const float4*)(vb + (size_t)(j0 + k) * QKVW + dq);
            float cw = cr[j0 + k];
            Ws[k][dq + 0] = tf32f(v.x * cw); Ws[k][dq + 1] = tf32f(v.y * cw);
            Ws[k][dq + 2] = tf32f(v.z * cw); Ws[k][dq + 3] = tf32f(v.w * cw);
        }
        __syncthreads();
#pragma unroll
        for (int ks = 0; ks < 32; ks += 8) {
            u32 a[2][4];
#pragma unroll
            for (int mf = 0; mf < 2; mf++) {
                a[mf][0] = su(&Es[ks + tc][m0w + mf * 16 + g]);
                a[mf][1] = su(&Es[ks + tc][m0w + mf * 16 + g + 8]);
                a[mf][2] = su(&Es[ks + tc + 4][m0w + mf * 16 + g]);
                a[mf][3] = su(&Es[ks + tc + 4][m0w + mf * 16 + g + 8]);
            }
#pragma unroll
            for (int nf = 0; nf < 4; nf++) {
                u32 b0 = su(&Ws[ks + tc][n0w + nf * 8 + g]);
                u32 b1 = su(&Ws[ks + tc + 4][n0w + nf * 8 + g]);
                mma_tf32(acc[0][nf], a[0], b0, b1);
                mma_tf32(acc[1][nf], a[1], b0, b1);
            }
        }
        __syncthreads();
    }
#pragma unroll
    for (int mf = 0; mf < 2; mf++) {
        int il = m0w + mf * 16 + g;
        float rv0 = rn[il], rv1 = rn[il + 8];
        float* hp0 = ho + (size_t)(b * SEQ + i0 + il) * DIMV + h * DHEAD;
        float* hp1 = ho + (size_t)(b * SEQ + i0 + il + 8) * DIMV + h * DHEAD;
#pragma unroll
        for (int nf = 0; nf < 4; nf++) {
            int gc = n0w + nf * 8 + tc * 2;
            *(float2*)(hp0 + gc) = make_float2(acc[mf][nf].x * rv0, acc[mf][nf].y * rv0);
            *(float2*)(hp1 + gc) = make_float2(acc[mf][nf].z * rv1, acc[mf][nf].w * rv1);
        }
    }
}

// ---------------- launcher ---------------------------------------------------
extern "C" void kernel_launch(void* const* d_in, const int* in_sizes, int n_in,
                              void* d_out, int out_size)
{
    const float* x    = (const float*)d_in[0];
    const float* Wqkv = (const float*)d_in[1];
    const float* Wout = (const float*)d_in[2];
    const float* bout = (const float*)d_in[3];
    float* out = (float*)d_out;

    float *qkvp, *rp, *rsp, *c1p, *c2p, *c3p, *hop;
    __half* Ehp;
    cudaGetSymbolAddress((void**)&qkvp, g_qkv);
    cudaGetSymbolAddress((void**)&Ehp,  g_Eh);
    cudaGetSymbolAddress((void**)&rp,   g_r);
    cudaGetSymbolAddress((void**)&rsp,  g_rowsum);
    cudaGetSymbolAddress((void**)&c1p,  g_cs1);
    cudaGetSymbolAddress((void**)&c2p,  g_cs2);
    cudaGetSymbolAddress((void**)&c3p,  g_cs3);
    cudaGetSymbolAddress((void**)&hop,  g_ho);

    const size_t FIN = (size_t)BQ * SEQ * DIMV;
    const size_t ATT = (size_t)NHEADS * SEQ * SEQ;
    float* fin_ptr = 0;
    float* attn_ptr = 0;
    if ((size_t)out_size >= FIN + ATT) { fin_ptr = out; attn_ptr = out + FIN; }
    else if ((size_t)out_size == ATT)  { attn_ptr = out; }
    else                               { fin_ptr = out; }

    const int NV = NHEADS * SEQ;

    init_sums<<<NV / 256, 256>>>(rsp, c1p, c2p, c3p);

    // 1) qkv = x @ W_qkv  (tf32, 128x256 tiles)
    gemm_tf32<<<dim3(QKVW / 256, (BQ * SEQ) / 128), 256>>>(
        x, Wqkv, qkvp, BQ * SEQ, QKVW, DIMV, (const float*)0);

    // 2) E = exp(-scale*q k^T) stored fp16 only, fused rowsum (c0 = 1)
    qk_dots_exp<<<dim3(SEQ / 256, SEQ / 128, NHEADS), 256>>>(qkvp, Ehp, rsp);

    // 3) Sinkhorn over fp16 E: col1, row2, col2, row3, col3
    colpass_h<<<dim3(SEQ / 64, NHEADS), 256>>>(Ehp, rsp, c1p, 1);
    rowpass_h<<<dim3(SEQ / 8, NHEADS), 256>>>(Ehp, c1p, rp);
    colpass_h<<<dim3(SEQ / 64, NHEADS), 256>>>(Ehp, rp, c2p, 0);
    rowpass_h<<<dim3(SEQ / 8, NHEADS), 256>>>(Ehp, c2p, rp);
    colpass_h<<<dim3(SEQ / 64, NHEADS), 256>>>(Ehp, rp, c3p, 0);

    // 4) attn = r*E*c*n (fused write) and ho = attn @ V (tf32 mma)
    av_gemm<<<dim3(SEQ / 128, NHEADS), 256>>>(
        Ehp, rp, c3p, qkvp, attn_ptr ? attn_ptr : hop, hop, attn_ptr ? 1 : 0);

    // 5) final = ho @ W_out + b_out  (tf32, 128x256 tiles)
    if (fin_ptr)
        gemm_tf32<<<dim3(DIMV / 256, (BQ * SEQ) / 128), 256>>>(
            hop, Wout, fin_ptr, BQ * SEQ, DIMV, DIMV, bout);
}

// round 11
// speedup vs baseline: 2.3359x; 1.2457x over previous
#include <cuda_runtime.h>
#include <cuda_fp16.h>
#include <math.h>

#define BQ 8
#define SEQ 1024
#define DIMV 512
#define HEADS 8
#define DHEAD 64
#define NHEADS 64        // BQ*HEADS
#define QKVW 1536        // 3*HEADS*DHEAD

#define MU_C (1.0f/1024.0f)
#define NU_C (1.0f/1024.0f)

typedef unsigned int u32;

__device__ __forceinline__ u32 sptr(const void* p) {
    return (u32)__cvta_generic_to_shared(p);
}
__device__ __forceinline__ void ldsm_x4(u32& r0, u32& r1, u32& r2, u32& r3, u32 a) {
    asm volatile("ldmatrix.sync.aligned.m8n8.x4.shared.b16 {%0,%1,%2,%3},[%4];"
        : "=r"(r0), "=r"(r1), "=r"(r2), "=r"(r3) : "r"(a));
}
__device__ __forceinline__ void ldsm_x4t(u32& r0, u32& r1, u32& r2, u32& r3, u32 a) {
    asm volatile("ldmatrix.sync.aligned.m8n8.x4.trans.shared.b16 {%0,%1,%2,%3},[%4];"
        : "=r"(r0), "=r"(r1), "=r"(r2), "=r"(r3) : "r"(a));
}
__device__ __forceinline__ void mma_f16(float4& d, const u32* a, u32 b0, u32 b1) {
    asm volatile(
        "mma.sync.aligned.m16n8k16.row.col.f32.f16.f16.f32 "
        "{%0,%1,%2,%3},{%4,%5,%6,%7},{%8,%9},{%0,%1,%2,%3};"
        : "+f"(d.x), "+f"(d.y), "+f"(d.z), "+f"(d.w)
        : "r"(a[0]), "r"(a[1]), "r"(a[2]), "r"(a[3]), "r"(b0), "r"(b1));
}

// ---------------- scratch (device globals; no allocations allowed) ----------
__device__ __half g_qkv[(size_t)BQ * SEQ * QKVW];      // fp16 qkv
__device__ __half g_Eh[(size_t)NHEADS * SEQ * SEQ];    // E = exp(-C), fp16
__device__ float g_r[NHEADS * SEQ];
__device__ float g_rowsum[NHEADS * SEQ];
__device__ float g_cs1[NHEADS * SEQ];
__device__ float g_cs2[NHEADS * SEQ];
__device__ float g_cs3[NHEADS * SEQ];
__device__ __half g_ho[(size_t)BQ * SEQ * DIMV];       // fp16 head-merged out

// ---- qkv GEMM: fp32 A,B -> fp16 C. block 128x128, BK=32, fp16 mma ----------
__global__ __launch_bounds__(256) void qkv_gemm(
    const float* __restrict__ A, const float* __restrict__ Bm,
    __half* __restrict__ C, int M, int N, int K)
{
    __shared__ __half Ah[128 * 40];
    __shared__ __half Bh[32 * 136];
    const int t = threadIdx.x;
    const int m0 = blockIdx.y * 128, n0 = blockIdx.x * 128;
    const int lane = t & 31, w = t >> 5;
    const int wm = w & 3, wn = w >> 2;
    const int g = lane >> 2, tc = lane & 3;
    const int m0w = wm * 32, n0w = wn * 64;

    float4 acc[2][8];
#pragma unroll
    for (int mf = 0; mf < 2; mf++)
#pragma unroll
        for (int nf = 0; nf < 8; nf++) acc[mf][nf] = make_float4(0.f, 0.f, 0.f, 0.f);

    const u32 aAddrBase = sptr(Ah) + ((lane & 15) * 40 + ((lane >> 4) << 3)) * 2;
    const u32 bAddrBase = sptr(Bh) +
        ((((lane >> 3) & 1) * 8 + (lane & 7)) * 136 + ((lane >> 4) << 3)) * 2;

    for (int kt = 0; kt < K; kt += 32) {
#pragma unroll
        for (int q = 0; q < 4; q++) {
            int f = t + 256 * q;
            int row = f >> 3, c4 = (f & 7) * 4;
            float4 v = *(const float4*)(A + (size_t)(m0 + row) * K + kt + c4);
            *(__half2*)(Ah + row * 40 + c4)     = __floats2half2_rn(v.x, v.y);
            *(__half2*)(Ah + row * 40 + c4 + 2) = __floats2half2_rn(v.z, v.w);
        }
#pragma unroll
        for (int q = 0; q < 4; q++) {
            int f = t + 256 * q;
            int kr = f >> 5, nc = (f & 31) * 4;
            float4 v = *(const float4*)(Bm + (size_t)(kt + kr) * N + n0 + nc);
            *(__half2*)(Bh + kr * 136 + nc)     = __floats2half2_rn(v.x, v.y);
            *(__half2*)(Bh + kr * 136 + nc + 2) = __floats2half2_rn(v.z, v.w);
        }
        __syncthreads();
#pragma unroll
        for (int ks = 0; ks < 32; ks += 16) {
            u32 a[2][4];
#pragma unroll
            for (int mf = 0; mf < 2; mf++)
                ldsm_x4(a[mf][0], a[mf][1], a[mf][2], a[mf][3],
                        aAddrBase + ((m0w + mf * 16) * 40 + ks) * 2);
#pragma unroll
            for (int nb = 0; nb < 4; nb++) {
                u32 b0, b1, b2, b3;
                ldsm_x4t(b0, b1, b2, b3,
                         bAddrBase + (ks * 136 + n0w + nb * 16) * 2);
                mma_f16(acc[0][nb * 2 + 0], a[0], b0, b1);
                mma_f16(acc[0][nb * 2 + 1], a[0], b2, b3);
                mma_f16(acc[1][nb * 2 + 0], a[1], b0, b1);
                mma_f16(acc[1][nb * 2 + 1], a[1], b2, b3);
            }
        }
        __syncthreads();
    }
#pragma unroll
    for (int mf = 0; mf < 2; mf++) {
        int gr = m0 + m0w + mf * 16 + g;
#pragma unroll
        for (int nf = 0; nf < 8; nf++) {
            int gc = n0 + n0w + nf * 8 + tc * 2;
            *(__half2*)(C + (size_t)gr * N + gc) =
                __floats2half2_rn(acc[mf][nf].x, acc[mf][nf].y);
            *(__half2*)(C + (size_t)(gr + 8) * N + gc) =
                __floats2half2_rn(acc[mf][nf].z, acc[mf][nf].w);
        }
    }
}

// ---- out GEMM: fp16 A, fp32 B -> fp32 C + bias ------------------------------
__global__ __launch_bounds__(256) void out_gemm(
    const __half* __restrict__ A, const float* __restrict__ Bm,
    float* __restrict__ C, int M, int N, int K, const float* __restrict__ bias)
{
    __shared__ __half Ah[128 * 40];
    __shared__ __half Bh[32 * 136];
    const int t = threadIdx.x;
    const int m0 = blockIdx.y * 128, n0 = blockIdx.x * 128;
    const int lane = t & 31, w = t >> 5;
    const int wm = w & 3, wn = w >> 2;
    const int g = lane >> 2, tc = lane & 3;
    const int m0w = wm * 32, n0w = wn * 64;

    float4 acc[2][8];
#pragma unroll
    for (int mf = 0; mf < 2; mf++)
#pragma unroll
        for (int nf = 0; nf < 8; nf++) acc[mf][nf] = make_float4(0.f, 0.f, 0.f, 0.f);

    const u32 aAddrBase = sptr(Ah) + ((lane & 15) * 40 + ((lane >> 4) << 3)) * 2;
    const u32 bAddrBase = sptr(Bh) +
        ((((lane >> 3) & 1) * 8 + (lane & 7)) * 136 + ((lane >> 4) << 3)) * 2;

    for (int kt = 0; kt < K; kt += 32) {
#pragma unroll
        for (int q = 0; q < 2; q++) {
            int f = t + 256 * q;
            int row = f >> 2, c8 = (f & 3) * 8;
            uint4 v = *(const uint4*)(A + (size_t)(m0 + row) * K + kt + c8);
            *(uint4*)(Ah + row * 40 + c8) = v;
        }
#pragma unroll
        for (int q = 0; q < 4; q++) {
            int f = t + 256 * q;
            int kr = f >> 5, nc = (f & 31) * 4;
            float4 v = *(const float4*)(Bm + (size_t)(kt + kr) * N + n0 + nc);
            *(__half2*)(Bh + kr * 136 + nc)     = __floats2half2_rn(v.x, v.y);
            *(__half2*)(Bh + kr * 136 + nc + 2) = __floats2half2_rn(v.z, v.w);
        }
        __syncthreads();
#pragma unroll
        for (int ks = 0; ks < 32; ks += 16) {
            u32 a[2][4];
#pragma unroll
            for (int mf = 0; mf < 2; mf++)
                ldsm_x4(a[mf][0], a[mf][1], a[mf][2], a[mf][3],
                        aAddrBase + ((m0w + mf * 16) * 40 + ks) * 2);
#pragma unroll
            for (int nb = 0; nb < 4; nb++) {
                u32 b0, b1, b2, b3;
                ldsm_x4t(b0, b1, b2, b3,
                         bAddrBase + (ks * 136 + n0w + nb * 16) * 2);
                mma_f16(acc[0][nb * 2 + 0], a[0], b0, b1);
                mma_f16(acc[0][nb * 2 + 1], a[0], b2, b3);
                mma_f16(acc[1][nb * 2 + 0], a[1], b0, b1);
                mma_f16(acc[1][nb * 2 + 1], a[1], b2, b3);
            }
        }
        __syncthreads();
    }
#pragma unroll
    for (int mf = 0; mf < 2; mf++) {
        int gr = m0 + m0w + mf * 16 + g;
#pragma unroll
        for (int nf = 0; nf < 8; nf++) {
            int gc = n0 + n0w + nf * 8 + tc * 2;
            float2 lo = make_float2(acc[mf][nf].x + bias[gc],
                                    acc[mf][nf].y + bias[gc + 1]);
            float2 hi = make_float2(acc[mf][nf].z + bias[gc],
                                    acc[mf][nf].w + bias[gc + 1]);
            *(float2*)(C + (size_t)gr * N + gc) = lo;
            *(float2*)(C + (size_t)(gr + 8) * N + gc) = hi;
        }
    }
}

// ------- dots (fp16 mma): E = exp(-scale*q k^T) fp16, fused row-sum ---------
__global__ __launch_bounds__(256) void qk_dots_exp(
    const __half* __restrict__ qkv, __half* __restrict__ Eh,
    float* __restrict__ rowsum)
{
    __shared__ __half Ah[128 * 72];   // [i][d], d=64+8 pad
    __shared__ __half Bh[128 * 72];   // [j][d]
    const int bh = blockIdx.z, b = bh >> 3, h = bh & 7;
    const int i0 = blockIdx.y * 128, j0 = blockIdx.x * 128;
    const __half* qbase = qkv + (size_t)b * SEQ * QKVW + h * DHEAD;
    const __half* kbase = qkv + (size_t)b * SEQ * QKVW + 512 + h * DHEAD;

    const int t = threadIdx.x;
    const int lane = t & 31, w = t >> 5;
    const int wm = w & 3, wn = w >> 2;
    const int g = lane >> 2, tc = lane & 3;
    const int m0w = wm * 32, n0w = wn * 64;

    float4 acc[2][8];
#pragma unroll
    for (int mf = 0; mf < 2; mf++)
#pragma unroll
        for (int nf = 0; nf < 8; nf++) acc[mf][nf] = make_float4(0.f, 0.f, 0.f, 0.f);

    // load q/k tiles (128 x 64 halves each)
#pragma unroll
    for (int q = 0; q < 4; q++) {
        int f = t + 256 * q;
        int row = f >> 3, c8 = (f & 7) * 8;
        *(uint4*)(Ah + row * 72 + c8) =
            *(const uint4*)(qbase + (size_t)(i0 + row) * QKVW + c8);
        *(uint4*)(Bh + row * 72 + c8) =
            *(const uint4*)(kbase + (size_t)(j0 + row) * QKVW + c8);
    }
    __syncthreads();

    const u32 aAddrBase = sptr(Ah) + ((lane & 15) * 72 + ((lane >> 4) << 3)) * 2;
    const u32 bAddrBase = sptr(Bh) +
        ((((lane >> 4) << 3) + (lane & 7)) * 72 + (((lane >> 3) & 1) * 8)) * 2;

#pragma unroll
    for (int ks = 0; ks < 64; ks += 16) {
        u32 a[2][4];
#pragma unroll
        for (int mf = 0; mf < 2; mf++)
            ldsm_x4(a[mf][0], a[mf][1], a[mf][2], a[mf][3],
                    aAddrBase + ((m0w + mf * 16) * 72 + ks) * 2);
#pragma unroll
        for (int nb = 0; nb < 4; nb++) {
            u32 b0, b1, b2, b3;
            ldsm_x4(b0, b1, b2, b3,
                    bAddrBase + ((n0w + nb * 16) * 72 + ks) * 2);
            mma_f16(acc[0][nb * 2 + 0], a[0], b0, b1);
            mma_f16(acc[0][nb * 2 + 1], a[0], b2, b3);
            mma_f16(acc[1][nb * 2 + 0], a[1], b0, b1);
            mma_f16(acc[1][nb * 2 + 1], a[1], b2, b3);
        }
    }

    __half* Ehp = Eh + (size_t)bh * SEQ * SEQ;
#pragma unroll
    for (int mf = 0; mf < 2; mf++) {
        int gi = i0 + m0w + mf * 16 + g;
        float rs0 = 0.f, rs1 = 0.f;
#pragma unroll
        for (int nf = 0; nf < 8; nf++) {
            int gj = j0 + n0w + nf * 8 + tc * 2;
            float e0 = __expf(-0.125f * acc[mf][nf].x);
            float e1 = __expf(-0.125f * acc[mf][nf].y);
            float e2 = __expf(-0.125f * acc[mf][nf].z);
            float e3 = __expf(-0.125f * acc[mf][nf].w);
            *(__half2*)(Ehp + (size_t)gi * SEQ + gj) = __floats2half2_rn(e0, e1);
            *(__half2*)(Ehp + (size_t)(gi + 8) * SEQ + gj) = __floats2half2_rn(e2, e3);
            rs0 += e0 + e1; rs1 += e2 + e3;
        }
        rs0 += __shfl_xor_sync(0xffffffffu, rs0, 1);
        rs0 += __shfl_xor_sync(0xffffffffu, rs0, 2);
        rs1 += __shfl_xor_sync(0xffffffffu, rs1, 1);
        rs1 += __shfl_xor_sync(0xffffffffu, rs1, 2);
        if (tc == 0) {
            atomicAdd(&rowsum[bh * SEQ + gi], rs0);
            atomicAdd(&rowsum[bh * SEQ + gi + 8], rs1);
        }
    }
}

// ---- col pass over fp16 E ---------------------------------------------------
__global__ __launch_bounds__(256) void colpass_h(
    const __half* __restrict__ Eh, const float* __restrict__ rvec,
    float* __restrict__ colsum, int recip)
{
    const int bh = blockIdx.y;
    const int i0 = blockIdx.x * 64;
    const int t = threadIdx.x;
    __shared__ float rs[64];
    if (t < 64) {
        float rv = rvec[bh * SEQ + i0 + t];
        rs[t] = recip ? (MU_C / rv) : rv;
    }
    __syncthreads();

    const __half* Ep = Eh + (size_t)bh * SEQ * SEQ + (size_t)i0 * SEQ;
    const int j = t * 4;
    float ax = 0.f, ay = 0.f, az = 0.f, aw = 0.f;
#pragma unroll 4
    for (int i = 0; i < 64; i++) {
        uint2 raw = *(const uint2*)(Ep + (size_t)i * SEQ + j);
        float2 f0 = __half22float2(*(__half2*)&raw.x);
        float2 f1 = __half22float2(*(__half2*)&raw.y);
        float rv = rs[i];
        ax = fmaf(f0.x, rv, ax); ay = fmaf(f0.y, rv, ay);
        az = fmaf(f1.x, rv, az); aw = fmaf(f1.y, rv, aw);
    }
    atomicAdd(&colsum[bh * SEQ + j + 0], ax);
    atomicAdd(&colsum[bh * SEQ + j + 1], ay);
    atomicAdd(&colsum[bh * SEQ + j + 2], az);
    atomicAdd(&colsum[bh * SEQ + j + 3], aw);
}

// ---- row pass over fp16 E ----------------------------------------------------
__global__ __launch_bounds__(256) void rowpass_h(
    const __half* __restrict__ Eh, const float* __restrict__ colsum,
    float* __restrict__ r)
{
    const int bh = blockIdx.y;
    const int t = threadIdx.x, lane = t & 31, w = t >> 5;
    const int row = blockIdx.x * 8 + w;
    __shared__ float cs[SEQ];
    {
        float4 cv = *(const float4*)(colsum + bh * SEQ + t * 4);
        cs[t * 4 + 0] = NU_C / cv.x;
        cs[t * 4 + 1] = NU_C / cv.y;
        cs[t * 4 + 2] = NU_C / cv.z;
        cs[t * 4 + 3] = NU_C / cv.w;
    }
    __syncthreads();

    const __half* Er = Eh + (size_t)bh * SEQ * SEQ + (size_t)row * SEQ;
    float acc = 0.f;
#pragma unroll
    for (int it = 0; it < 8; it++) {
        int j = it * 128 + lane * 4;
        uint2 raw = *(const uint2*)(Er + j);
        float2 f0 = __half22float2(*(__half2*)&raw.x);
        float2 f1 = __half22float2(*(__half2*)&raw.y);
        acc += f0.x * cs[j] + f0.y * cs[j + 1] + f1.x * cs[j + 2] + f1.y * cs[j + 3];
    }
#pragma unroll
    for (int o = 16; o > 0; o >>= 1)
        acc += __shfl_xor_sync(0xffffffffu, acc, o);
    if (lane == 0) r[bh * SEQ + row] = MU_C / acc;
}

__global__ void init_sums(float* __restrict__ rowsum, float* __restrict__ c1,
                          float* __restrict__ c2, float* __restrict__ c3)
{
    int i = blockIdx.x * 256 + threadIdx.x;
    rowsum[i] = 0.f; c1[i] = 0.f; c2[i] = 0.f; c3[i] = 0.f;
}

// --- per-head AV (fp16 mma): ho = rn_i*(E@(c_j V)), fused attn write --------
__global__ __launch_bounds__(256) void av_gemm(
    const __half* __restrict__ Eh, const float* __restrict__ r,
    const float* __restrict__ colsum3, const __half* __restrict__ qkv,
    float* __restrict__ attn, __half* __restrict__ ho, int write_attn)
{
    __shared__ __half Es[128 * 40];   // [i][j-chunk]
    __shared__ __half Vs[32 * 72];    // [j][d]
    __shared__ float cr[SEQ];
    __shared__ float rn[128];

    const int bh = blockIdx.y, b = bh >> 3, h = bh & 7;
    const int i0 = blockIdx.x * 128;
    const int t = threadIdx.x;
    const int lane = t & 31, w = t >> 5;
    const int wm = w & 3, wn = w >> 2;
    const int g = lane >> 2, tc = lane & 3;
    const int m0w = wm * 32, n0w = wn * 32;

    if (t < 128) rn[t] = r[bh * SEQ + i0 + t] * 1024.0f;
#pragma unroll
    for (int q = 0; q < 4; q++) {
        int j = t + 256 * q;
        cr[j] = NU_C / colsum3[bh * SEQ + j];
    }
    __syncthreads();

    const __half* Ep = Eh + (size_t)bh * SEQ * SEQ;
    const __half* vb = qkv + (size_t)b * SEQ * QKVW + 1024 + h * DHEAD;
    float* ap = attn + (size_t)bh * SEQ * SEQ;

    float4 acc[2][4];
#pragma unroll
    for (int mf = 0; mf < 2; mf++)
#pragma unroll
        for (int nf = 0; nf < 4; nf++) acc[mf][nf] = make_float4(0.f, 0.f, 0.f, 0.f);

    const u32 aAddrBase = sptr(Es) + ((lane & 15) * 40 + ((lane >> 4) << 3)) * 2;
    const u32 bAddrBase = sptr(Vs) +
        ((((lane >> 3) & 1) * 8 + (lane & 7)) * 72 + ((lane >> 4) << 3)) * 2;

    for (int jt = 0; jt < 32; jt++) {
        const int j0 = jt * 32;
        // E tile 128x32 halves (+ fused fp32 attn write)
#pragma unroll
        for (int q = 0; q < 2; q++) {
            int f = t + 256 * q;
            int i = f >> 2, c8 = (f & 3) * 8;
            uint4 raw = *(const uint4*)(Ep + (size_t)(i0 + i) * SEQ + j0 + c8);
            *(uint4*)(Es + i * 40 + c8) = raw;
            if (write_attn) {
                float rv = rn[i];
                const __half2* hp = (const __half2*)&raw;
                float* dst = ap + (size_t)(i0 + i) * SEQ + j0 + c8;
#pragma unroll
                for (int p = 0; p < 4; p++) {
                    float2 e = __half22float2(hp[p]);
                    float2 o;
                    o.x = rv * e.x * cr[j0 + c8 + p * 2];
                    o.y = rv * e.y * cr[j0 + c8 + p * 2 + 1];
                    *(float2*)(dst + p * 2) = o;
                }
            }
        }
        // V tile 32x64, scale by c_j, keep [j][d] for trans-ldsm
        {
            int row = t >> 3, c8 = (t & 7) * 8;
            uint4 raw = *(const uint4*)(vb + (size_t)(j0 + row) * QKVW + c8);
            float cw = cr[j0 + row];
            const __half2* hp = (const __half2*)&raw;
            __half2* dst = (__half2*)(Vs + row * 72 + c8);
#pragma unroll
            for (int p = 0; p < 4; p++) {
                float2 v = __half22float2(hp[p]);
                dst[p] = __floats2half2_rn(v.x * cw, v.y * cw);
            }
        }
        __syncthreads();
#pragma unroll
        for (int ks = 0; ks < 32; ks += 16) {
            u32 a[2][4];
#pragma unroll
            for (int mf = 0; mf < 2; mf++)
                ldsm_x4(a[mf][0], a[mf][1], a[mf][2], a[mf][3],
                        aAddrBase + ((m0w + mf * 16) * 40 + ks) * 2);
#pragma unroll
            for (int nb = 0; nb < 2; nb++) {
                u32 b0, b1, b2, b3;
                ldsm_x4t(b0, b1, b2, b3,
                         bAddrBase + (ks * 72 + n0w + nb * 16) * 2);
                mma_f16(acc[0][nb * 2 + 0], a[0], b0, b1);
                mma_f16(acc[0][nb * 2 + 1], a[0], b2, b3);
                mma_f16(acc[1][nb * 2 + 0], a[1], b0, b1);
                mma_f16(acc[1][nb * 2 + 1], a[1], b2, b3);
            }
        }
        __syncthreads();
    }
#pragma unroll
    for (int mf = 0; mf < 2; mf++) {
        int il = m0w + mf * 16 + g;
        float rv0 = rn[il], rv1 = rn[il + 8];
        __half* hp0 = ho + (size_t)(b * SEQ + i0 + il) * DIMV + h * DHEAD;
        __half* hp1 = ho + (size_t)(b * SEQ + i0 + il + 8) * DIMV + h * DHEAD;
#pragma unroll
        for (int nf = 0; nf < 4; nf++) {
            int gc = n0w + nf * 8 + tc * 2;
            *(__half2*)(hp0 + gc) =
                __floats2half2_rn(acc[mf][nf].x * rv0, acc[mf][nf].y * rv0);
            *(__half2*)(hp1 + gc) =
                __floats2half2_rn(acc[mf][nf].z * rv1, acc[mf][nf].w * rv1);
        }
    }
}

// ---------------- launcher ---------------------------------------------------
extern "C" void kernel_launch(void* const* d_in, const int* in_sizes, int n_in,
                              void* d_out, int out_size)
{
    const float* x    = (const float*)d_in[0];
    const float* Wqkv = (const float*)d_in[1];
    const float* Wout = (const float*)d_in[2];
    const float* bout = (const float*)d_in[3];
    float* out = (float*)d_out;

    float *rp, *rsp, *c1p, *c2p, *c3p;
    __half *qkvp, *Ehp, *hop;
    cudaGetSymbolAddress((void**)&qkvp, g_qkv);
    cudaGetSymbolAddress((void**)&Ehp,  g_Eh);
    cudaGetSymbolAddress((void**)&rp,   g_r);
    cudaGetSymbolAddress((void**)&rsp,  g_rowsum);
    cudaGetSymbolAddress((void**)&c1p,  g_cs1);
    cudaGetSymbolAddress((void**)&c2p,  g_cs2);
    cudaGetSymbolAddress((void**)&c3p,  g_cs3);
    cudaGetSymbolAddress((void**)&hop,  g_ho);

    const size_t FIN = (size_t)BQ * SEQ * DIMV;
    const size_t ATT = (size_t)NHEADS * SEQ * SEQ;
    float* fin_ptr = 0;
    float* attn_ptr = 0;
    if ((size_t)out_size >= FIN + ATT) { fin_ptr = out; attn_ptr = out + FIN; }
    else if ((size_t)out_size == ATT)  { attn_ptr = out; }
    else                               { fin_ptr = out; }

    const int NV = NHEADS * SEQ;

    init_sums<<<NV / 256, 256>>>(rsp, c1p, c2p, c3p);

    // 1) qkv = x @ W_qkv  (fp16 mma, fp16 output)
    qkv_gemm<<<dim3(QKVW / 128, (BQ * SEQ) / 128), 256>>>(
        x, Wqkv, qkvp, BQ * SEQ, QKVW, DIMV);

    // 2) E = exp(-scale*q k^T) fp16, fused rowsum (c0 = 1)
    qk_dots_exp<<<dim3(SEQ / 128, SEQ / 128, NHEADS), 256>>>(qkvp, Ehp, rsp);

    // 3) Sinkhorn over fp16 E: col1, row2, col2, row3, col3
    colpass_h<<<dim3(SEQ / 64, NHEADS), 256>>>(Ehp, rsp, c1p, 1);
    rowpass_h<<<dim3(SEQ / 8, NHEADS), 256>>>(Ehp, c1p, rp);
    colpass_h<<<dim3(SEQ / 64, NHEADS), 256>>>(Ehp, rp, c2p, 0);
    rowpass_h<<<dim3(SEQ / 8, NHEADS), 256>>>(Ehp, c2p, rp);
    colpass_h<<<dim3(SEQ / 64, NHEADS), 256>>>(Ehp, rp, c3p, 0);

    // 4) attn = r*E*c*n (fused fp32 write) and ho = attn @ V (fp16 mma)
    av_gemm<<<dim3(SEQ / 128, NHEADS), 256>>>(
        Ehp, rp, c3p, qkvp, attn_ptr ? attn_ptr : (float*)out, hop,
        attn_ptr ? 1 : 0);

    // 5) final = ho @ W_out + b_out  (fp16 mma, fp32 output)
    if (fin_ptr)
        out_gemm<<<dim3(DIMV / 128, (BQ * SEQ) / 128), 256>>>(
            hop, Wout, fin_ptr, BQ * SEQ, DIMV, DIMV, bout);
}

// round 12
// speedup vs baseline: 2.4005x; 1.0277x over previous
#include <cuda_runtime.h>
#include <cuda_fp16.h>
#include <math.h>

#define BQ 8
#define SEQ 1024
#define DIMV 512
#define HEADS 8
#define DHEAD 64
#define NHEADS 64        // BQ*HEADS
#define QKVW 1536        // 3*HEADS*DHEAD

#define MU_C (1.0f/1024.0f)
#define NU_C (1.0f/1024.0f)

typedef unsigned int u32;

__device__ __forceinline__ u32 sptr(const void* p) {
    return (u32)__cvta_generic_to_shared(p);
}
__device__ __forceinline__ void ldsm_x4(u32& r0, u32& r1, u32& r2, u32& r3, u32 a) {
    asm volatile("ldmatrix.sync.aligned.m8n8.x4.shared.b16 {%0,%1,%2,%3},[%4];"
        : "=r"(r0), "=r"(r1), "=r"(r2), "=r"(r3) : "r"(a));
}
__device__ __forceinline__ void ldsm_x4t(u32& r0, u32& r1, u32& r2, u32& r3, u32 a) {
    asm volatile("ldmatrix.sync.aligned.m8n8.x4.trans.shared.b16 {%0,%1,%2,%3},[%4];"
        : "=r"(r0), "=r"(r1), "=r"(r2), "=r"(r3) : "r"(a));
}
__device__ __forceinline__ void mma_f16(float4& d, const u32* a, u32 b0, u32 b1) {
    asm volatile(
        "mma.sync.aligned.m16n8k16.row.col.f32.f16.f16.f32 "
        "{%0,%1,%2,%3},{%4,%5,%6,%7},{%8,%9},{%0,%1,%2,%3};"
        : "+f"(d.x), "+f"(d.y), "+f"(d.z), "+f"(d.w)
        : "r"(a[0]), "r"(a[1]), "r"(a[2]), "r"(a[3]), "r"(b0), "r"(b1));
}

// ---------------- scratch (device globals; no allocations allowed) ----------
__device__ __half g_qkv[(size_t)BQ * SEQ * QKVW];      // fp16 qkv
__device__ __half g_Eh[(size_t)NHEADS * SEQ * SEQ];    // E = exp(-C), fp16
__device__ float g_r[NHEADS * SEQ];
__device__ float g_rowsum[NHEADS * SEQ];
__device__ float g_cs1[NHEADS * SEQ];
__device__ float g_cs2[NHEADS * SEQ];
__device__ float g_cs3[NHEADS * SEQ];
__device__ __half g_ho[(size_t)BQ * SEQ * DIMV];       // fp16 head-merged out

// ---- qkv GEMM: fp32 A,B -> fp16 C. block 128x128, BK=32, fp16 mma ----------
__global__ __launch_bounds__(256) void qkv_gemm(
    const float* __restrict__ A, const float* __restrict__ Bm,
    __half* __restrict__ C, int M, int N, int K)
{
    __shared__ __half Ah[128 * 40];
    __shared__ __half Bh[32 * 136];
    const int t = threadIdx.x;
    const int m0 = blockIdx.y * 128, n0 = blockIdx.x * 128;
    const int lane = t & 31, w = t >> 5;
    const int wm = w & 3, wn = w >> 2;
    const int g = lane >> 2, tc = lane & 3;
    const int m0w = wm * 32, n0w = wn * 64;

    float4 acc[2][8];
#pragma unroll
    for (int mf = 0; mf < 2; mf++)
#pragma unroll
        for (int nf = 0; nf < 8; nf++) acc[mf][nf] = make_float4(0.f, 0.f, 0.f, 0.f);

    const u32 aAddrBase = sptr(Ah) + ((lane & 15) * 40 + ((lane >> 4) << 3)) * 2;
    const u32 bAddrBase = sptr(Bh) +
        ((((lane >> 3) & 1) * 8 + (lane & 7)) * 136 + ((lane >> 4) << 3)) * 2;

    for (int kt = 0; kt < K; kt += 32) {
#pragma unroll
        for (int q = 0; q < 4; q++) {
            int f = t + 256 * q;
            int row = f >> 3, c4 = (f & 7) * 4;
            float4 v = *(const float4*)(A + (size_t)(m0 + row) * K + kt + c4);
            *(__half2*)(Ah + row * 40 + c4)     = __floats2half2_rn(v.x, v.y);
            *(__half2*)(Ah + row * 40 + c4 + 2) = __floats2half2_rn(v.z, v.w);
        }
#pragma unroll
        for (int q = 0; q < 4; q++) {
            int f = t + 256 * q;
            int kr = f >> 5, nc = (f & 31) * 4;
            float4 v = *(const float4*)(Bm + (size_t)(kt + kr) * N + n0 + nc);
            *(__half2*)(Bh + kr * 136 + nc)     = __floats2half2_rn(v.x, v.y);
            *(__half2*)(Bh + kr * 136 + nc + 2) = __floats2half2_rn(v.z, v.w);
        }
        __syncthreads();
#pragma unroll
        for (int ks = 0; ks < 32; ks += 16) {
            u32 a[2][4];
#pragma unroll
            for (int mf = 0; mf < 2; mf++)
                ldsm_x4(a[mf][0], a[mf][1], a[mf][2], a[mf][3],
                        aAddrBase + ((m0w + mf * 16) * 40 + ks) * 2);
#pragma unroll
            for (int nb = 0; nb < 4; nb++) {
                u32 b0, b1, b2, b3;
                ldsm_x4t(b0, b1, b2, b3,
                         bAddrBase + (ks * 136 + n0w + nb * 16) * 2);
                mma_f16(acc[0][nb * 2 + 0], a[0], b0, b1);
                mma_f16(acc[0][nb * 2 + 1], a[0], b2, b3);
                mma_f16(acc[1][nb * 2 + 0], a[1], b0, b1);
                mma_f16(acc[1][nb * 2 + 1], a[1], b2, b3);
            }
        }
        __syncthreads();
    }
#pragma unroll
    for (int mf = 0; mf < 2; mf++) {
        int gr = m0 + m0w + mf * 16 + g;
#pragma unroll
        for (int nf = 0; nf < 8; nf++) {
            int gc = n0 + n0w + nf * 8 + tc * 2;
            *(__half2*)(C + (size_t)gr * N + gc) =
                __floats2half2_rn(acc[mf][nf].x, acc[mf][nf].y);
            *(__half2*)(C + (size_t)(gr + 8) * N + gc) =
                __floats2half2_rn(acc[mf][nf].z, acc[mf][nf].w);
        }
    }
}

// ---- out GEMM: fp16 A, fp32 B -> fp32 C + bias ------------------------------
__global__ __launch_bounds__(256) void out_gemm(
    const __half* __restrict__ A, const float* __restrict__ Bm,
    float* __restrict__ C, int M, int N, int K, const float* __restrict__ bias)
{
    __shared__ __half Ah[128 * 40];
    __shared__ __half Bh[32 * 136];
    const int t = threadIdx.x;
    const int m0 = blockIdx.y * 128, n0 = blockIdx.x * 128;
    const int lane = t & 31, w = t >> 5;
    const int wm = w & 3, wn = w >> 2;
    const int g = lane >> 2, tc = lane & 3;
    const int m0w = wm * 32, n0w = wn * 64;

    float4 acc[2][8];
#pragma unroll
    for (int mf = 0; mf < 2; mf++)
#pragma unroll
        for (int nf = 0; nf < 8; nf++) acc[mf][nf] = make_float4(0.f, 0.f, 0.f, 0.f);

    const u32 aAddrBase = sptr(Ah) + ((lane & 15) * 40 + ((lane >> 4) << 3)) * 2;
    const u32 bAddrBase = sptr(Bh) +
        ((((lane >> 3) & 1) * 8 + (lane & 7)) * 136 + ((lane >> 4) << 3)) * 2;

    for (int kt = 0; kt < K; kt += 32) {
#pragma unroll
        for (int q = 0; q < 2; q++) {
            int f = t + 256 * q;
            int row = f >> 2, c8 = (f & 3) * 8;
            uint4 v = *(const uint4*)(A + (size_t)(m0 + row) * K + kt + c8);
            *(uint4*)(Ah + row * 40 + c8) = v;
        }
#pragma unroll
        for (int q = 0; q < 4; q++) {
            int f = t + 256 * q;
            int kr = f >> 5, nc = (f & 31) * 4;
            float4 v = *(const float4*)(Bm + (size_t)(kt + kr) * N + n0 + nc);
            *(__half2*)(Bh + kr * 136 + nc)     = __floats2half2_rn(v.x, v.y);
            *(__half2*)(Bh + kr * 136 + nc + 2) = __floats2half2_rn(v.z, v.w);
        }
        __syncthreads();
#pragma unroll
        for (int ks = 0; ks < 32; ks += 16) {
            u32 a[2][4];
#pragma unroll
            for (int mf = 0; mf < 2; mf++)
                ldsm_x4(a[mf][0], a[mf][1], a[mf][2], a[mf][3],
                        aAddrBase + ((m0w + mf * 16) * 40 + ks) * 2);
#pragma unroll
            for (int nb = 0; nb < 4; nb++) {
                u32 b0, b1, b2, b3;
                ldsm_x4t(b0, b1, b2, b3,
                         bAddrBase + (ks * 136 + n0w + nb * 16) * 2);
                mma_f16(acc[0][nb * 2 + 0], a[0], b0, b1);
                mma_f16(acc[0][nb * 2 + 1], a[0], b2, b3);
                mma_f16(acc[1][nb * 2 + 0], a[1], b0, b1);
                mma_f16(acc[1][nb * 2 + 1], a[1], b2, b3);
            }
        }
        __syncthreads();
    }
#pragma unroll
    for (int mf = 0; mf < 2; mf++) {
        int gr = m0 + m0w + mf * 16 + g;
#pragma unroll
        for (int nf = 0; nf < 8; nf++) {
            int gc = n0 + n0w + nf * 8 + tc * 2;
            float2 lo = make_float2(acc[mf][nf].x + bias[gc],
                                    acc[mf][nf].y + bias[gc + 1]);
            float2 hi = make_float2(acc[mf][nf].z + bias[gc],
                                    acc[mf][nf].w + bias[gc + 1]);
            *(float2*)(C + (size_t)gr * N + gc) = lo;
            *(float2*)(C + (size_t)(gr + 8) * N + gc) = hi;
        }
    }
}

// ------- dots (fp16 mma): E = exp(-scale*q k^T) fp16, fused row-sum ---------
__global__ __launch_bounds__(256) void qk_dots_exp(
    const __half* __restrict__ qkv, __half* __restrict__ Eh,
    float* __restrict__ rowsum)
{
    __shared__ __half Ah[128 * 72];   // [i][d]
    __shared__ __half Bh[128 * 72];   // [j][d]
    const int bh = blockIdx.z, b = bh >> 3, h = bh & 7;
    const int i0 = blockIdx.y * 128, j0 = blockIdx.x * 128;
    const __half* qbase = qkv + (size_t)b * SEQ * QKVW + h * DHEAD;
    const __half* kbase = qkv + (size_t)b * SEQ * QKVW + 512 + h * DHEAD;

    const int t = threadIdx.x;
    const int lane = t & 31, w = t >> 5;
    const int wm = w & 3, wn = w >> 2;
    const int g = lane >> 2, tc = lane & 3;
    const int m0w = wm * 32, n0w = wn * 64;

    float4 acc[2][8];
#pragma unroll
    for (int mf = 0; mf < 2; mf++)
#pragma unroll
        for (int nf = 0; nf < 8; nf++) acc[mf][nf] = make_float4(0.f, 0.f, 0.f, 0.f);

#pragma unroll
    for (int q = 0; q < 4; q++) {
        int f = t + 256 * q;
        int row = f >> 3, c8 = (f & 7) * 8;
        *(uint4*)(Ah + row * 72 + c8) =
            *(const uint4*)(qbase + (size_t)(i0 + row) * QKVW + c8);
        *(uint4*)(Bh + row * 72 + c8) =
            *(const uint4*)(kbase + (size_t)(j0 + row) * QKVW + c8);
    }
    __syncthreads();

    const u32 aAddrBase = sptr(Ah) + ((lane & 15) * 72 + ((lane >> 4) << 3)) * 2;
    const u32 bAddrBase = sptr(Bh) +
        ((((lane >> 4) << 3) + (lane & 7)) * 72 + (((lane >> 3) & 1) * 8)) * 2;

#pragma unroll
    for (int ks = 0; ks < 64; ks += 16) {
        u32 a[2][4];
#pragma unroll
        for (int mf = 0; mf < 2; mf++)
            ldsm_x4(a[mf][0], a[mf][1], a[mf][2], a[mf][3],
                    aAddrBase + ((m0w + mf * 16) * 72 + ks) * 2);
#pragma unroll
        for (int nb = 0; nb < 4; nb++) {
            u32 b0, b1, b2, b3;
            ldsm_x4(b0, b1, b2, b3,
                    bAddrBase + ((n0w + nb * 16) * 72 + ks) * 2);
            mma_f16(acc[0][nb * 2 + 0], a[0], b0, b1);
            mma_f16(acc[0][nb * 2 + 1], a[0], b2, b3);
            mma_f16(acc[1][nb * 2 + 0], a[1], b0, b1);
            mma_f16(acc[1][nb * 2 + 1], a[1], b2, b3);
        }
    }

    __half* Ehp = Eh + (size_t)bh * SEQ * SEQ;
#pragma unroll
    for (int mf = 0; mf < 2; mf++) {
        int gi = i0 + m0w + mf * 16 + g;
        float rs0 = 0.f, rs1 = 0.f;
#pragma unroll
        for (int nf = 0; nf < 8; nf++) {
            int gj = j0 + n0w + nf * 8 + tc * 2;
            float e0 = __expf(-0.125f * acc[mf][nf].x);
            float e1 = __expf(-0.125f * acc[mf][nf].y);
            float e2 = __expf(-0.125f * acc[mf][nf].z);
            float e3 = __expf(-0.125f * acc[mf][nf].w);
            *(__half2*)(Ehp + (size_t)gi * SEQ + gj) = __floats2half2_rn(e0, e1);
            *(__half2*)(Ehp + (size_t)(gi + 8) * SEQ + gj) = __floats2half2_rn(e2, e3);
            rs0 += e0 + e1; rs1 += e2 + e3;
        }
        rs0 += __shfl_xor_sync(0xffffffffu, rs0, 1);
        rs0 += __shfl_xor_sync(0xffffffffu, rs0, 2);
        rs1 += __shfl_xor_sync(0xffffffffu, rs1, 1);
        rs1 += __shfl_xor_sync(0xffffffffu, rs1, 2);
        if (tc == 0) {
            atomicAdd(&rowsum[bh * SEQ + gi], rs0);
            atomicAdd(&rowsum[bh * SEQ + gi + 8], rs1);
        }
    }
}

// ---- col pass over fp16 E ---------------------------------------------------
__global__ __launch_bounds__(256) void colpass_h(
    const __half* __restrict__ Eh, const float* __restrict__ rvec,
    float* __restrict__ colsum, int recip)
{
    const int bh = blockIdx.y;
    const int i0 = blockIdx.x * 64;
    const int t = threadIdx.x;
    __shared__ float rs[64];
    if (t < 64) {
        float rv = rvec[bh * SEQ + i0 + t];
        rs[t] = recip ? (MU_C / rv) : rv;
    }
    __syncthreads();

    const __half* Ep = Eh + (size_t)bh * SEQ * SEQ + (size_t)i0 * SEQ;
    const int j = t * 4;
    float ax = 0.f, ay = 0.f, az = 0.f, aw = 0.f;
#pragma unroll 8
    for (int i = 0; i < 64; i++) {
        uint2 raw = *(const uint2*)(Ep + (size_t)i * SEQ + j);
        float2 f0 = __half22float2(*(__half2*)&raw.x);
        float2 f1 = __half22float2(*(__half2*)&raw.y);
        float rv = rs[i];
        ax = fmaf(f0.x, rv, ax); ay = fmaf(f0.y, rv, ay);
        az = fmaf(f1.x, rv, az); aw = fmaf(f1.y, rv, aw);
    }
    atomicAdd(&colsum[bh * SEQ + j + 0], ax);
    atomicAdd(&colsum[bh * SEQ + j + 1], ay);
    atomicAdd(&colsum[bh * SEQ + j + 2], az);
    atomicAdd(&colsum[bh * SEQ + j + 3], aw);
}

// ---- fused row+col pass: r = MU/(E·(NU/cs_in)); cs_out += E^T r ------------
// 32 rows per block; phase A reads E from DRAM, phase B re-reads from L2.
__global__ __launch_bounds__(256) void rc_fused_h(
    const __half* __restrict__ Eh, const float* __restrict__ cs_in,
    float* __restrict__ cs_out, float* __restrict__ rvec)
{
    __shared__ float cs[SEQ];
    __shared__ float rl[32];
    const int bh = blockIdx.y, i0 = blockIdx.x * 32;
    const int t = threadIdx.x, lane = t & 31, w = t >> 5;

#pragma unroll
    for (int q = 0; q < 4; q++) {
        int j = t + 256 * q;
        cs[j] = NU_C / cs_in[bh * SEQ + j];
    }
    __syncthreads();

    const __half* Ep = Eh + (size_t)bh * SEQ * SEQ + (size_t)i0 * SEQ;

    // phase A: warp w owns rows 4w..4w+3 (uint4 loads: 8 halves)
#pragma unroll
    for (int rr = 0; rr < 4; rr++) {
        const int row = w * 4 + rr;
        const __half* Er = Ep + (size_t)row * SEQ;
        float acc = 0.f;
#pragma unroll
        for (int it = 0; it < 4; it++) {
            int j = it * 256 + lane * 8;
            uint4 raw = *(const uint4*)(Er + j);
            const __half2* hp = (const __half2*)&raw;
#pragma unroll
            for (int p = 0; p < 4; p++) {
                float2 f = __half22float2(hp[p]);
                acc += f.x * cs[j + p * 2] + f.y * cs[j + p * 2 + 1];
            }
        }
#pragma unroll
        for (int o = 16; o > 0; o >>= 1)
            acc += __shfl_xor_sync(0xffffffffu, acc, o);
        if (lane == 0) {
            float rv = MU_C / acc;
            rl[row] = rv;
            rvec[bh * SEQ + i0 + row] = rv;
        }
    }
    __syncthreads();

    // phase B: column partials, re-reading the 32 rows (L2-resident)
    const int j = t * 4;
    float ax = 0.f, ay = 0.f, az = 0.f, aw = 0.f;
#pragma unroll 8
    for (int i = 0; i < 32; i++) {
        uint2 raw = *(const uint2*)(Ep + (size_t)i * SEQ + j);
        float2 f0 = __half22float2(*(__half2*)&raw.x);
        float2 f1 = __half22float2(*(__half2*)&raw.y);
        float rv = rl[i];
        ax = fmaf(f0.x, rv, ax); ay = fmaf(f0.y, rv, ay);
        az = fmaf(f1.x, rv, az); aw = fmaf(f1.y, rv, aw);
    }
    atomicAdd(&cs_out[bh * SEQ + j + 0], ax);
    atomicAdd(&cs_out[bh * SEQ + j + 1], ay);
    atomicAdd(&cs_out[bh * SEQ + j + 2], az);
    atomicAdd(&cs_out[bh * SEQ + j + 3], aw);
}

__global__ void init_sums(float* __restrict__ rowsum, float* __restrict__ c1,
                          float* __restrict__ c2, float* __restrict__ c3)
{
    int i = blockIdx.x * 256 + threadIdx.x;
    rowsum[i] = 0.f; c1[i] = 0.f; c2[i] = 0.f; c3[i] = 0.f;
}

// --- per-head AV (fp16 mma): ho = rn_i*(E@(c_j V)), fused attn write --------
__global__ __launch_bounds__(256) void av_gemm(
    const __half* __restrict__ Eh, const float* __restrict__ r,
    const float* __restrict__ colsum3, const __half* __restrict__ qkv,
    float* __restrict__ attn, __half* __restrict__ ho, int write_attn)
{
    __shared__ __half Es[128 * 40];   // [i][j-chunk]
    __shared__ __half Vs[32 * 72];    // [j][d]
    __shared__ float cr[SEQ];
    __shared__ float rn[128];

    const int bh = blockIdx.y, b = bh >> 3, h = bh & 7;
    const int i0 = blockIdx.x * 128;
    const int t = threadIdx.x;
    const int lane = t & 31, w = t >> 5;
    const int wm = w & 3, wn = w >> 2;
    const int g = lane >> 2, tc = lane & 3;
    const int m0w = wm * 32, n0w = wn * 32;

    if (t < 128) rn[t] = r[bh * SEQ + i0 + t] * 1024.0f;
#pragma unroll
    for (int q = 0; q < 4; q++) {
        int j = t + 256 * q;
        cr[j] = NU_C / colsum3[bh * SEQ + j];
    }
    __syncthreads();

    const __half* Ep = Eh + (size_t)bh * SEQ * SEQ;
    const __half* vb = qkv + (size_t)b * SEQ * QKVW + 1024 + h * DHEAD;
    float* ap = attn + (size_t)bh * SEQ * SEQ;

    float4 acc[2][4];
#pragma unroll
    for (int mf = 0; mf < 2; mf++)
#pragma unroll
        for (int nf = 0; nf < 4; nf++) acc[mf][nf] = make_float4(0.f, 0.f, 0.f, 0.f);

    const u32 aAddrBase = sptr(Es) + ((lane & 15) * 40 + ((lane >> 4) << 3)) * 2;
    const u32 bAddrBase = sptr(Vs) +
        ((((lane >> 3) & 1) * 8 + (lane & 7)) * 72 + ((lane >> 4) << 3)) * 2;

    for (int jt = 0; jt < 32; jt++) {
        const int j0 = jt * 32;
#pragma unroll
        for (int q = 0; q < 2; q++) {
            int f = t + 256 * q;
            int i = f >> 2, c8 = (f & 3) * 8;
            uint4 raw = *(const uint4*)(Ep + (size_t)(i0 + i) * SEQ + j0 + c8);
            *(uint4*)(Es + i * 40 + c8) = raw;
            if (write_attn) {
                float rv = rn[i];
                const __half2* hp = (const __half2*)&raw;
                float* dst = ap + (size_t)(i0 + i) * SEQ + j0 + c8;
#pragma unroll
                for (int p = 0; p < 4; p++) {
                    float2 e = __half22float2(hp[p]);
                    float2 o;
                    o.x = rv * e.x * cr[j0 + c8 + p * 2];
                    o.y = rv * e.y * cr[j0 + c8 + p * 2 + 1];
                    *(float2*)(dst + p * 2) = o;
                }
            }
        }
        {
            int row = t >> 3, c8 = (t & 7) * 8;
            uint4 raw = *(const uint4*)(vb + (size_t)(j0 + row) * QKVW + c8);
            float cw = cr[j0 + row];
            const __half2* hp = (const __half2*)&raw;
            __half2* dst = (__half2*)(Vs + row * 72 + c8);
#pragma unroll
            for (int p = 0; p < 4; p++) {
                float2 v = __half22float2(hp[p]);
                dst[p] = __floats2half2_rn(v.x * cw, v.y * cw);
            }
        }
        __syncthreads();
#pragma unroll
        for (int ks = 0; ks < 32; ks += 16) {
            u32 a[2][4];
#pragma unroll
            for (int mf = 0; mf < 2; mf++)
                ldsm_x4(a[mf][0], a[mf][1], a[mf][2], a[mf][3],
                        aAddrBase + ((m0w + mf * 16) * 40 + ks) * 2);
#pragma unroll
            for (int nb = 0; nb < 2; nb++) {
                u32 b0, b1, b2, b3;
                ldsm_x4t(b0, b1, b2, b3,
                         bAddrBase + (ks * 72 + n0w + nb * 16) * 2);
                mma_f16(acc[0][nb * 2 + 0], a[0], b0, b1);
                mma_f16(acc[0][nb * 2 + 1], a[0], b2, b3);
                mma_f16(acc[1][nb * 2 + 0], a[1], b0, b1);
                mma_f16(acc[1][nb * 2 + 1], a[1], b2, b3);
            }
        }
        __syncthreads();
    }
#pragma unroll
    for (int mf = 0; mf < 2; mf++) {
        int il = m0w + mf * 16 + g;
        float rv0 = rn[il], rv1 = rn[il + 8];
        __half* hp0 = ho + (size_t)(b * SEQ + i0 + il) * DIMV + h * DHEAD;
        __half* hp1 = ho + (size_t)(b * SEQ + i0 + il + 8) * DIMV + h * DHEAD;
#pragma unroll
        for (int nf = 0; nf < 4; nf++) {
            int gc = n0w + nf * 8 + tc * 2;
            *(__half2*)(hp0 + gc) =
                __floats2half2_rn(acc[mf][nf].x * rv0, acc[mf][nf].y * rv0);
            *(__half2*)(hp1 + gc) =
                __floats2half2_rn(acc[mf][nf].z * rv1, acc[mf][nf].w * rv1);
        }
    }
}

// ---------------- launcher ---------------------------------------------------
extern "C" void kernel_launch(void* const* d_in, const int* in_sizes, int n_in,
                              void* d_out, int out_size)
{
    const float* x    = (const float*)d_in[0];
    const float* Wqkv = (const float*)d_in[1];
    const float* Wout = (const float*)d_in[2];
    const float* bout = (const float*)d_in[3];
    float* out = (float*)d_out;

    float *rp, *rsp, *c1p, *c2p, *c3p;
    __half *qkvp, *Ehp, *hop;
    cudaGetSymbolAddress((void**)&qkvp, g_qkv);
    cudaGetSymbolAddress((void**)&Ehp,  g_Eh);
    cudaGetSymbolAddress((void**)&rp,   g_r);
    cudaGetSymbolAddress((void**)&rsp,  g_rowsum);
    cudaGetSymbolAddress((void**)&c1p,  g_cs1);
    cudaGetSymbolAddress((void**)&c2p,  g_cs2);
    cudaGetSymbolAddress((void**)&c3p,  g_cs3);
    cudaGetSymbolAddress((void**)&hop,  g_ho);

    const size_t FIN = (size_t)BQ * SEQ * DIMV;
    const size_t ATT = (size_t)NHEADS * SEQ * SEQ;
    float* fin_ptr = 0;
    float* attn_ptr = 0;
    if ((size_t)out_size >= FIN + ATT) { fin_ptr = out; attn_ptr = out + FIN; }
    else if ((size_t)out_size == ATT)  { attn_ptr = out; }
    else                               { fin_ptr = out; }

    const int NV = NHEADS * SEQ;

    init_sums<<<NV / 256, 256>>>(rsp, c1p, c2p, c3p);

    // 1) qkv = x @ W_qkv  (fp16 mma)
    qkv_gemm<<<dim3(QKVW / 128, (BQ * SEQ) / 128), 256>>>(
        x, Wqkv, qkvp, BQ * SEQ, QKVW, DIMV);

    // 2) E = exp(-scale*q k^T) fp16, fused rowsum (c0 = 1)
    qk_dots_exp<<<dim3(SEQ / 128, SEQ / 128, NHEADS), 256>>>(qkvp, Ehp, rsp);

    // 3) Sinkhorn: col1, then two fused (row+col) passes
    colpass_h<<<dim3(SEQ / 64, NHEADS), 256>>>(Ehp, rsp, c1p, 1);
    rc_fused_h<<<dim3(SEQ / 32, NHEADS), 256>>>(Ehp, c1p, c2p, rp);   // r2, cs2
    rc_fused_h<<<dim3(SEQ / 32, NHEADS), 256>>>(Ehp, c2p, c3p, rp);   // r3, cs3

    // 4) attn = r*E*c*n (fused fp32 write) and ho = attn @ V (fp16 mma)
    av_gemm<<<dim3(SEQ / 128, NHEADS), 256>>>(
        Ehp, rp, c3p, qkvp, attn_ptr ? attn_ptr : (float*)out, hop,
        attn_ptr ? 1 : 0);

    // 5) final = ho @ W_out + b_out  (fp16 mma, fp32 output)
    if (fin_ptr)
        out_gemm<<<dim3(DIMV / 128, (BQ * SEQ) / 128), 256>>>(
            hop, Wout, fin_ptr, BQ * SEQ, DIMV, DIMV, bout);
}

// round 13
// speedup vs baseline: 2.8724x; 1.1966x over previous
#include <cuda_runtime.h>
#include <cuda_fp16.h>
#include <math.h>

#define BQ 8
#define SEQ 1024
#define DIMV 512
#define HEADS 8
#define DHEAD 64
#define NHEADS 64        // BQ*HEADS
#define QKVW 1536        // 3*HEADS*DHEAD

#define MU_C (1.0f/1024.0f)
#define NU_C (1.0f/1024.0f)

typedef unsigned int u32;

__device__ __forceinline__ u32 sptr(const void* p) {
    return (u32)__cvta_generic_to_shared(p);
}
__device__ __forceinline__ void ldsm_x4(u32& r0, u32& r1, u32& r2, u32& r3, u32 a) {
    asm volatile("ldmatrix.sync.aligned.m8n8.x4.shared.b16 {%0,%1,%2,%3},[%4];"
        : "=r"(r0), "=r"(r1), "=r"(r2), "=r"(r3) : "r"(a));
}
__device__ __forceinline__ void ldsm_x4t(u32& r0, u32& r1, u32& r2, u32& r3, u32 a) {
    asm volatile("ldmatrix.sync.aligned.m8n8.x4.trans.shared.b16 {%0,%1,%2,%3},[%4];"
        : "=r"(r0), "=r"(r1), "=r"(r2), "=r"(r3) : "r"(a));
}
__device__ __forceinline__ void mma_f16(float4& d, const u32* a, u32 b0, u32 b1) {
    asm volatile(
        "mma.sync.aligned.m16n8k16.row.col.f32.f16.f16.f32 "
        "{%0,%1,%2,%3},{%4,%5,%6,%7},{%8,%9},{%0,%1,%2,%3};"
        : "+f"(d.x), "+f"(d.y), "+f"(d.z), "+f"(d.w)
        : "r"(a[0]), "r"(a[1]), "r"(a[2]), "r"(a[3]), "r"(b0), "r"(b1));
}

// ---------------- scratch (device globals; no allocations allowed) ----------
__device__ __half g_qkv[(size_t)BQ * SEQ * QKVW];      // fp16 qkv
__device__ __half g_Eh[(size_t)NHEADS * SEQ * SEQ];    // E = exp(-C), fp16
__device__ float g_r[NHEADS * SEQ];
__device__ float g_rowsum[NHEADS * SEQ];
__device__ float g_cs1[NHEADS * SEQ];
__device__ float g_cs2[NHEADS * SEQ];
__device__ float g_cs3[NHEADS * SEQ];
__device__ __half g_ho[(size_t)BQ * SEQ * DIMV];       // fp16 head-merged out

// ---- qkv GEMM: fp32 A,B -> fp16 C. 128x128, BK=32, double-buffered ---------
__global__ __launch_bounds__(256) void qkv_gemm(
    const float* __restrict__ A, const float* __restrict__ Bm,
    __half* __restrict__ C, int M, int N, int K)
{
    __shared__ __half Ah[2][128 * 40];
    __shared__ __half Bh[2][32 * 136];
    const int t = threadIdx.x;
    const int m0 = blockIdx.y * 128, n0 = blockIdx.x * 128;
    const int lane = t & 31, w = t >> 5;
    const int wm = w & 3, wn = w >> 2;
    const int g = lane >> 2, tc = lane & 3;
    const int m0w = wm * 32, n0w = wn * 64;
    const int arow = t >> 3, ac4 = (t & 7) * 4;     // A: 4 chunks of 256
    const int bkr = t >> 5, bnc = (t & 31) * 4;     // B: 4 chunks

    float4 acc[2][8];
#pragma unroll
    for (int mf = 0; mf < 2; mf++)
#pragma unroll
        for (int nf = 0; nf < 8; nf++) acc[mf][nf] = make_float4(0.f, 0.f, 0.f, 0.f);

    float4 avr[4], bvr[4];
    // prologue: load tile 0 to regs, store to buf 0
#pragma unroll
    for (int q = 0; q < 4; q++) {
        int f = t + 256 * q;
        avr[q] = *(const float4*)(A + (size_t)(m0 + (f >> 3)) * K + (f & 7) * 4);
        bvr[q] = *(const float4*)(Bm + (size_t)(f >> 5) * N + n0 + (f & 31) * 4);
    }
#pragma unroll
    for (int q = 0; q < 4; q++) {
        int f = t + 256 * q;
        int row = f >> 3, c4 = (f & 7) * 4;
        *(__half2*)(Ah[0] + row * 40 + c4)     = __floats2half2_rn(avr[q].x, avr[q].y);
        *(__half2*)(Ah[0] + row * 40 + c4 + 2) = __floats2half2_rn(avr[q].z, avr[q].w);
        int kr = f >> 5, nc = (f & 31) * 4;
        *(__half2*)(Bh[0] + kr * 136 + nc)     = __floats2half2_rn(bvr[q].x, bvr[q].y);
        *(__half2*)(Bh[0] + kr * 136 + nc + 2) = __floats2half2_rn(bvr[q].z, bvr[q].w);
    }
    __syncthreads();

    const u32 aAddr0 = sptr(Ah[0]) + ((lane & 15) * 40 + ((lane >> 4) << 3)) * 2;
    const u32 bAddr0 = sptr(Bh[0]) +
        ((((lane >> 3) & 1) * 8 + (lane & 7)) * 136 + ((lane >> 4) << 3)) * 2;
    const u32 bufStepA = 128 * 40 * 2, bufStepB = 32 * 136 * 2;

    const int NT = K / 32;
    for (int kt = 0; kt < NT; kt++) {
        const int buf = kt & 1;
        if (kt + 1 < NT) {
            int ko = (kt + 1) * 32;
#pragma unroll
            for (int q = 0; q < 4; q++) {
                int f = t + 256 * q;
                avr[q] = *(const float4*)(A + (size_t)(m0 + (f >> 3)) * K + ko + (f & 7) * 4);
                bvr[q] = *(const float4*)(Bm + (size_t)(ko + (f >> 5)) * N + n0 + (f & 31) * 4);
            }
        }
        const u32 aB = aAddr0 + buf * bufStepA;
        const u32 bB = bAddr0 + buf * bufStepB;
#pragma unroll
        for (int ks = 0; ks < 32; ks += 16) {
            u32 a[2][4];
#pragma unroll
            for (int mf = 0; mf < 2; mf++)
                ldsm_x4(a[mf][0], a[mf][1], a[mf][2], a[mf][3],
                        aB + ((m0w + mf * 16) * 40 + ks) * 2);
#pragma unroll
            for (int nb = 0; nb < 4; nb++) {
                u32 b0, b1, b2, b3;
                ldsm_x4t(b0, b1, b2, b3, bB + (ks * 136 + n0w + nb * 16) * 2);
                mma_f16(acc[0][nb * 2 + 0], a[0], b0, b1);
                mma_f16(acc[0][nb * 2 + 1], a[0], b2, b3);
                mma_f16(acc[1][nb * 2 + 0], a[1], b0, b1);
                mma_f16(acc[1][nb * 2 + 1], a[1], b2, b3);
            }
        }
        if (kt + 1 < NT) {
            const int nb_ = buf ^ 1;
#pragma unroll
            for (int q = 0; q < 4; q++) {
                int f = t + 256 * q;
                int row = f >> 3, c4 = (f & 7) * 4;
                *(__half2*)(Ah[nb_] + row * 40 + c4)     = __floats2half2_rn(avr[q].x, avr[q].y);
                *(__half2*)(Ah[nb_] + row * 40 + c4 + 2) = __floats2half2_rn(avr[q].z, avr[q].w);
                int kr = f >> 5, nc = (f & 31) * 4;
                *(__half2*)(Bh[nb_] + kr * 136 + nc)     = __floats2half2_rn(bvr[q].x, bvr[q].y);
                *(__half2*)(Bh[nb_] + kr * 136 + nc + 2) = __floats2half2_rn(bvr[q].z, bvr[q].w);
            }
        }
        __syncthreads();
    }
#pragma unroll
    for (int mf = 0; mf < 2; mf++) {
        int gr = m0 + m0w + mf * 16 + g;
#pragma unroll
        for (int nf = 0; nf < 8; nf++) {
            int gc = n0 + n0w + nf * 8 + tc * 2;
            *(__half2*)(C + (size_t)gr * N + gc) =
                __floats2half2_rn(acc[mf][nf].x, acc[mf][nf].y);
            *(__half2*)(C + (size_t)(gr + 8) * N + gc) =
                __floats2half2_rn(acc[mf][nf].z, acc[mf][nf].w);
        }
    }
    (void)arow; (void)ac4; (void)bkr; (void)bnc;
}

// ---- out GEMM: fp16 A, fp32 B -> fp32 C + bias; double-buffered ------------
__global__ __launch_bounds__(256) void out_gemm(
    const __half* __restrict__ A, const float* __restrict__ Bm,
    float* __restrict__ C, int M, int N, int K, const float* __restrict__ bias)
{
    __shared__ __half Ah[2][128 * 40];
    __shared__ __half Bh[2][32 * 136];
    const int t = threadIdx.x;
    const int m0 = blockIdx.y * 128, n0 = blockIdx.x * 128;
    const int lane = t & 31, w = t >> 5;
    const int wm = w & 3, wn = w >> 2;
    const int g = lane >> 2, tc = lane & 3;
    const int m0w = wm * 32, n0w = wn * 64;

    float4 acc[2][8];
#pragma unroll
    for (int mf = 0; mf < 2; mf++)
#pragma unroll
        for (int nf = 0; nf < 8; nf++) acc[mf][nf] = make_float4(0.f, 0.f, 0.f, 0.f);

    uint4 avr[2];
    float4 bvr[4];
#pragma unroll
    for (int q = 0; q < 2; q++) {
        int f = t + 256 * q;
        avr[q] = *(const uint4*)(A + (size_t)(m0 + (f >> 2)) * K + (f & 3) * 8);
    }
#pragma unroll
    for (int q = 0; q < 4; q++) {
        int f = t + 256 * q;
        bvr[q] = *(const float4*)(Bm + (size_t)(f >> 5) * N + n0 + (f & 31) * 4);
    }
#pragma unroll
    for (int q = 0; q < 2; q++) {
        int f = t + 256 * q;
        *(uint4*)(Ah[0] + (f >> 2) * 40 + (f & 3) * 8) = avr[q];
    }
#pragma unroll
    for (int q = 0; q < 4; q++) {
        int f = t + 256 * q;
        int kr = f >> 5, nc = (f & 31) * 4;
        *(__half2*)(Bh[0] + kr * 136 + nc)     = __floats2half2_rn(bvr[q].x, bvr[q].y);
        *(__half2*)(Bh[0] + kr * 136 + nc + 2) = __floats2half2_rn(bvr[q].z, bvr[q].w);
    }
    __syncthreads();

    const u32 aAddr0 = sptr(Ah[0]) + ((lane & 15) * 40 + ((lane >> 4) << 3)) * 2;
    const u32 bAddr0 = sptr(Bh[0]) +
        ((((lane >> 3) & 1) * 8 + (lane & 7)) * 136 + ((lane >> 4) << 3)) * 2;
    const u32 bufStepA = 128 * 40 * 2, bufStepB = 32 * 136 * 2;

    const int NT = K / 32;
    for (int kt = 0; kt < NT; kt++) {
        const int buf = kt & 1;
        if (kt + 1 < NT) {
            int ko = (kt + 1) * 32;
#pragma unroll
            for (int q = 0; q < 2; q++) {
                int f = t + 256 * q;
                avr[q] = *(const uint4*)(A + (size_t)(m0 + (f >> 2)) * K + ko + (f & 3) * 8);
            }
#pragma unroll
            for (int q = 0; q < 4; q++) {
                int f = t + 256 * q;
                bvr[q] = *(const float4*)(Bm + (size_t)(ko + (f >> 5)) * N + n0 + (f & 31) * 4);
            }
        }
        const u32 aB = aAddr0 + buf * bufStepA;
        const u32 bB = bAddr0 + buf * bufStepB;
#pragma unroll
        for (int ks = 0; ks < 32; ks += 16) {
            u32 a[2][4];
#pragma unroll
            for (int mf = 0; mf < 2; mf++)
                ldsm_x4(a[mf][0], a[mf][1], a[mf][2], a[mf][3],
                        aB + ((m0w + mf * 16) * 40 + ks) * 2);
#pragma unroll
            for (int nb = 0; nb < 4; nb++) {
                u32 b0, b1, b2, b3;
                ldsm_x4t(b0, b1, b2, b3, bB + (ks * 136 + n0w + nb * 16) * 2);
                mma_f16(acc[0][nb * 2 + 0], a[0], b0, b1);
                mma_f16(acc[0][nb * 2 + 1], a[0], b2, b3);
                mma_f16(acc[1][nb * 2 + 0], a[1], b0, b1);
                mma_f16(acc[1][nb * 2 + 1], a[1], b2, b3);
            }
        }
        if (kt + 1 < NT) {
            const int nb_ = buf ^ 1;
#pragma unroll
            for (int q = 0; q < 2; q++) {
                int f = t + 256 * q;
                *(uint4*)(Ah[nb_] + (f >> 2) * 40 + (f & 3) * 8) = avr[q];
            }
#pragma unroll
            for (int q = 0; q < 4; q++) {
                int f = t + 256 * q;
                int kr = f >> 5, nc = (f & 31) * 4;
                *(__half2*)(Bh[nb_] + kr * 136 + nc)     = __floats2half2_rn(bvr[q].x, bvr[q].y);
                *(__half2*)(Bh[nb_] + kr * 136 + nc + 2) = __floats2half2_rn(bvr[q].z, bvr[q].w);
            }
        }
        __syncthreads();
    }
#pragma unroll
    for (int mf = 0; mf < 2; mf++) {
        int gr = m0 + m0w + mf * 16 + g;
#pragma unroll
        for (int nf = 0; nf < 8; nf++) {
            int gc = n0 + n0w + nf * 8 + tc * 2;
            float2 lo = make_float2(acc[mf][nf].x + bias[gc],
                                    acc[mf][nf].y + bias[gc + 1]);
            float2 hi = make_float2(acc[mf][nf].z + bias[gc],
                                    acc[mf][nf].w + bias[gc + 1]);
            *(float2*)(C + (size_t)gr * N + gc) = lo;
            *(float2*)(C + (size_t)(gr + 8) * N + gc) = hi;
        }
    }
}

// ------- dots (fp16 mma): E = exp(-scale*q k^T) fp16, fused row-sum ---------
__global__ __launch_bounds__(256) void qk_dots_exp(
    const __half* __restrict__ qkv, __half* __restrict__ Eh,
    float* __restrict__ rowsum)
{
    __shared__ __half Ah[128 * 72];   // [i][d]
    __shared__ __half Bh[128 * 72];   // [j][d]
    const int bh = blockIdx.z, b = bh >> 3, h = bh & 7;
    const int i0 = blockIdx.y * 128, j0 = blockIdx.x * 128;
    const __half* qbase = qkv + (size_t)b * SEQ * QKVW + h * DHEAD;
    const __half* kbase = qkv + (size_t)b * SEQ * QKVW + 512 + h * DHEAD;

    const int t = threadIdx.x;
    const int lane = t & 31, w = t >> 5;
    const int wm = w & 3, wn = w >> 2;
    const int g = lane >> 2, tc = lane & 3;
    const int m0w = wm * 32, n0w = wn * 64;

    float4 acc[2][8];
#pragma unroll
    for (int mf = 0; mf < 2; mf++)
#pragma unroll
        for (int nf = 0; nf < 8; nf++) acc[mf][nf] = make_float4(0.f, 0.f, 0.f, 0.f);

#pragma unroll
    for (int q = 0; q < 4; q++) {
        int f = t + 256 * q;
        int row = f >> 3, c8 = (f & 7) * 8;
        *(uint4*)(Ah + row * 72 + c8) =
            *(const uint4*)(qbase + (size_t)(i0 + row) * QKVW + c8);
        *(uint4*)(Bh + row * 72 + c8) =
            *(const uint4*)(kbase + (size_t)(j0 + row) * QKVW + c8);
    }
    __syncthreads();

    const u32 aAddrBase = sptr(Ah) + ((lane & 15) * 72 + ((lane >> 4) << 3)) * 2;
    const u32 bAddrBase = sptr(Bh) +
        ((((lane >> 4) << 3) + (lane & 7)) * 72 + (((lane >> 3) & 1) * 8)) * 2;

#pragma unroll
    for (int ks = 0; ks < 64; ks += 16) {
        u32 a[2][4];
#pragma unroll
        for (int mf = 0; mf < 2; mf++)
            ldsm_x4(a[mf][0], a[mf][1], a[mf][2], a[mf][3],
                    aAddrBase + ((m0w + mf * 16) * 72 + ks) * 2);
#pragma unroll
        for (int nb = 0; nb < 4; nb++) {
            u32 b0, b1, b2, b3;
            ldsm_x4(b0, b1, b2, b3,
                    bAddrBase + ((n0w + nb * 16) * 72 + ks) * 2);
            mma_f16(acc[0][nb * 2 + 0], a[0], b0, b1);
            mma_f16(acc[0][nb * 2 + 1], a[0], b2, b3);
            mma_f16(acc[1][nb * 2 + 0], a[1], b0, b1);
            mma_f16(acc[1][nb * 2 + 1], a[1], b2, b3);
        }
    }

    __half* Ehp = Eh + (size_t)bh * SEQ * SEQ;
#pragma unroll
    for (int mf = 0; mf < 2; mf++) {
        int gi = i0 + m0w + mf * 16 + g;
        float rs0 = 0.f, rs1 = 0.f;
#pragma unroll
        for (int nf = 0; nf < 8; nf++) {
            int gj = j0 + n0w + nf * 8 + tc * 2;
            float e0 = __expf(-0.125f * acc[mf][nf].x);
            float e1 = __expf(-0.125f * acc[mf][nf].y);
            float e2 = __expf(-0.125f * acc[mf][nf].z);
            float e3 = __expf(-0.125f * acc[mf][nf].w);
            *(__half2*)(Ehp + (size_t)gi * SEQ + gj) = __floats2half2_rn(e0, e1);
            *(__half2*)(Ehp + (size_t)(gi + 8) * SEQ + gj) = __floats2half2_rn(e2, e3);
            rs0 += e0 + e1; rs1 += e2 + e3;
        }
        rs0 += __shfl_xor_sync(0xffffffffu, rs0, 1);
        rs0 += __shfl_xor_sync(0xffffffffu, rs0, 2);
        rs1 += __shfl_xor_sync(0xffffffffu, rs1, 1);
        rs1 += __shfl_xor_sync(0xffffffffu, rs1, 2);
        if (tc == 0) {
            atomicAdd(&rowsum[bh * SEQ + gi], rs0);
            atomicAdd(&rowsum[bh * SEQ + gi + 8], rs1);
        }
    }
}

// ---- col pass over fp16 E ---------------------------------------------------
__global__ __launch_bounds__(256) void colpass_h(
    const __half* __restrict__ Eh, const float* __restrict__ rvec,
    float* __restrict__ colsum, int recip)
{
    const int bh = blockIdx.y;
    const int i0 = blockIdx.x * 64;
    const int t = threadIdx.x;
    __shared__ float rs[64];
    if (t < 64) {
        float rv = rvec[bh * SEQ + i0 + t];
        rs[t] = recip ? (MU_C / rv) : rv;
    }
    __syncthreads();

    const __half* Ep = Eh + (size_t)bh * SEQ * SEQ + (size_t)i0 * SEQ;
    const int j = t * 4;
    float ax = 0.f, ay = 0.f, az = 0.f, aw = 0.f;
#pragma unroll 8
    for (int i = 0; i < 64; i++) {
        uint2 raw = *(const uint2*)(Ep + (size_t)i * SEQ + j);
        float2 f0 = __half22float2(*(__half2*)&raw.x);
        float2 f1 = __half22float2(*(__half2*)&raw.y);
        float rv = rs[i];
        ax = fmaf(f0.x, rv, ax); ay = fmaf(f0.y, rv, ay);
        az = fmaf(f1.x, rv, az); aw = fmaf(f1.y, rv, aw);
    }
    atomicAdd(&colsum[bh * SEQ + j + 0], ax);
    atomicAdd(&colsum[bh * SEQ + j + 1], ay);
    atomicAdd(&colsum[bh * SEQ + j + 2], az);
    atomicAdd(&colsum[bh * SEQ + j + 3], aw);
}

// ---- fused row+col pass ------------------------------------------------------
__global__ __launch_bounds__(256) void rc_fused_h(
    const __half* __restrict__ Eh, const float* __restrict__ cs_in,
    float* __restrict__ cs_out, float* __restrict__ rvec)
{
    __shared__ float cs[SEQ];
    __shared__ float rl[32];
    const int bh = blockIdx.y, i0 = blockIdx.x * 32;
    const int t = threadIdx.x, lane = t & 31, w = t >> 5;

#pragma unroll
    for (int q = 0; q < 4; q++) {
        int j = t + 256 * q;
        cs[j] = NU_C / cs_in[bh * SEQ + j];
    }
    __syncthreads();

    const __half* Ep = Eh + (size_t)bh * SEQ * SEQ + (size_t)i0 * SEQ;

#pragma unroll
    for (int rr = 0; rr < 4; rr++) {
        const int row = w * 4 + rr;
        const __half* Er = Ep + (size_t)row * SEQ;
        float acc = 0.f;
#pragma unroll
        for (int it = 0; it < 4; it++) {
            int j = it * 256 + lane * 8;
            uint4 raw = *(const uint4*)(Er + j);
            const __half2* hp = (const __half2*)&raw;
#pragma unroll
            for (int p = 0; p < 4; p++) {
                float2 f = __half22float2(hp[p]);
                acc += f.x * cs[j + p * 2] + f.y * cs[j + p * 2 + 1];
            }
        }
#pragma unroll
        for (int o = 16; o > 0; o >>= 1)
            acc += __shfl_xor_sync(0xffffffffu, acc, o);
        if (lane == 0) {
            float rv = MU_C / acc;
            rl[row] = rv;
            rvec[bh * SEQ + i0 + row] = rv;
        }
    }
    __syncthreads();

    const int j = t * 4;
    float ax = 0.f, ay = 0.f, az = 0.f, aw = 0.f;
#pragma unroll 8
    for (int i = 0; i < 32; i++) {
        uint2 raw = *(const uint2*)(Ep + (size_t)i * SEQ + j);
        float2 f0 = __half22float2(*(__half2*)&raw.x);
        float2 f1 = __half22float2(*(__half2*)&raw.y);
        float rv = rl[i];
        ax = fmaf(f0.x, rv, ax); ay = fmaf(f0.y, rv, ay);
        az = fmaf(f1.x, rv, az); aw = fmaf(f1.y, rv, aw);
    }
    atomicAdd(&cs_out[bh * SEQ + j + 0], ax);
    atomicAdd(&cs_out[bh * SEQ + j + 1], ay);
    atomicAdd(&cs_out[bh * SEQ + j + 2], az);
    atomicAdd(&cs_out[bh * SEQ + j + 3], aw);
}

__global__ void init_sums(float* __restrict__ rowsum, float* __restrict__ c1,
                          float* __restrict__ c2, float* __restrict__ c3)
{
    int i = blockIdx.x * 256 + threadIdx.x;
    rowsum[i] = 0.f; c1[i] = 0.f; c2[i] = 0.f; c3[i] = 0.f;
}

// --- per-head AV (fp16 mma, BK=64): ho = rn_i*(E@(c_j V)), fused attn write --
__global__ __launch_bounds__(256) void av_gemm(
    const __half* __restrict__ Eh, const float* __restrict__ r,
    const float* __restrict__ colsum3, const __half* __restrict__ qkv,
    float* __restrict__ attn, __half* __restrict__ ho, int write_attn)
{
    __shared__ __half Es[128 * 72];   // [i][j-chunk], 64 j + 8 pad
    __shared__ __half Vs[64 * 72];    // [j][d]
    __shared__ float cr[SEQ];
    __shared__ float rn[128];

    const int bh = blockIdx.y, b = bh >> 3, h = bh & 7;
    const int i0 = blockIdx.x * 128;
    const int t = threadIdx.x;
    const int lane = t & 31, w = t >> 5;
    const int wm = w & 3, wn = w >> 2;
    const int g = lane >> 2, tc = lane & 3;
    const int m0w = wm * 32, n0w = wn * 32;

    if (t < 128) rn[t] = r[bh * SEQ + i0 + t] * 1024.0f;
#pragma unroll
    for (int q = 0; q < 4; q++) {
        int j = t + 256 * q;
        cr[j] = NU_C / colsum3[bh * SEQ + j];
    }
    __syncthreads();

    const __half* Ep = Eh + (size_t)bh * SEQ * SEQ;
    const __half* vb = qkv + (size_t)b * SEQ * QKVW + 1024 + h * DHEAD;
    float* ap = attn + (size_t)bh * SEQ * SEQ;

    float4 acc[2][4];
#pragma unroll
    for (int mf = 0; mf < 2; mf++)
#pragma unroll
        for (int nf = 0; nf < 4; nf++) acc[mf][nf] = make_float4(0.f, 0.f, 0.f, 0.f);

    const u32 aAddrBase = sptr(Es) + ((lane & 15) * 72 + ((lane >> 4) << 3)) * 2;
    const u32 bAddrBase = sptr(Vs) +
        ((((lane >> 3) & 1) * 8 + (lane & 7)) * 72 + ((lane >> 4) << 3)) * 2;

    for (int jt = 0; jt < 16; jt++) {
        const int j0 = jt * 64;
        // E tile 128x64 halves (+ fused fp32 attn write)
#pragma unroll
        for (int q = 0; q < 4; q++) {
            int f = t + 256 * q;
            int i = f >> 3, c8 = (f & 7) * 8;
            uint4 raw = *(const uint4*)(Ep + (size_t)(i0 + i) * SEQ + j0 + c8);
            *(uint4*)(Es + i * 72 + c8) = raw;
            if (write_attn) {
                float rv = rn[i];
                const __half2* hp = (const __half2*)&raw;
                float* dst = ap + (size_t)(i0 + i) * SEQ + j0 + c8;
#pragma unroll
                for (int p = 0; p < 4; p++) {
                    float2 e = __half22float2(hp[p]);
                    float2 o;
                    o.x = rv * e.x * cr[j0 + c8 + p * 2];
                    o.y = rv * e.y * cr[j0 + c8 + p * 2 + 1];
                    *(float2*)(dst + p * 2) = o;
                }
            }
        }
        // V tile 64x64, scale by c_j
#pragma unroll
        for (int q = 0; q < 2; q++) {
            int f = t + 256 * q;
            int row = f >> 3, c8 = (f & 7) * 8;
            uint4 raw = *(const uint4*)(vb + (size_t)(j0 + row) * QKVW + c8);
            float cw = cr[j0 + row];
            const __half2* hp = (const __half2*)&raw;
            __half2* dst = (__half2*)(Vs + row * 72 + c8);
#pragma unroll
            for (int p = 0; p < 4; p++) {
                float2 v = __half22float2(hp[p]);
                dst[p] = __floats2half2_rn(v.x * cw, v.y * cw);
            }
        }
        __syncthreads();
#pragma unroll
        for (int ks = 0; ks < 64; ks += 16) {
            u32 a[2][4];
#pragma unroll
            for (int mf = 0; mf < 2; mf++)
                ldsm_x4(a[mf][0], a[mf][1], a[mf][2], a[mf][3],
                        aAddrBase + ((m0w + mf * 16) * 72 + ks) * 2);
#pragma unroll
            for (int nb = 0; nb < 2; nb++) {
                u32 b0, b1, b2, b3;
                ldsm_x4t(b0, b1, b2, b3,
                         bAddrBase + (ks * 72 + n0w + nb * 16) * 2);
                mma_f16(acc[0][nb * 2 + 0], a[0], b0, b1);
                mma_f16(acc[0][nb * 2 + 1], a[0], b2, b3);
                mma_f16(acc[1][nb * 2 + 0], a[1], b0, b1);
                mma_f16(acc[1][nb * 2 + 1], a[1], b2, b3);
            }
        }
        __syncthreads();
    }
#pragma unroll
    for (int mf = 0; mf < 2; mf++) {
        int il = m0w + mf * 16 + g;
        float rv0 = rn[il], rv1 = rn[il + 8];
        __half* hp0 = ho + (size_t)(b * SEQ + i0 + il) * DIMV + h * DHEAD;
        __half* hp1 = ho + (size_t)(b * SEQ + i0 + il + 8) * DIMV + h * DHEAD;
#pragma unroll
        for (int nf = 0; nf < 4; nf++) {
            int gc = n0w + nf * 8 + tc * 2;
            *(__half2*)(hp0 + gc) =
                __floats2half2_rn(acc[mf][nf].x * rv0, acc[mf][nf].y * rv0);
            *(__half2*)(hp1 + gc) =
                __floats2half2_rn(acc[mf][nf].z * rv1, acc[mf][nf].w * rv1);
        }
    }
}

// ---------------- launcher ---------------------------------------------------
extern "C" void kernel_launch(void* const* d_in, const int* in_sizes, int n_in,
                              void* d_out, int out_size)
{
    const float* x    = (const float*)d_in[0];
    const float* Wqkv = (const float*)d_in[1];
    const float* Wout = (const float*)d_in[2];
    const float* bout = (const float*)d_in[3];
    float* out = (float*)d_out;

    float *rp, *rsp, *c1p, *c2p, *c3p;
    __half *qkvp, *Ehp, *hop;
    cudaGetSymbolAddress((void**)&qkvp, g_qkv);
    cudaGetSymbolAddress((void**)&Ehp,  g_Eh);
    cudaGetSymbolAddress((void**)&rp,   g_r);
    cudaGetSymbolAddress((void**)&rsp,  g_rowsum);
    cudaGetSymbolAddress((void**)&c1p,  g_cs1);
    cudaGetSymbolAddress((void**)&c2p,  g_cs2);
    cudaGetSymbolAddress((void**)&c3p,  g_cs3);
    cudaGetSymbolAddress((void**)&hop,  g_ho);

    const size_t FIN = (size_t)BQ * SEQ * DIMV;
    const size_t ATT = (size_t)NHEADS * SEQ * SEQ;
    float* fin_ptr = 0;
    float* attn_ptr = 0;
    if ((size_t)out_size >= FIN + ATT) { fin_ptr = out; attn_ptr = out + FIN; }
    else if ((size_t)out_size == ATT)  { attn_ptr = out; }
    else                               { fin_ptr = out; }

    const int NV = NHEADS * SEQ;

    init_sums<<<NV / 256, 256>>>(rsp, c1p, c2p, c3p);

    // 1) qkv = x @ W_qkv  (fp16 mma, double-buffered)
    qkv_gemm<<<dim3(QKVW / 128, (BQ * SEQ) / 128), 256>>>(
        x, Wqkv, qkvp, BQ * SEQ, QKVW, DIMV);

    // 2) E = exp(-scale*q k^T) fp16, fused rowsum (c0 = 1)
    qk_dots_exp<<<dim3(SEQ / 128, SEQ / 128, NHEADS), 256>>>(qkvp, Ehp, rsp);

    // 3) Sinkhorn: col1, then two fused (row+col) passes
    colpass_h<<<dim3(SEQ / 64, NHEADS), 256>>>(Ehp, rsp, c1p, 1);
    rc_fused_h<<<dim3(SEQ / 32, NHEADS), 256>>>(Ehp, c1p, c2p, rp);   // r2, cs2
    rc_fused_h<<<dim3(SEQ / 32, NHEADS), 256>>>(Ehp, c2p, c3p, rp);   // r3, cs3

    // 4) attn = r*E*c*n (fused fp32 write) and ho = attn @ V (fp16 mma, BK=64)
    av_gemm<<<dim3(SEQ / 128, NHEADS), 256>>>(
        Ehp, rp, c3p, qkvp, attn_ptr ? attn_ptr : (float*)out, hop,
        attn_ptr ? 1 : 0);

    // 5) final = ho @ W_out + b_out  (fp16 mma, double-buffered)
    if (fin_ptr)
        out_gemm<<<dim3(DIMV / 128, (BQ * SEQ) / 128), 256>>>(
            hop, Wout, fin_ptr, BQ * SEQ, DIMV, DIMV, bout);
}